// round 1
// baseline (speedup 1.0000x reference)
#include <cuda_runtime.h>
#include <math.h>

#define S_LEN 2048
#define BATCH 2
#define HDIM  4096
#define HD    128
#define NH    32
#define NKV   8
#define T_TOK (BATCH*S_LEN)   // 4096 tokens
#define KV_N  (NKV*HD)        // 1024

static __device__ __constant__ float kSCALE = 0.08838834764831845f; // 128^-0.5

// Scratch (allocation-free rule: __device__ globals)
__device__ float g_Q[(size_t)BATCH*NH*S_LEN*HD];    // [b][h][s][d]
__device__ float g_K[(size_t)BATCH*NKV*S_LEN*HD];   // [b][kv][s][d] (rope'd)
__device__ float g_V[(size_t)BATCH*NKV*S_LEN*HD];   // [b][kv][s][d]
__device__ float g_AO[(size_t)T_TOK*HDIM];          // attn out, [t][h*HD+d]

// ---------------------------------------------------------------------------
// Tiled SGEMM: C[M,N] = A[M,K] @ B[N,K]^T (+bias), M fixed by grid (128/block)
// MODE 0: plain row-major store (stride N)      -> final Wo proj (to d_out)
// MODE 1: bias + RoPE + permute to [b][h][s][d] -> Q, K proj
// MODE 2: bias + permute to [b][h][s][d]        -> V proj
// BN=128 == one head, so epilogue threads own full (even,odd) rope pairs.
// ---------------------------------------------------------------------------
template<int MODE>
__global__ void __launch_bounds__(256)
gemm_k(const float* __restrict__ A, const float* __restrict__ Bw,
       const float* __restrict__ bias, float* __restrict__ C,
       int N, int K,
       const float* __restrict__ cosp, const float* __restrict__ sinp,
       int n_heads)
{
    __shared__ float As[8][128];
    __shared__ float Bs[8][128];

    const int tid = threadIdx.x;
    const int bm = blockIdx.y, bn = blockIdx.x;
    const int ty = tid >> 4, tx = tid & 15;

    float acc[8][8];
#pragma unroll
    for (int i = 0; i < 8; i++)
#pragma unroll
        for (int j = 0; j < 8; j++) acc[i][j] = 0.f;

    const int lrow = tid >> 1;
    const int lc4  = (tid & 1) * 4;
    const float* Ap = A  + (size_t)(bm*128 + lrow)*K + lc4;
    const float* Bp = Bw + (size_t)(bn*128 + lrow)*K + lc4;

    float4 av = *(const float4*)Ap;
    float4 bv = *(const float4*)Bp;

    for (int k0 = 0; k0 < K; k0 += 8) {
        __syncthreads();
        As[lc4+0][lrow] = av.x; As[lc4+1][lrow] = av.y;
        As[lc4+2][lrow] = av.z; As[lc4+3][lrow] = av.w;
        Bs[lc4+0][lrow] = bv.x; Bs[lc4+1][lrow] = bv.y;
        Bs[lc4+2][lrow] = bv.z; Bs[lc4+3][lrow] = bv.w;
        __syncthreads();
        if (k0 + 8 < K) {
            av = *(const float4*)(Ap + k0 + 8);
            bv = *(const float4*)(Bp + k0 + 8);
        }
#pragma unroll
        for (int kk = 0; kk < 8; kk++) {
            float4 a0 = *(const float4*)&As[kk][ty*8];
            float4 a1 = *(const float4*)&As[kk][ty*8+4];
            float4 b0 = *(const float4*)&Bs[kk][tx*8];
            float4 b1 = *(const float4*)&Bs[kk][tx*8+4];
            float a[8] = {a0.x,a0.y,a0.z,a0.w,a1.x,a1.y,a1.z,a1.w};
            float b[8] = {b0.x,b0.y,b0.z,b0.w,b1.x,b1.y,b1.z,b1.w};
#pragma unroll
            for (int i = 0; i < 8; i++)
#pragma unroll
                for (int j = 0; j < 8; j++)
                    acc[i][j] = fmaf(a[i], b[j], acc[i][j]);
        }
    }

    if (MODE == 0) {
#pragma unroll
        for (int i = 0; i < 8; i++) {
            int row = bm*128 + ty*8 + i;
            float4 v0 = make_float4(acc[i][0],acc[i][1],acc[i][2],acc[i][3]);
            float4 v1 = make_float4(acc[i][4],acc[i][5],acc[i][6],acc[i][7]);
            float* cp = &C[(size_t)row*N + bn*128 + tx*8];
            *(float4*)cp       = v0;
            *(float4*)(cp + 4) = v1;
        }
    } else {
#pragma unroll
        for (int i = 0; i < 8; i++) {
            int t = bm*128 + ty*8 + i;          // token
            int b = t >> 11;                    // /S_LEN
            int s = t & (S_LEN - 1);
            size_t base = ((size_t)(b*n_heads + bn)*S_LEN + s)*HD;
            if (MODE == 2) {
#pragma unroll
                for (int j = 0; j < 8; j++) {
                    int c = bn*128 + tx*8 + j;
                    C[base + tx*8 + j] = acc[i][j] + bias[c];
                }
            } else { // MODE 1: bias (optional) + rope
#pragma unroll
                for (int j = 0; j < 8; j += 2) {
                    int cl = tx*8 + j;          // local col within head (even)
                    int d  = cl >> 1;           // rope pair index 0..63
                    int c  = bn*128 + cl;
                    float x1 = acc[i][j]   + (bias ? bias[c]   : 0.f);
                    float x2 = acc[i][j+1] + (bias ? bias[c+1] : 0.f);
                    float cs = cosp[s*64 + d];
                    float sn = sinp[s*64 + d];
                    C[base + d]      = x1*cs - x2*sn;
                    C[base + 64 + d] = x1*sn + x2*cs;
                }
            }
        }
    }
}

// ---------------------------------------------------------------------------
// Flash attention (non-causal), BM=BN=64, HD=128, fp32, online softmax.
// grid: (S/64, B*NH), 256 threads. Thread (ty,tx): rows ty*4..+3,
// score cols {tx, tx+16, tx+32, tx+48}, output cols tx*8..+7.
// ---------------------------------------------------------------------------
__device__ __forceinline__ float redmax16(float v) {
#pragma unroll
    for (int o = 1; o < 16; o <<= 1)
        v = fmaxf(v, __shfl_xor_sync(0xffffffffu, v, o));
    return v;
}
__device__ __forceinline__ float redsum16(float v) {
#pragma unroll
    for (int o = 1; o < 16; o <<= 1)
        v += __shfl_xor_sync(0xffffffffu, v, o);
    return v;
}

#define QK_PAD 132
#define P_PAD  68

__global__ void __launch_bounds__(256)
attn_k(const float* __restrict__ Q, const float* __restrict__ K,
       const float* __restrict__ V, float* __restrict__ AO)
{
    extern __shared__ float sm[];
    float* sQ = sm;
    float* sK = sQ + 64*QK_PAD;
    float* sV = sK + 64*QK_PAD;
    float* sP = sV + 64*QK_PAD;

    const int tid = threadIdx.x;
    const int qb = blockIdx.x;
    const int bh = blockIdx.y;
    const int b  = bh / NH;
    const int h  = bh % NH;
    const int kv = h >> 2;   // N_REP = 4

    const float* Qb = Q + ((size_t)bh*S_LEN + qb*64)*HD;
    const float* Kb = K + ((size_t)(b*NKV + kv)*S_LEN)*HD;
    const float* Vb = V + ((size_t)(b*NKV + kv)*S_LEN)*HD;

    // load Q tile (64x128)
#pragma unroll
    for (int u = 0; u < 8; u++) {
        int f = tid + u*256;
        int r = f >> 5, c = (f & 31) * 4;
        *(float4*)&sQ[r*QK_PAD + c] = *(const float4*)&Qb[r*128 + c];
    }

    const int ty = tid >> 4, tx = tid & 15;
    float m[4], l[4], o[4][8];
#pragma unroll
    for (int i = 0; i < 4; i++) {
        m[i] = -1e30f; l[i] = 0.f;
#pragma unroll
        for (int c = 0; c < 8; c++) o[i][c] = 0.f;
    }

    for (int kt = 0; kt < S_LEN/64; kt++) {
        __syncthreads();  // prev iter readers done (also fences Q load on iter 0)
        const float* Kt = Kb + (size_t)kt*64*HD;
        const float* Vt = Vb + (size_t)kt*64*HD;
#pragma unroll
        for (int u = 0; u < 8; u++) {
            int f = tid + u*256;
            int r = f >> 5, c = (f & 31) * 4;
            *(float4*)&sK[r*QK_PAD + c] = *(const float4*)&Kt[r*128 + c];
            *(float4*)&sV[r*QK_PAD + c] = *(const float4*)&Vt[r*128 + c];
        }
        __syncthreads();

        // scores: 4 rows x 4 cols per thread
        float sc[4][4];
#pragma unroll
        for (int i = 0; i < 4; i++)
#pragma unroll
            for (int jj = 0; jj < 4; jj++) sc[i][jj] = 0.f;

#pragma unroll 4
        for (int d = 0; d < 128; d += 4) {
            float4 q4[4], k4[4];
#pragma unroll
            for (int i = 0; i < 4; i++)
                q4[i] = *(const float4*)&sQ[(ty*4 + i)*QK_PAD + d];
#pragma unroll
            for (int jj = 0; jj < 4; jj++)
                k4[jj] = *(const float4*)&sK[(tx + 16*jj)*QK_PAD + d];
#pragma unroll
            for (int i = 0; i < 4; i++)
#pragma unroll
                for (int jj = 0; jj < 4; jj++) {
                    sc[i][jj] = fmaf(q4[i].x, k4[jj].x, sc[i][jj]);
                    sc[i][jj] = fmaf(q4[i].y, k4[jj].y, sc[i][jj]);
                    sc[i][jj] = fmaf(q4[i].z, k4[jj].z, sc[i][jj]);
                    sc[i][jj] = fmaf(q4[i].w, k4[jj].w, sc[i][jj]);
                }
        }

        // online softmax update
#pragma unroll
        for (int i = 0; i < 4; i++) {
            float mt = -1e30f;
#pragma unroll
            for (int jj = 0; jj < 4; jj++) {
                sc[i][jj] *= kSCALE;
                mt = fmaxf(mt, sc[i][jj]);
            }
            mt = redmax16(mt);
            float mn = fmaxf(m[i], mt);
            float al = __expf(m[i] - mn);
            float sum = 0.f;
#pragma unroll
            for (int jj = 0; jj < 4; jj++) {
                float p = __expf(sc[i][jj] - mn);
                sP[(ty*4 + i)*P_PAD + tx + 16*jj] = p;
                sum += p;
            }
            sum = redsum16(sum);
            l[i] = l[i]*al + sum;
            m[i] = mn;
#pragma unroll
            for (int c = 0; c < 8; c++) o[i][c] *= al;
        }
        __syncthreads();

        // O += P @ V
#pragma unroll 4
        for (int j = 0; j < 64; j++) {
            float pv[4];
#pragma unroll
            for (int i = 0; i < 4; i++) pv[i] = sP[(ty*4 + i)*P_PAD + j];
            float4 v0 = *(const float4*)&sV[j*QK_PAD + tx*8];
            float4 v1 = *(const float4*)&sV[j*QK_PAD + tx*8 + 4];
            float vv[8] = {v0.x,v0.y,v0.z,v0.w,v1.x,v1.y,v1.z,v1.w};
#pragma unroll
            for (int i = 0; i < 4; i++)
#pragma unroll
                for (int c = 0; c < 8; c++)
                    o[i][c] = fmaf(pv[i], vv[c], o[i][c]);
        }
    }

    // write AO[t][h*HD + d]
#pragma unroll
    for (int i = 0; i < 4; i++) {
        int s = qb*64 + ty*4 + i;
        int t = b*S_LEN + s;
        float inv = 1.f / l[i];
        float4 w0 = make_float4(o[i][0]*inv, o[i][1]*inv, o[i][2]*inv, o[i][3]*inv);
        float4 w1 = make_float4(o[i][4]*inv, o[i][5]*inv, o[i][6]*inv, o[i][7]*inv);
        float* op = &AO[(size_t)t*HDIM + h*HD + tx*8];
        *(float4*)op       = w0;
        *(float4*)(op + 4) = w1;
    }
}

// ---------------------------------------------------------------------------
extern "C" void kernel_launch(void* const* d_in, const int* in_sizes, int n_in,
                              void* d_out, int out_size)
{
    const float* hidden = (const float*)d_in[0];
    const float* cosp   = (const float*)d_in[1];
    const float* sinp   = (const float*)d_in[2];
    const float* Wq     = (const float*)d_in[3];
    const float* Wk     = (const float*)d_in[4];
    const float* bk     = (const float*)d_in[5];
    const float* Wv     = (const float*)d_in[6];
    const float* bv     = (const float*)d_in[7];
    const float* Wo     = (const float*)d_in[8];
    float* out = (float*)d_out;

    float *Qp, *Kp, *Vp, *AOp;
    cudaGetSymbolAddress((void**)&Qp,  g_Q);
    cudaGetSymbolAddress((void**)&Kp,  g_K);
    cudaGetSymbolAddress((void**)&Vp,  g_V);
    cudaGetSymbolAddress((void**)&AOp, g_AO);

    dim3 blk(256);
    // Q = rope(hidden @ Wq^T)          -> [b][h][s][d]
    gemm_k<1><<<dim3(HDIM/128, T_TOK/128), blk>>>(hidden, Wq, nullptr, Qp,
                                                  HDIM, HDIM, cosp, sinp, NH);
    // K = rope(hidden @ Wk^T + bk)     -> [b][kv][s][d]
    gemm_k<1><<<dim3(KV_N/128, T_TOK/128), blk>>>(hidden, Wk, bk, Kp,
                                                  KV_N, HDIM, cosp, sinp, NKV);
    // V = hidden @ Wv^T + bv           -> [b][kv][s][d]
    gemm_k<2><<<dim3(KV_N/128, T_TOK/128), blk>>>(hidden, Wv, bv, Vp,
                                                  KV_N, HDIM, nullptr, nullptr, NKV);

    size_t smem = (size_t)(3*64*QK_PAD + 64*P_PAD) * sizeof(float); // 118784 B
    cudaFuncSetAttribute(attn_k, cudaFuncAttributeMaxDynamicSharedMemorySize,
                         (int)smem);
    attn_k<<<dim3(S_LEN/64, BATCH*NH), blk, smem>>>(Qp, Kp, Vp, AOp);

    // out = AO @ Wo^T
    gemm_k<0><<<dim3(HDIM/128, T_TOK/128), blk>>>(AOp, Wo, nullptr, out,
                                                  HDIM, HDIM, nullptr, nullptr, 0);
}

// round 3
// speedup vs baseline: 1.6902x; 1.6902x over previous
#include <cuda_runtime.h>
#include <cuda_bf16.h>
#include <cstdint>
#include <math.h>

#define S_LEN 2048
#define BATCH 2
#define HDIM  4096
#define HD    128
#define NH    32
#define NKV   8
#define T_TOK (BATCH*S_LEN)   // 4096 tokens
#define KV_N  (NKV*HD)        // 1024

static __device__ __constant__ float kSCALE = 0.08838834764831845f; // 128^-0.5

// ---------------- scratch (__device__ globals; no allocation allowed) -------
__device__ float g_Q[(size_t)BATCH*NH*S_LEN*HD];    // [b][h][s][d]
__device__ float g_K[(size_t)BATCH*NKV*S_LEN*HD];   // [b][kv][s][d]
__device__ float g_V[(size_t)BATCH*NKV*S_LEN*HD];   // [b][kv][s][d]
__device__ float g_AO[(size_t)T_TOK*HDIM];          // attn out [t][h*HD+d]

__device__ __nv_bfloat16 g_Hh[(size_t)T_TOK*HDIM];
__device__ __nv_bfloat16 g_Hl[(size_t)T_TOK*HDIM];
__device__ __nv_bfloat16 g_Wqh[(size_t)HDIM*HDIM];
__device__ __nv_bfloat16 g_Wql[(size_t)HDIM*HDIM];
__device__ __nv_bfloat16 g_Wkh[(size_t)KV_N*HDIM];
__device__ __nv_bfloat16 g_Wkl[(size_t)KV_N*HDIM];
__device__ __nv_bfloat16 g_Wvh[(size_t)KV_N*HDIM];
__device__ __nv_bfloat16 g_Wvl[(size_t)KV_N*HDIM];
__device__ __nv_bfloat16 g_Woh[(size_t)HDIM*HDIM];
__device__ __nv_bfloat16 g_Wol[(size_t)HDIM*HDIM];
__device__ __nv_bfloat16 g_AOh[(size_t)T_TOK*HDIM];
__device__ __nv_bfloat16 g_AOl[(size_t)T_TOK*HDIM];

// ---------------- PTX helpers (sm_103 base target: mma.sync/ldmatrix/cp.async)
__device__ __forceinline__ uint32_t smem_to_u32(const void* p) {
    uint32_t a;
    asm("{ .reg .u64 t; cvta.to.shared.u64 t, %1; cvt.u32.u64 %0, t; }"
        : "=r"(a) : "l"(p));
    return a;
}
__device__ __forceinline__ void ldsm_x4(uint32_t* r, uint32_t addr) {
    asm volatile("ldmatrix.sync.aligned.m8n8.x4.shared.b16 {%0,%1,%2,%3}, [%4];"
                 : "=r"(r[0]), "=r"(r[1]), "=r"(r[2]), "=r"(r[3]) : "r"(addr));
}
__device__ __forceinline__ void mma16816(float* d, const uint32_t* a, const uint32_t* b) {
    asm volatile(
        "mma.sync.aligned.m16n8k16.row.col.f32.bf16.bf16.f32 "
        "{%0,%1,%2,%3}, {%4,%5,%6,%7}, {%8,%9}, {%0,%1,%2,%3};"
        : "+f"(d[0]), "+f"(d[1]), "+f"(d[2]), "+f"(d[3])
        : "r"(a[0]), "r"(a[1]), "r"(a[2]), "r"(a[3]), "r"(b[0]), "r"(b[1]));
}
#define CP_ASYNC16(dst, src) \
    asm volatile("cp.async.cg.shared.global [%0], [%1], 16;" \
                 :: "r"(dst), "l"(src))
#define CP_COMMIT() asm volatile("cp.async.commit_group;" ::: "memory")
#define CP_WAIT(n)  asm volatile("cp.async.wait_group %0;" :: "n"(n) : "memory")

// ---------------- fp32 -> bf16 hi/lo split conversion -----------------------
__global__ void __launch_bounds__(256)
cvt_k(const float* __restrict__ x, __nv_bfloat16* __restrict__ h,
      __nv_bfloat16* __restrict__ l, int n)
{
    int i = (blockIdx.x * 256 + threadIdx.x) * 4;
    if (i >= n) return;
    float4 v = *(const float4*)(x + i);
    __nv_bfloat16 h0 = __float2bfloat16(v.x);
    __nv_bfloat16 h1 = __float2bfloat16(v.y);
    __nv_bfloat16 h2 = __float2bfloat16(v.z);
    __nv_bfloat16 h3 = __float2bfloat16(v.w);
    __nv_bfloat16 l0 = __float2bfloat16(v.x - __bfloat162float(h0));
    __nv_bfloat16 l1 = __float2bfloat16(v.y - __bfloat162float(h1));
    __nv_bfloat16 l2 = __float2bfloat16(v.z - __bfloat162float(h2));
    __nv_bfloat16 l3 = __float2bfloat16(v.w - __bfloat162float(h3));
    *(__nv_bfloat162*)(h + i)     = __halves2bfloat162(h0, h1);
    *(__nv_bfloat162*)(h + i + 2) = __halves2bfloat162(h2, h3);
    *(__nv_bfloat162*)(l + i)     = __halves2bfloat162(l0, l1);
    *(__nv_bfloat162*)(l + i + 2) = __halves2bfloat162(l2, l3);
}

// ---------------------------------------------------------------------------
// HMMA split-bf16 GEMM: C[M,N] = A[M,K] @ B[N,K]^T (+bias), K=4096.
// Block 128x128x32, 256 thr (8 warps 4Mx2N), warp tile 32x64.
// SMEM tiles: 128 rows x 32 bf16, row stride 80B (conflict-free ldmatrix).
// Per K-step: 3 MMA passes (AhBh + AlBh + AhBl) into one fp32 accumulator.
// MODE 0: plain row-major store    (O projection -> d_out)
// MODE 1: bias? + RoPE + permute to [b][head][s][d]  (Q, K)
// MODE 2: bias + permute to [b][head][s][d]          (V)
// ---------------------------------------------------------------------------
#define BK 32
#define ROWB 80                    // bytes per smem row (32 bf16 + 16B pad)
#define TILE_BYTES (128*ROWB)      // 10240
#define BUFSZ (4*TILE_BYTES)       // Ah,Al,Bh,Bl = 40960
#define GEMM_SMEM (2*BUFSZ)        // 81920

template<int MODE>
__global__ void __launch_bounds__(256, 2)
gemm_tc(const __nv_bfloat16* __restrict__ Agh, const __nv_bfloat16* __restrict__ Agl,
        const __nv_bfloat16* __restrict__ Bgh, const __nv_bfloat16* __restrict__ Bgl,
        const float* __restrict__ bias, float* __restrict__ C,
        const float* __restrict__ cosp, const float* __restrict__ sinp,
        int n_heads)
{
    extern __shared__ char smem[];
    const uint32_t sbase = smem_to_u32(smem);
    const int tid = threadIdx.x;
    const int w   = tid >> 5;
    const int l   = tid & 31;
    const int wm  = w >> 1;          // 0..3
    const int wn  = w & 1;           // 0..1
    const int bm = blockIdx.y, bn = blockIdx.x;
    const int K = HDIM;
    const int NIT = K / BK;          // 128

    // per-thread load slots: chunks tid and tid+256 of each 128x32 tile
    const int r0 = tid >> 2,        c0 = tid & 3;          // rows 0..63
    const int r1 = (tid + 256) >> 2;                       // rows 64..127

    float acc[2][8][4];
#pragma unroll
    for (int mt = 0; mt < 2; mt++)
#pragma unroll
        for (int nt = 0; nt < 8; nt++)
#pragma unroll
            for (int e = 0; e < 4; e++) acc[mt][nt][e] = 0.f;

    // prologue: load tile 0
    {
        const int k0 = 0;
        uint32_t dst = sbase;
        const __nv_bfloat16* srcs[4] = {Agh, Agl, Bgh, Bgl};
        const int rowoff[4] = {bm*128, bm*128, bn*128, bn*128};
#pragma unroll
        for (int tno = 0; tno < 4; tno++) {
            const __nv_bfloat16* s = srcs[tno];
            CP_ASYNC16(dst + r0*ROWB + c0*16, s + (size_t)(rowoff[tno]+r0)*K + k0 + c0*8);
            CP_ASYNC16(dst + r1*ROWB + c0*16, s + (size_t)(rowoff[tno]+r1)*K + k0 + c0*8);
            dst += TILE_BYTES;
        }
        CP_COMMIT();
    }

    for (int it = 0; it < NIT; it++) {
        __syncthreads();   // all warps done computing it-1 (protects buf (it+1)&1)
        if (it + 1 < NIT) {
            const int k0 = (it + 1) * BK;
            uint32_t dst = sbase + ((it + 1) & 1) * BUFSZ;
            const __nv_bfloat16* srcs[4] = {Agh, Agl, Bgh, Bgl};
            const int rowoff[4] = {bm*128, bm*128, bn*128, bn*128};
#pragma unroll
            for (int tno = 0; tno < 4; tno++) {
                const __nv_bfloat16* s = srcs[tno];
                CP_ASYNC16(dst + r0*ROWB + c0*16, s + (size_t)(rowoff[tno]+r0)*K + k0 + c0*8);
                CP_ASYNC16(dst + r1*ROWB + c0*16, s + (size_t)(rowoff[tno]+r1)*K + k0 + c0*8);
                dst += TILE_BYTES;
            }
        }
        CP_COMMIT();
        CP_WAIT(1);        // tile `it` resident
        __syncthreads();

        const uint32_t sAh = sbase + (it & 1) * BUFSZ;
        const uint32_t sAl = sAh + TILE_BYTES;
        const uint32_t sBh = sAh + 2*TILE_BYTES;
        const uint32_t sBl = sAh + 3*TILE_BYTES;

#pragma unroll
        for (int ks = 0; ks < 2; ks++) {
            const uint32_t koff = ks*32 + ((l >> 4) * 16);           // A chunk sel
            const uint32_t aoff = (uint32_t)(wm*32 + (l & 15)) * ROWB + koff;
            const uint32_t boff = (uint32_t)(wn*64 + ((l >> 4) << 3) + (l & 7)) * ROWB
                                  + ks*32 + (((l >> 3) & 1) * 16);
            uint32_t ah[2][4], al[2][4], bh[4][4], bl[4][4];
#pragma unroll
            for (int mt = 0; mt < 2; mt++) ldsm_x4(ah[mt], sAh + aoff + mt*16*ROWB);
#pragma unroll
            for (int bt = 0; bt < 4; bt++) ldsm_x4(bh[bt], sBh + boff + bt*16*ROWB);
#pragma unroll
            for (int mt = 0; mt < 2; mt++)
#pragma unroll
                for (int bt = 0; bt < 4; bt++) {
                    mma16816(acc[mt][2*bt],   ah[mt], &bh[bt][0]);
                    mma16816(acc[mt][2*bt+1], ah[mt], &bh[bt][2]);
                }
#pragma unroll
            for (int mt = 0; mt < 2; mt++) ldsm_x4(al[mt], sAl + aoff + mt*16*ROWB);
#pragma unroll
            for (int mt = 0; mt < 2; mt++)
#pragma unroll
                for (int bt = 0; bt < 4; bt++) {
                    mma16816(acc[mt][2*bt],   al[mt], &bh[bt][0]);
                    mma16816(acc[mt][2*bt+1], al[mt], &bh[bt][2]);
                }
#pragma unroll
            for (int bt = 0; bt < 4; bt++) ldsm_x4(bl[bt], sBl + boff + bt*16*ROWB);
#pragma unroll
            for (int mt = 0; mt < 2; mt++)
#pragma unroll
                for (int bt = 0; bt < 4; bt++) {
                    mma16816(acc[mt][2*bt],   ah[mt], &bl[bt][0]);
                    mma16816(acc[mt][2*bt+1], ah[mt], &bl[bt][2]);
                }
        }
    }

    // ---------------- epilogue ----------------
#pragma unroll
    for (int mt = 0; mt < 2; mt++) {
        const int rbase = bm*128 + wm*32 + mt*16 + (l >> 2);
#pragma unroll
        for (int half = 0; half < 2; half++) {
            const int t  = rbase + half*8;          // token
            const int bb = t >> 11;
            const int s  = t & (S_LEN - 1);
#pragma unroll
            for (int nt = 0; nt < 8; nt++) {
                const int n0 = bn*128 + wn*64 + nt*8 + (l & 3)*2;
                float x1 = acc[mt][nt][half*2 + 0];
                float x2 = acc[mt][nt][half*2 + 1];
                if (MODE == 0) {
                    float* cp = C + (size_t)t*HDIM + n0;
                    cp[0] = x1; cp[1] = x2;
                } else {
                    const int head = n0 >> 7;
                    const int cl   = n0 & 127;
                    const size_t base = ((size_t)(bb*n_heads + head)*S_LEN + s) * HD;
                    if (MODE == 2) {
                        C[base + cl]     = x1 + bias[n0];
                        C[base + cl + 1] = x2 + bias[n0 + 1];
                    } else {
                        if (bias) { x1 += bias[n0]; x2 += bias[n0 + 1]; }
                        const int d = cl >> 1;
                        const float cs = cosp[s*64 + d];
                        const float sn = sinp[s*64 + d];
                        C[base + d]      = x1*cs - x2*sn;
                        C[base + 64 + d] = x1*sn + x2*cs;
                    }
                }
            }
        }
    }
}

// ---------------------------------------------------------------------------
// Flash attention (unchanged from R0 passing version)
// ---------------------------------------------------------------------------
__device__ __forceinline__ float redmax16(float v) {
#pragma unroll
    for (int o = 1; o < 16; o <<= 1)
        v = fmaxf(v, __shfl_xor_sync(0xffffffffu, v, o));
    return v;
}
__device__ __forceinline__ float redsum16(float v) {
#pragma unroll
    for (int o = 1; o < 16; o <<= 1)
        v += __shfl_xor_sync(0xffffffffu, v, o);
    return v;
}

#define QK_PAD 132
#define P_PAD  68

__global__ void __launch_bounds__(256)
attn_k(const float* __restrict__ Q, const float* __restrict__ K,
       const float* __restrict__ V, float* __restrict__ AO)
{
    extern __shared__ float sm[];
    float* sQ = sm;
    float* sK = sQ + 64*QK_PAD;
    float* sV = sK + 64*QK_PAD;
    float* sP = sV + 64*QK_PAD;

    const int tid = threadIdx.x;
    const int qb = blockIdx.x;
    const int bh = blockIdx.y;
    const int b  = bh / NH;
    const int h  = bh % NH;
    const int kv = h >> 2;

    const float* Qb = Q + ((size_t)bh*S_LEN + qb*64)*HD;
    const float* Kb = K + ((size_t)(b*NKV + kv)*S_LEN)*HD;
    const float* Vb = V + ((size_t)(b*NKV + kv)*S_LEN)*HD;

#pragma unroll
    for (int u = 0; u < 8; u++) {
        int f = tid + u*256;
        int r = f >> 5, c = (f & 31) * 4;
        *(float4*)&sQ[r*QK_PAD + c] = *(const float4*)&Qb[r*128 + c];
    }

    const int ty = tid >> 4, tx = tid & 15;
    float m[4], l[4], o[4][8];
#pragma unroll
    for (int i = 0; i < 4; i++) {
        m[i] = -1e30f; l[i] = 0.f;
#pragma unroll
        for (int c = 0; c < 8; c++) o[i][c] = 0.f;
    }

    for (int kt = 0; kt < S_LEN/64; kt++) {
        __syncthreads();
        const float* Kt = Kb + (size_t)kt*64*HD;
        const float* Vt = Vb + (size_t)kt*64*HD;
#pragma unroll
        for (int u = 0; u < 8; u++) {
            int f = tid + u*256;
            int r = f >> 5, c = (f & 31) * 4;
            *(float4*)&sK[r*QK_PAD + c] = *(const float4*)&Kt[r*128 + c];
            *(float4*)&sV[r*QK_PAD + c] = *(const float4*)&Vt[r*128 + c];
        }
        __syncthreads();

        float sc[4][4];
#pragma unroll
        for (int i = 0; i < 4; i++)
#pragma unroll
            for (int jj = 0; jj < 4; jj++) sc[i][jj] = 0.f;

#pragma unroll 4
        for (int d = 0; d < 128; d += 4) {
            float4 q4[4], k4[4];
#pragma unroll
            for (int i = 0; i < 4; i++)
                q4[i] = *(const float4*)&sQ[(ty*4 + i)*QK_PAD + d];
#pragma unroll
            for (int jj = 0; jj < 4; jj++)
                k4[jj] = *(const float4*)&sK[(tx + 16*jj)*QK_PAD + d];
#pragma unroll
            for (int i = 0; i < 4; i++)
#pragma unroll
                for (int jj = 0; jj < 4; jj++) {
                    sc[i][jj] = fmaf(q4[i].x, k4[jj].x, sc[i][jj]);
                    sc[i][jj] = fmaf(q4[i].y, k4[jj].y, sc[i][jj]);
                    sc[i][jj] = fmaf(q4[i].z, k4[jj].z, sc[i][jj]);
                    sc[i][jj] = fmaf(q4[i].w, k4[jj].w, sc[i][jj]);
                }
        }

#pragma unroll
        for (int i = 0; i < 4; i++) {
            float mt = -1e30f;
#pragma unroll
            for (int jj = 0; jj < 4; jj++) {
                sc[i][jj] *= kSCALE;
                mt = fmaxf(mt, sc[i][jj]);
            }
            mt = redmax16(mt);
            float mn = fmaxf(m[i], mt);
            float al = __expf(m[i] - mn);
            float sum = 0.f;
#pragma unroll
            for (int jj = 0; jj < 4; jj++) {
                float p = __expf(sc[i][jj] - mn);
                sP[(ty*4 + i)*P_PAD + tx + 16*jj] = p;
                sum += p;
            }
            sum = redsum16(sum);
            l[i] = l[i]*al + sum;
            m[i] = mn;
#pragma unroll
            for (int c = 0; c < 8; c++) o[i][c] *= al;
        }
        __syncthreads();

#pragma unroll 4
        for (int j = 0; j < 64; j++) {
            float pv[4];
#pragma unroll
            for (int i = 0; i < 4; i++) pv[i] = sP[(ty*4 + i)*P_PAD + j];
            float4 v0 = *(const float4*)&sV[j*QK_PAD + tx*8];
            float4 v1 = *(const float4*)&sV[j*QK_PAD + tx*8 + 4];
            float vv[8] = {v0.x,v0.y,v0.z,v0.w,v1.x,v1.y,v1.z,v1.w};
#pragma unroll
            for (int i = 0; i < 4; i++)
#pragma unroll
                for (int c = 0; c < 8; c++)
                    o[i][c] = fmaf(pv[i], vv[c], o[i][c]);
        }
    }

#pragma unroll
    for (int i = 0; i < 4; i++) {
        int s = qb*64 + ty*4 + i;
        int t = b*S_LEN + s;
        float inv = 1.f / l[i];
        float4 w0 = make_float4(o[i][0]*inv, o[i][1]*inv, o[i][2]*inv, o[i][3]*inv);
        float4 w1 = make_float4(o[i][4]*inv, o[i][5]*inv, o[i][6]*inv, o[i][7]*inv);
        float* op = &AO[(size_t)t*HDIM + h*HD + tx*8];
        *(float4*)op       = w0;
        *(float4*)(op + 4) = w1;
    }
}

// ---------------------------------------------------------------------------
extern "C" void kernel_launch(void* const* d_in, const int* in_sizes, int n_in,
                              void* d_out, int out_size)
{
    const float* hidden = (const float*)d_in[0];
    const float* cosp   = (const float*)d_in[1];
    const float* sinp   = (const float*)d_in[2];
    const float* Wq     = (const float*)d_in[3];
    const float* Wk     = (const float*)d_in[4];
    const float* bk     = (const float*)d_in[5];
    const float* Wv     = (const float*)d_in[6];
    const float* bv     = (const float*)d_in[7];
    const float* Wo     = (const float*)d_in[8];
    float* out = (float*)d_out;

    float *Qp, *Kp, *Vp, *AOp;
    cudaGetSymbolAddress((void**)&Qp,  g_Q);
    cudaGetSymbolAddress((void**)&Kp,  g_K);
    cudaGetSymbolAddress((void**)&Vp,  g_V);
    cudaGetSymbolAddress((void**)&AOp, g_AO);
    __nv_bfloat16 *Hh,*Hl,*Wqh,*Wql,*Wkh,*Wkl,*Wvh,*Wvl,*Woh,*Wol,*AOh,*AOl;
    cudaGetSymbolAddress((void**)&Hh,  g_Hh);  cudaGetSymbolAddress((void**)&Hl,  g_Hl);
    cudaGetSymbolAddress((void**)&Wqh, g_Wqh); cudaGetSymbolAddress((void**)&Wql, g_Wql);
    cudaGetSymbolAddress((void**)&Wkh, g_Wkh); cudaGetSymbolAddress((void**)&Wkl, g_Wkl);
    cudaGetSymbolAddress((void**)&Wvh, g_Wvh); cudaGetSymbolAddress((void**)&Wvl, g_Wvl);
    cudaGetSymbolAddress((void**)&Woh, g_Woh); cudaGetSymbolAddress((void**)&Wol, g_Wol);
    cudaGetSymbolAddress((void**)&AOh, g_AOh); cudaGetSymbolAddress((void**)&AOl, g_AOl);

    static bool attr_set = false;
    if (!attr_set) {
        cudaFuncSetAttribute(gemm_tc<0>, cudaFuncAttributeMaxDynamicSharedMemorySize, GEMM_SMEM);
        cudaFuncSetAttribute(gemm_tc<1>, cudaFuncAttributeMaxDynamicSharedMemorySize, GEMM_SMEM);
        cudaFuncSetAttribute(gemm_tc<2>, cudaFuncAttributeMaxDynamicSharedMemorySize, GEMM_SMEM);
        cudaFuncSetAttribute(attn_k, cudaFuncAttributeMaxDynamicSharedMemorySize,
                             (int)((3*64*QK_PAD + 64*P_PAD) * sizeof(float)));
        attr_set = true;
    }

    // convert fp32 inputs to bf16 hi/lo pairs
    {
        int nH = T_TOK*HDIM;   // 16M
        int nW = HDIM*HDIM;    // 16M
        int nK = KV_N*HDIM;    // 4M
        cvt_k<<<nH/1024, 256>>>(hidden, Hh, Hl, nH);
        cvt_k<<<nW/1024, 256>>>(Wq, Wqh, Wql, nW);
        cvt_k<<<nK/1024, 256>>>(Wk, Wkh, Wkl, nK);
        cvt_k<<<nK/1024, 256>>>(Wv, Wvh, Wvl, nK);
        cvt_k<<<nW/1024, 256>>>(Wo, Woh, Wol, nW);
    }

    // Q = rope(hidden @ Wq^T)  -> [b][h][s][d]
    gemm_tc<1><<<dim3(HDIM/128, T_TOK/128), 256, GEMM_SMEM>>>(
        Hh, Hl, Wqh, Wql, nullptr, Qp, cosp, sinp, NH);
    // K = rope(hidden @ Wk^T + bk)
    gemm_tc<1><<<dim3(KV_N/128, T_TOK/128), 256, GEMM_SMEM>>>(
        Hh, Hl, Wkh, Wkl, bk, Kp, cosp, sinp, NKV);
    // V = hidden @ Wv^T + bv
    gemm_tc<2><<<dim3(KV_N/128, T_TOK/128), 256, GEMM_SMEM>>>(
        Hh, Hl, Wvh, Wvl, bv, Vp, nullptr, nullptr, NKV);

    size_t smem = (size_t)(3*64*QK_PAD + 64*P_PAD) * sizeof(float);
    attn_k<<<dim3(S_LEN/64, BATCH*NH), 256, smem>>>(Qp, Kp, Vp, AOp);

    // convert AO, then out = AO @ Wo^T
    cvt_k<<<(T_TOK*HDIM)/1024, 256>>>(AOp, AOh, AOl, T_TOK*HDIM);
    gemm_tc<0><<<dim3(HDIM/128, T_TOK/128), 256, GEMM_SMEM>>>(
        AOh, AOl, Woh, Wol, nullptr, out, nullptr, nullptr, 0);
}

// round 6
// speedup vs baseline: 3.1155x; 1.8432x over previous
#include <cuda_runtime.h>
#include <cuda_bf16.h>
#include <cstdint>
#include <math.h>

#define S_LEN 2048
#define BATCH 2
#define HDIM  4096
#define HD    128
#define NH    32
#define NKV   8
#define T_TOK (BATCH*S_LEN)   // 4096 tokens
#define KV_N  (NKV*HD)        // 1024

// SCALE * log2(e) folded into Q so softmax works in exp2 domain
#define Q_SCALE (0.08838834764831845f * 1.4426950408889634f)

// ---------------- scratch (__device__ globals; no allocation allowed) -------
__device__ __nv_bfloat16 g_Hh[(size_t)T_TOK*HDIM];
__device__ __nv_bfloat16 g_Hl[(size_t)T_TOK*HDIM];
__device__ __nv_bfloat16 g_Wqh[(size_t)HDIM*HDIM];
__device__ __nv_bfloat16 g_Wql[(size_t)HDIM*HDIM];
__device__ __nv_bfloat16 g_Wkh[(size_t)KV_N*HDIM];
__device__ __nv_bfloat16 g_Wkl[(size_t)KV_N*HDIM];
__device__ __nv_bfloat16 g_Wvh[(size_t)KV_N*HDIM];
__device__ __nv_bfloat16 g_Wvl[(size_t)KV_N*HDIM];
__device__ __nv_bfloat16 g_Woh[(size_t)HDIM*HDIM];
__device__ __nv_bfloat16 g_Wol[(size_t)HDIM*HDIM];

__device__ __nv_bfloat16 g_Qh[(size_t)BATCH*NH*S_LEN*HD];   // [b][h][s][d] (scaled)
__device__ __nv_bfloat16 g_Ql[(size_t)BATCH*NH*S_LEN*HD];
__device__ __nv_bfloat16 g_Kh[(size_t)BATCH*NKV*S_LEN*HD];  // [b][kv][s][d]
__device__ __nv_bfloat16 g_Kl[(size_t)BATCH*NKV*S_LEN*HD];
__device__ __nv_bfloat16 g_Vth[(size_t)BATCH*NKV*HD*S_LEN]; // [b][kv][d][s] (transposed)
__device__ __nv_bfloat16 g_Vtl[(size_t)BATCH*NKV*HD*S_LEN];
__device__ __nv_bfloat16 g_AOh[(size_t)T_TOK*HDIM];         // [t][h*HD+d]
__device__ __nv_bfloat16 g_AOl[(size_t)T_TOK*HDIM];

// ---------------- PTX helpers ----------------
__device__ __forceinline__ uint32_t smem_to_u32(const void* p) {
    uint32_t a;
    asm("{ .reg .u64 t; cvta.to.shared.u64 t, %1; cvt.u32.u64 %0, t; }"
        : "=r"(a) : "l"(p));
    return a;
}
__device__ __forceinline__ void ldsm_x4(uint32_t* r, uint32_t addr) {
    asm volatile("ldmatrix.sync.aligned.m8n8.x4.shared.b16 {%0,%1,%2,%3}, [%4];"
                 : "=r"(r[0]), "=r"(r[1]), "=r"(r[2]), "=r"(r[3]) : "r"(addr));
}
__device__ __forceinline__ void mma16816(float* d, const uint32_t* a, const uint32_t* b) {
    asm volatile(
        "mma.sync.aligned.m16n8k16.row.col.f32.bf16.bf16.f32 "
        "{%0,%1,%2,%3}, {%4,%5,%6,%7}, {%8,%9}, {%0,%1,%2,%3};"
        : "+f"(d[0]), "+f"(d[1]), "+f"(d[2]), "+f"(d[3])
        : "r"(a[0]), "r"(a[1]), "r"(a[2]), "r"(a[3]), "r"(b[0]), "r"(b[1]));
}
#define CP_ASYNC16(dst, src) \
    asm volatile("cp.async.cg.shared.global [%0], [%1], 16;" \
                 :: "r"(dst), "l"(src))
#define CP_COMMIT() asm volatile("cp.async.commit_group;" ::: "memory")
#define CP_WAIT(n)  asm volatile("cp.async.wait_group %0;" :: "n"(n) : "memory")

__device__ __forceinline__ float ex2f(float x) {
    float y;
    asm("ex2.approx.ftz.f32 %0, %1;" : "=f"(y) : "f"(x));
    return y;
}
// pack two fp32 -> bf16x2 reg (lo = a, hi = b), round-nearest
__device__ __forceinline__ uint32_t pack_bf16x2(float a, float b) {
    uint32_t r;
    asm("cvt.rn.bf16x2.f32 %0, %1, %2;" : "=r"(r) : "f"(b), "f"(a));
    return r;
}

// ---------------- fp32 -> bf16 hi/lo split conversion -----------------------
__global__ void __launch_bounds__(256)
cvt_k(const float* __restrict__ x, __nv_bfloat16* __restrict__ h,
      __nv_bfloat16* __restrict__ l, int n)
{
    int i = (blockIdx.x * 256 + threadIdx.x) * 4;
    if (i >= n) return;
    float4 v = *(const float4*)(x + i);
    __nv_bfloat16 h0 = __float2bfloat16(v.x);
    __nv_bfloat16 h1 = __float2bfloat16(v.y);
    __nv_bfloat16 h2 = __float2bfloat16(v.z);
    __nv_bfloat16 h3 = __float2bfloat16(v.w);
    __nv_bfloat16 l0 = __float2bfloat16(v.x - __bfloat162float(h0));
    __nv_bfloat16 l1 = __float2bfloat16(v.y - __bfloat162float(h1));
    __nv_bfloat16 l2 = __float2bfloat16(v.z - __bfloat162float(h2));
    __nv_bfloat16 l3 = __float2bfloat16(v.w - __bfloat162float(h3));
    *(__nv_bfloat162*)(h + i)     = __halves2bfloat162(h0, h1);
    *(__nv_bfloat162*)(h + i + 2) = __halves2bfloat162(h2, h3);
    *(__nv_bfloat162*)(l + i)     = __halves2bfloat162(l0, l1);
    *(__nv_bfloat162*)(l + i + 2) = __halves2bfloat162(l2, l3);
}

// ---------------------------------------------------------------------------
// HMMA split-bf16 GEMM: block 128x128x32, 8 warps (4Mx2N), warp tile 32x64.
// MODE 0: fp32 row-major store (O projection -> d_out)
// MODE 1: bias? + RoPE + scale, store bf16 hi/lo to [b][head][s][d]  (Q, K)
// MODE 2: bias, store bf16 hi/lo TRANSPOSED to [b][head][d][s]       (V)
// ---------------------------------------------------------------------------
#define BK 32
#define ROWB 80
#define TILE_BYTES (128*ROWB)
#define BUFSZ (4*TILE_BYTES)
#define GEMM_SMEM (2*BUFSZ)

template<int MODE>
__global__ void __launch_bounds__(256, 2)
gemm_tc(const __nv_bfloat16* __restrict__ Agh, const __nv_bfloat16* __restrict__ Agl,
        const __nv_bfloat16* __restrict__ Bgh, const __nv_bfloat16* __restrict__ Bgl,
        const float* __restrict__ bias, float* __restrict__ Cf,
        __nv_bfloat16* __restrict__ Ch, __nv_bfloat16* __restrict__ Cl,
        const float* __restrict__ cosp, const float* __restrict__ sinp,
        int n_heads, float scale)
{
    extern __shared__ char smem[];
    const uint32_t sbase = smem_to_u32(smem);
    const int tid = threadIdx.x;
    const int w   = tid >> 5;
    const int l   = tid & 31;
    const int wm  = w >> 1;
    const int wn  = w & 1;
    const int bm = blockIdx.y, bn = blockIdx.x;
    const int K = HDIM;
    const int NIT = K / BK;

    const int r0 = tid >> 2, c0 = tid & 3;
    const int r1 = (tid + 256) >> 2;

    float acc[2][8][4];
#pragma unroll
    for (int mt = 0; mt < 2; mt++)
#pragma unroll
        for (int nt = 0; nt < 8; nt++)
#pragma unroll
            for (int e = 0; e < 4; e++) acc[mt][nt][e] = 0.f;

    {
        uint32_t dst = sbase;
        const __nv_bfloat16* srcs[4] = {Agh, Agl, Bgh, Bgl};
        const int rowoff[4] = {bm*128, bm*128, bn*128, bn*128};
#pragma unroll
        for (int tno = 0; tno < 4; tno++) {
            const __nv_bfloat16* s = srcs[tno];
            CP_ASYNC16(dst + r0*ROWB + c0*16, s + (size_t)(rowoff[tno]+r0)*K + c0*8);
            CP_ASYNC16(dst + r1*ROWB + c0*16, s + (size_t)(rowoff[tno]+r1)*K + c0*8);
            dst += TILE_BYTES;
        }
        CP_COMMIT();
    }

    for (int it = 0; it < NIT; it++) {
        __syncthreads();
        if (it + 1 < NIT) {
            const int k0 = (it + 1) * BK;
            uint32_t dst = sbase + ((it + 1) & 1) * BUFSZ;
            const __nv_bfloat16* srcs[4] = {Agh, Agl, Bgh, Bgl};
            const int rowoff[4] = {bm*128, bm*128, bn*128, bn*128};
#pragma unroll
            for (int tno = 0; tno < 4; tno++) {
                const __nv_bfloat16* s = srcs[tno];
                CP_ASYNC16(dst + r0*ROWB + c0*16, s + (size_t)(rowoff[tno]+r0)*K + k0 + c0*8);
                CP_ASYNC16(dst + r1*ROWB + c0*16, s + (size_t)(rowoff[tno]+r1)*K + k0 + c0*8);
                dst += TILE_BYTES;
            }
        }
        CP_COMMIT();
        CP_WAIT(1);
        __syncthreads();

        const uint32_t sAh = sbase + (it & 1) * BUFSZ;
        const uint32_t sAl = sAh + TILE_BYTES;
        const uint32_t sBh = sAh + 2*TILE_BYTES;
        const uint32_t sBl = sAh + 3*TILE_BYTES;

#pragma unroll
        for (int ks = 0; ks < 2; ks++) {
            const uint32_t koff = ks*32 + ((l >> 4) * 16);
            const uint32_t aoff = (uint32_t)(wm*32 + (l & 15)) * ROWB + koff;
            const uint32_t boff = (uint32_t)(wn*64 + ((l >> 4) << 3) + (l & 7)) * ROWB
                                  + ks*32 + (((l >> 3) & 1) * 16);
            uint32_t ah[2][4], al[2][4], bh[4][4], bl[4][4];
#pragma unroll
            for (int mt = 0; mt < 2; mt++) ldsm_x4(ah[mt], sAh + aoff + mt*16*ROWB);
#pragma unroll
            for (int bt = 0; bt < 4; bt++) ldsm_x4(bh[bt], sBh + boff + bt*16*ROWB);
#pragma unroll
            for (int mt = 0; mt < 2; mt++)
#pragma unroll
                for (int bt = 0; bt < 4; bt++) {
                    mma16816(acc[mt][2*bt],   ah[mt], &bh[bt][0]);
                    mma16816(acc[mt][2*bt+1], ah[mt], &bh[bt][2]);
                }
#pragma unroll
            for (int mt = 0; mt < 2; mt++) ldsm_x4(al[mt], sAl + aoff + mt*16*ROWB);
#pragma unroll
            for (int mt = 0; mt < 2; mt++)
#pragma unroll
                for (int bt = 0; bt < 4; bt++) {
                    mma16816(acc[mt][2*bt],   al[mt], &bh[bt][0]);
                    mma16816(acc[mt][2*bt+1], al[mt], &bh[bt][2]);
                }
#pragma unroll
            for (int bt = 0; bt < 4; bt++) ldsm_x4(bl[bt], sBl + boff + bt*16*ROWB);
#pragma unroll
            for (int mt = 0; mt < 2; mt++)
#pragma unroll
                for (int bt = 0; bt < 4; bt++) {
                    mma16816(acc[mt][2*bt],   ah[mt], &bl[bt][0]);
                    mma16816(acc[mt][2*bt+1], ah[mt], &bl[bt][2]);
                }
        }
    }

    // ---------------- epilogue ----------------
#pragma unroll
    for (int mt = 0; mt < 2; mt++) {
        const int rbase = bm*128 + wm*32 + mt*16 + (l >> 2);
#pragma unroll
        for (int half = 0; half < 2; half++) {
            const int t  = rbase + half*8;
            const int bb = t >> 11;
            const int s  = t & (S_LEN - 1);
#pragma unroll
            for (int nt = 0; nt < 8; nt++) {
                const int n0 = bn*128 + wn*64 + nt*8 + (l & 3)*2;
                float x1 = acc[mt][nt][half*2 + 0];
                float x2 = acc[mt][nt][half*2 + 1];
                if (MODE == 0) {
                    float* cp = Cf + (size_t)t*HDIM + n0;
                    cp[0] = x1; cp[1] = x2;
                } else {
                    const int head = n0 >> 7;
                    const int cl   = n0 & 127;
                    if (MODE == 2) {
                        x1 += bias[n0]; x2 += bias[n0 + 1];
                        const size_t base = ((size_t)(bb*n_heads + head)*HD) * S_LEN;
                        __nv_bfloat16 h1 = __float2bfloat16(x1);
                        __nv_bfloat16 h2 = __float2bfloat16(x2);
                        Ch[base + (size_t)cl*S_LEN + s]     = h1;
                        Ch[base + (size_t)(cl+1)*S_LEN + s] = h2;
                        Cl[base + (size_t)cl*S_LEN + s]     = __float2bfloat16(x1 - __bfloat162float(h1));
                        Cl[base + (size_t)(cl+1)*S_LEN + s] = __float2bfloat16(x2 - __bfloat162float(h2));
                    } else {
                        if (bias) { x1 += bias[n0]; x2 += bias[n0 + 1]; }
                        const int d = cl >> 1;
                        const float cs = cosp[s*64 + d];
                        const float sn = sinp[s*64 + d];
                        float y1 = (x1*cs - x2*sn) * scale;
                        float y2 = (x1*sn + x2*cs) * scale;
                        const size_t base = ((size_t)(bb*n_heads + head)*S_LEN + s) * HD;
                        __nv_bfloat16 h1 = __float2bfloat16(y1);
                        __nv_bfloat16 h2 = __float2bfloat16(y2);
                        Ch[base + d]      = h1;
                        Ch[base + 64 + d] = h2;
                        Cl[base + d]      = __float2bfloat16(y1 - __bfloat162float(h1));
                        Cl[base + 64 + d] = __float2bfloat16(y2 - __bfloat162float(h2));
                    }
                }
            }
        }
    }
}

// ---------------------------------------------------------------------------
// HMMA flash attention: BM=128 (8 warps x 16 rows), BN=64 keys/tile, HD=128.
// Q (scaled, split) register-resident; K [s][d] / V^T [d][s] split, cp.async
// double-buffered. Scores = 3 passes; P split in registers; PV = 3 passes.
// Online softmax in exp2 domain. Output: AOh/AOl bf16 [t][h*HD+d].
// ---------------------------------------------------------------------------
#define KROW 272                   // K smem row stride bytes (128 bf16 + pad)
#define VROW 144                   // V^T smem row stride bytes (64 bf16 + pad)
#define OFF_KH 0
#define OFF_KL 17408
#define OFF_VH 34816
#define OFF_VL 53248
#define ABUF   71680               // one K/V buffer
#define ATTN_SMEM (2*ABUF)         // 143360

__global__ void __launch_bounds__(256, 1)
attn_tc(const __nv_bfloat16* __restrict__ Qh, const __nv_bfloat16* __restrict__ Ql,
        const __nv_bfloat16* __restrict__ Kh, const __nv_bfloat16* __restrict__ Kl,
        const __nv_bfloat16* __restrict__ Vth, const __nv_bfloat16* __restrict__ Vtl,
        __nv_bfloat16* __restrict__ AOh, __nv_bfloat16* __restrict__ AOl)
{
    extern __shared__ char smem[];
    const uint32_t sbase = smem_to_u32(smem);
    const int tid = threadIdx.x;
    const int w   = tid >> 5;
    const int l   = tid & 31;
    const int qb  = blockIdx.x;          // q block (128 rows)
    const int bh  = blockIdx.y;
    const int b   = bh / NH;
    const int h   = bh % NH;
    const int kv  = h >> 2;              // N_REP = 4

    const __nv_bfloat16* Qhb = Qh + ((size_t)bh*S_LEN + qb*128)*HD;
    const __nv_bfloat16* Qlb = Ql + ((size_t)bh*S_LEN + qb*128)*HD;
    const __nv_bfloat16* Khb = Kh + ((size_t)(b*NKV + kv)*S_LEN)*HD;
    const __nv_bfloat16* Klb = Kl + ((size_t)(b*NKV + kv)*S_LEN)*HD;
    const __nv_bfloat16* Vhb = Vth + ((size_t)(b*NKV + kv)*HD)*S_LEN;
    const __nv_bfloat16* Vlb = Vtl + ((size_t)(b*NKV + kv)*HD)*S_LEN;

    // ---- stage Q into smem (buf0 area), rows 0..127, stride KROW ----
    {
        // Qh at sbase+0, Ql at sbase+34816; 128 rows x 16 chunks of 16B
#pragma unroll
        for (int i = 0; i < 8; i++) {
            int id = tid + i*256;        // 0..2047
            int r = id >> 4, c = id & 15;
            *(uint4*)(smem + r*KROW + c*16) =
                *(const uint4*)(Qhb + (size_t)r*HD + c*8);
            *(uint4*)(smem + 34816 + r*KROW + c*16) =
                *(const uint4*)(Qlb + (size_t)r*HD + c*8);
        }
    }
    __syncthreads();

    // ---- load Q fragments to registers ----
    uint32_t qh[8][4], ql[8][4];
    {
        const uint32_t arow = (uint32_t)(w*16 + (l & 15)) * KROW;
#pragma unroll
        for (int kc = 0; kc < 8; kc++) {
            const uint32_t koff = kc*32 + ((l >> 4) * 16);
            ldsm_x4(qh[kc], sbase + arow + koff);
            ldsm_x4(ql[kc], sbase + 34816 + arow + koff);
        }
    }
    __syncthreads();   // everyone done reading Q staging before buf0 overwrite

    float o[16][4];
#pragma unroll
    for (int nt = 0; nt < 16; nt++)
#pragma unroll
        for (int e = 0; e < 4; e++) o[nt][e] = 0.f;
    float m0 = -1e30f, m1 = -1e30f, l0 = 0.f, l1 = 0.f;

    // ---- prologue: issue K/V tile 0 into buf0 ----
    {
        uint32_t dst = sbase;
#pragma unroll
        for (int i = 0; i < 4; i++) {
            int id = tid + i*256;
            int r = id >> 4, c = id & 15;             // K: 64 rows x 16 chunks
            CP_ASYNC16(dst + OFF_KH + r*KROW + c*16, Khb + (size_t)r*HD + c*8);
            CP_ASYNC16(dst + OFF_KL + r*KROW + c*16, Klb + (size_t)r*HD + c*8);
            int rv = id >> 3, cv = id & 7;            // V^T: 128 rows x 8 chunks
            CP_ASYNC16(dst + OFF_VH + rv*VROW + cv*16, Vhb + (size_t)rv*S_LEN + cv*8);
            CP_ASYNC16(dst + OFF_VL + rv*VROW + cv*16, Vlb + (size_t)rv*S_LEN + cv*8);
        }
        CP_COMMIT();
    }

    const int NKT = S_LEN / 64;   // 32
    for (int kt = 0; kt < NKT; kt++) {
        __syncthreads();
        if (kt + 1 < NKT) {
            uint32_t dst = sbase + ((kt + 1) & 1) * ABUF;
            const size_t ko = (size_t)(kt + 1) * 64 * HD;
            const size_t vo = (size_t)(kt + 1) * 64;
#pragma unroll
            for (int i = 0; i < 4; i++) {
                int id = tid + i*256;
                int r = id >> 4, c = id & 15;
                CP_ASYNC16(dst + OFF_KH + r*KROW + c*16, Khb + ko + (size_t)r*HD + c*8);
                CP_ASYNC16(dst + OFF_KL + r*KROW + c*16, Klb + ko + (size_t)r*HD + c*8);
                int rv = id >> 3, cv = id & 7;
                CP_ASYNC16(dst + OFF_VH + rv*VROW + cv*16, Vhb + vo + (size_t)rv*S_LEN + cv*8);
                CP_ASYNC16(dst + OFF_VL + rv*VROW + cv*16, Vlb + vo + (size_t)rv*S_LEN + cv*8);
            }
        }
        CP_COMMIT();
        CP_WAIT(1);
        __syncthreads();

        const uint32_t buf = sbase + (kt & 1) * ABUF;
        const uint32_t sKh = buf + OFF_KH;
        const uint32_t sKl = buf + OFF_KL;
        const uint32_t sVh = buf + OFF_VH;
        const uint32_t sVl = buf + OFF_VL;

        // ---- QK^T: 16x64 scores, 3 split passes ----
        float sc[8][4];
#pragma unroll
        for (int nt = 0; nt < 8; nt++)
#pragma unroll
            for (int e = 0; e < 4; e++) sc[nt][e] = 0.f;

        const uint32_t krow = (uint32_t)(((l >> 4) << 3) + (l & 7)) * KROW;
#pragma unroll
        for (int kc = 0; kc < 8; kc++) {
            const uint32_t kcol = kc*32 + (((l >> 3) & 1) * 16);
            uint32_t khf[4][4], klf[4][4];
#pragma unroll
            for (int bt = 0; bt < 4; bt++) ldsm_x4(khf[bt], sKh + krow + bt*16*KROW + kcol);
#pragma unroll
            for (int bt = 0; bt < 4; bt++) ldsm_x4(klf[bt], sKl + krow + bt*16*KROW + kcol);
#pragma unroll
            for (int bt = 0; bt < 4; bt++) {
                mma16816(sc[2*bt],   qh[kc], &khf[bt][0]);
                mma16816(sc[2*bt+1], qh[kc], &khf[bt][2]);
            }
#pragma unroll
            for (int bt = 0; bt < 4; bt++) {
                mma16816(sc[2*bt],   ql[kc], &khf[bt][0]);
                mma16816(sc[2*bt+1], ql[kc], &khf[bt][2]);
            }
#pragma unroll
            for (int bt = 0; bt < 4; bt++) {
                mma16816(sc[2*bt],   qh[kc], &klf[bt][0]);
                mma16816(sc[2*bt+1], qh[kc], &klf[bt][2]);
            }
        }

        // ---- online softmax (exp2 domain) ----
        float mt0 = -1e30f, mt1 = -1e30f;
#pragma unroll
        for (int nt = 0; nt < 8; nt++) {
            mt0 = fmaxf(mt0, fmaxf(sc[nt][0], sc[nt][1]));
            mt1 = fmaxf(mt1, fmaxf(sc[nt][2], sc[nt][3]));
        }
        mt0 = fmaxf(mt0, __shfl_xor_sync(0xffffffffu, mt0, 1));
        mt0 = fmaxf(mt0, __shfl_xor_sync(0xffffffffu, mt0, 2));
        mt1 = fmaxf(mt1, __shfl_xor_sync(0xffffffffu, mt1, 1));
        mt1 = fmaxf(mt1, __shfl_xor_sync(0xffffffffu, mt1, 2));
        const float mn0 = fmaxf(m0, mt0);
        const float mn1 = fmaxf(m1, mt1);
        const float al0 = ex2f(m0 - mn0);
        const float al1 = ex2f(m1 - mn1);
        m0 = mn0; m1 = mn1;

        float lp0 = 0.f, lp1 = 0.f;
#pragma unroll
        for (int nt = 0; nt < 8; nt++) {
            sc[nt][0] = ex2f(sc[nt][0] - mn0); lp0 += sc[nt][0];
            sc[nt][1] = ex2f(sc[nt][1] - mn0); lp0 += sc[nt][1];
            sc[nt][2] = ex2f(sc[nt][2] - mn1); lp1 += sc[nt][2];
            sc[nt][3] = ex2f(sc[nt][3] - mn1); lp1 += sc[nt][3];
        }
        l0 = l0*al0 + lp0;
        l1 = l1*al1 + lp1;
#pragma unroll
        for (int nt = 0; nt < 16; nt++) {
            o[nt][0] *= al0; o[nt][1] *= al0;
            o[nt][2] *= al1; o[nt][3] *= al1;
        }

        // ---- P split hi/lo fragments (registers) ----
        uint32_t ph[4][4], pl[4][4];
#pragma unroll
        for (int kk = 0; kk < 4; kk++) {
#pragma unroll
            for (int e = 0; e < 4; e++) {
                const int nt = 2*kk + (e >> 1);
                const int i0 = (e & 1) * 2;
                float p0 = sc[nt][i0], p1 = sc[nt][i0+1];
                uint32_t hp = pack_bf16x2(p0, p1);
                ph[kk][e] = hp;
                float f0 = __uint_as_float(hp << 16);
                float f1 = __uint_as_float(hp & 0xFFFF0000u);
                pl[kk][e] = pack_bf16x2(p0 - f0, p1 - f1);
            }
        }

        // ---- O += P @ V  (3 split passes) ----
        const uint32_t vrow = (uint32_t)(((l >> 4) << 3) + (l & 7)) * VROW;
#pragma unroll
        for (int kk = 0; kk < 4; kk++) {
            const uint32_t vcol = kk*32 + (((l >> 3) & 1) * 16);
            uint32_t vhf[8][4], vlf[8][4];
#pragma unroll
            for (int nt = 0; nt < 8; nt++) ldsm_x4(vhf[nt], sVh + vrow + nt*16*VROW + vcol);
#pragma unroll
            for (int nt = 0; nt < 8; nt++) {
                mma16816(o[2*nt],   ph[kk], &vhf[nt][0]);
                mma16816(o[2*nt+1], ph[kk], &vhf[nt][2]);
            }
#pragma unroll
            for (int nt = 0; nt < 8; nt++) ldsm_x4(vlf[nt], sVl + vrow + nt*16*VROW + vcol);
#pragma unroll
            for (int nt = 0; nt < 8; nt++) {
                mma16816(o[2*nt],   pl[kk], &vhf[nt][0]);
                mma16816(o[2*nt+1], pl[kk], &vhf[nt][2]);
                mma16816(o[2*nt],   ph[kk], &vlf[nt][0]);
                mma16816(o[2*nt+1], ph[kk], &vlf[nt][2]);
            }
        }
    }

    // ---- finalize ----
    l0 += __shfl_xor_sync(0xffffffffu, l0, 1);
    l0 += __shfl_xor_sync(0xffffffffu, l0, 2);
    l1 += __shfl_xor_sync(0xffffffffu, l1, 1);
    l1 += __shfl_xor_sync(0xffffffffu, l1, 2);
    const float inv0 = 1.f / l0;
    const float inv1 = 1.f / l1;

    const int gr = l >> 2;
    const int row0 = qb*128 + w*16 + gr;
    const int t0 = b*S_LEN + row0;          // (bh span within batch: rows are s)
    const int t1 = t0 + 8;
    const int cbase = h*HD + (l & 3)*2;
#pragma unroll
    for (int nt = 0; nt < 16; nt++) {
        const int c = cbase + nt*8;
        {
            float v0 = o[nt][0]*inv0, v1 = o[nt][1]*inv0;
            uint32_t hp = pack_bf16x2(v0, v1);
            *(uint32_t*)(AOh + (size_t)t0*HDIM + c) = hp;
            float f0 = __uint_as_float(hp << 16);
            float f1 = __uint_as_float(hp & 0xFFFF0000u);
            *(uint32_t*)(AOl + (size_t)t0*HDIM + c) = pack_bf16x2(v0 - f0, v1 - f1);
        }
        {
            float v0 = o[nt][2]*inv1, v1 = o[nt][3]*inv1;
            uint32_t hp = pack_bf16x2(v0, v1);
            *(uint32_t*)(AOh + (size_t)t1*HDIM + c) = hp;
            float f0 = __uint_as_float(hp << 16);
            float f1 = __uint_as_float(hp & 0xFFFF0000u);
            *(uint32_t*)(AOl + (size_t)t1*HDIM + c) = pack_bf16x2(v0 - f0, v1 - f1);
        }
    }
}

// ---------------------------------------------------------------------------
extern "C" void kernel_launch(void* const* d_in, const int* in_sizes, int n_in,
                              void* d_out, int out_size)
{
    const float* hidden = (const float*)d_in[0];
    const float* cosp   = (const float*)d_in[1];
    const float* sinp   = (const float*)d_in[2];
    const float* Wq     = (const float*)d_in[3];
    const float* Wk     = (const float*)d_in[4];
    const float* bk     = (const float*)d_in[5];
    const float* Wv     = (const float*)d_in[6];
    const float* bv     = (const float*)d_in[7];
    const float* Wo     = (const float*)d_in[8];
    float* out = (float*)d_out;

    __nv_bfloat16 *Hh,*Hl,*Wqh,*Wql,*Wkh,*Wkl,*Wvh,*Wvl,*Woh,*Wol;
    __nv_bfloat16 *Qhp,*Qlp,*Khp,*Klp,*Vthp,*Vtlp,*AOh,*AOl;
    cudaGetSymbolAddress((void**)&Hh,  g_Hh);  cudaGetSymbolAddress((void**)&Hl,  g_Hl);
    cudaGetSymbolAddress((void**)&Wqh, g_Wqh); cudaGetSymbolAddress((void**)&Wql, g_Wql);
    cudaGetSymbolAddress((void**)&Wkh, g_Wkh); cudaGetSymbolAddress((void**)&Wkl, g_Wkl);
    cudaGetSymbolAddress((void**)&Wvh, g_Wvh); cudaGetSymbolAddress((void**)&Wvl, g_Wvl);
    cudaGetSymbolAddress((void**)&Woh, g_Woh); cudaGetSymbolAddress((void**)&Wol, g_Wol);
    cudaGetSymbolAddress((void**)&Qhp, g_Qh);  cudaGetSymbolAddress((void**)&Qlp, g_Ql);
    cudaGetSymbolAddress((void**)&Khp, g_Kh);  cudaGetSymbolAddress((void**)&Klp, g_Kl);
    cudaGetSymbolAddress((void**)&Vthp, g_Vth); cudaGetSymbolAddress((void**)&Vtlp, g_Vtl);
    cudaGetSymbolAddress((void**)&AOh, g_AOh); cudaGetSymbolAddress((void**)&AOl, g_AOl);

    static bool attr_set = false;
    if (!attr_set) {
        cudaFuncSetAttribute(gemm_tc<0>, cudaFuncAttributeMaxDynamicSharedMemorySize, GEMM_SMEM);
        cudaFuncSetAttribute(gemm_tc<1>, cudaFuncAttributeMaxDynamicSharedMemorySize, GEMM_SMEM);
        cudaFuncSetAttribute(gemm_tc<2>, cudaFuncAttributeMaxDynamicSharedMemorySize, GEMM_SMEM);
        cudaFuncSetAttribute(attn_tc, cudaFuncAttributeMaxDynamicSharedMemorySize, ATTN_SMEM);
        attr_set = true;
    }

    // convert fp32 inputs to bf16 hi/lo pairs
    {
        int nH = T_TOK*HDIM;
        int nW = HDIM*HDIM;
        int nK = KV_N*HDIM;
        cvt_k<<<nH/1024, 256>>>(hidden, Hh, Hl, nH);
        cvt_k<<<nW/1024, 256>>>(Wq, Wqh, Wql, nW);
        cvt_k<<<nK/1024, 256>>>(Wk, Wkh, Wkl, nK);
        cvt_k<<<nK/1024, 256>>>(Wv, Wvh, Wvl, nK);
        cvt_k<<<nW/1024, 256>>>(Wo, Woh, Wol, nW);
    }

    // Q = rope(hidden @ Wq^T) * (SCALE*log2e)  -> bf16 hi/lo [b][h][s][d]
    gemm_tc<1><<<dim3(HDIM/128, T_TOK/128), 256, GEMM_SMEM>>>(
        Hh, Hl, Wqh, Wql, nullptr, nullptr, Qhp, Qlp, cosp, sinp, NH, Q_SCALE);
    // K = rope(hidden @ Wk^T + bk)             -> bf16 hi/lo [b][kv][s][d]
    gemm_tc<1><<<dim3(KV_N/128, T_TOK/128), 256, GEMM_SMEM>>>(
        Hh, Hl, Wkh, Wkl, bk, nullptr, Khp, Klp, cosp, sinp, NKV, 1.0f);
    // V = hidden @ Wv^T + bv                   -> bf16 hi/lo [b][kv][d][s]
    gemm_tc<2><<<dim3(KV_N/128, T_TOK/128), 256, GEMM_SMEM>>>(
        Hh, Hl, Wvh, Wvl, bv, nullptr, Vthp, Vtlp, nullptr, nullptr, NKV, 1.0f);

    // attention -> AOh/AOl bf16 [t][h*HD+d]
    attn_tc<<<dim3(S_LEN/128, BATCH*NH), 256, ATTN_SMEM>>>(
        Qhp, Qlp, Khp, Klp, Vthp, Vtlp, AOh, AOl);

    // out = AO @ Wo^T (fp32)
    gemm_tc<0><<<dim3(HDIM/128, T_TOK/128), 256, GEMM_SMEM>>>(
        AOh, AOl, Woh, Wol, nullptr, out, nullptr, nullptr, nullptr, nullptr, 0, 1.0f);
}

// round 8
// speedup vs baseline: 4.7430x; 1.5224x over previous
#include <cuda_runtime.h>
#include <cuda_fp16.h>
#include <cstdint>
#include <math.h>

#define S_LEN 2048
#define BATCH 2
#define HDIM  4096
#define HD    128
#define NH    32
#define NKV   8
#define T_TOK (BATCH*S_LEN)   // 4096 tokens
#define KV_N  (NKV*HD)        // 1024

// SCALE * log2(e) folded into Q so softmax works in exp2 domain
#define Q_SCALE (0.08838834764831845f * 1.4426950408889634f)

// ---------------- scratch (__device__ globals; no allocation allowed) -------
__device__ __half g_Hh[(size_t)T_TOK*HDIM];
__device__ __half g_Hl[(size_t)T_TOK*HDIM];
__device__ __half g_Wqh[(size_t)HDIM*HDIM];
__device__ __half g_Wkh[(size_t)KV_N*HDIM];
__device__ __half g_Wvh[(size_t)KV_N*HDIM];
__device__ __half g_Woh[(size_t)HDIM*HDIM];

__device__ __half g_Qh[(size_t)BATCH*NH*S_LEN*HD];   // [b][h][s][d] (scaled)
__device__ __half g_Ql[(size_t)BATCH*NH*S_LEN*HD];
__device__ __half g_Kh[(size_t)BATCH*NKV*S_LEN*HD];  // [b][kv][s][d] (hi only)
__device__ __half g_Vth[(size_t)BATCH*NKV*HD*S_LEN]; // [b][kv][d][s] (hi only)
__device__ __half g_AOh[(size_t)T_TOK*HDIM];         // [t][h*HD+d]
__device__ __half g_AOl[(size_t)T_TOK*HDIM];

// ---------------- PTX helpers ----------------
__device__ __forceinline__ uint32_t smem_to_u32(const void* p) {
    uint32_t a;
    asm("{ .reg .u64 t; cvta.to.shared.u64 t, %1; cvt.u32.u64 %0, t; }"
        : "=r"(a) : "l"(p));
    return a;
}
__device__ __forceinline__ void ldsm_x4(uint32_t* r, uint32_t addr) {
    asm volatile("ldmatrix.sync.aligned.m8n8.x4.shared.b16 {%0,%1,%2,%3}, [%4];"
                 : "=r"(r[0]), "=r"(r[1]), "=r"(r[2]), "=r"(r[3]) : "r"(addr));
}
__device__ __forceinline__ void mma16816(float* d, const uint32_t* a, const uint32_t* b) {
    asm volatile(
        "mma.sync.aligned.m16n8k16.row.col.f32.f16.f16.f32 "
        "{%0,%1,%2,%3}, {%4,%5,%6,%7}, {%8,%9}, {%0,%1,%2,%3};"
        : "+f"(d[0]), "+f"(d[1]), "+f"(d[2]), "+f"(d[3])
        : "r"(a[0]), "r"(a[1]), "r"(a[2]), "r"(a[3]), "r"(b[0]), "r"(b[1]));
}
#define CP_ASYNC16(dst, src) \
    asm volatile("cp.async.cg.shared.global [%0], [%1], 16;" \
                 :: "r"(dst), "l"(src))
#define CP_COMMIT() asm volatile("cp.async.commit_group;" ::: "memory")
#define CP_WAIT(n)  asm volatile("cp.async.wait_group %0;" :: "n"(n) : "memory")

__device__ __forceinline__ float ex2f(float x) {
    float y;
    asm("ex2.approx.ftz.f32 %0, %1;" : "=f"(y) : "f"(x));
    return y;
}
__device__ __forceinline__ uint32_t h2_u32(__half2 h) {
    return *reinterpret_cast<uint32_t*>(&h);
}

// ---------------- fp32 -> fp16 conversions -----------------------
__global__ void __launch_bounds__(256)
cvt2_k(const float* __restrict__ x, __half* __restrict__ h,
       __half* __restrict__ l, int n)
{
    int i = (blockIdx.x * 256 + threadIdx.x) * 4;
    if (i >= n) return;
    float4 v = *(const float4*)(x + i);
    __half h0 = __float2half(v.x);
    __half h1 = __float2half(v.y);
    __half h2 = __float2half(v.z);
    __half h3 = __float2half(v.w);
    *(__half2*)(h + i)     = __halves2half2(h0, h1);
    *(__half2*)(h + i + 2) = __halves2half2(h2, h3);
    *(__half2*)(l + i)     = __floats2half2_rn(v.x - __half2float(h0),
                                               v.y - __half2float(h1));
    *(__half2*)(l + i + 2) = __floats2half2_rn(v.z - __half2float(h2),
                                               v.w - __half2float(h3));
}
__global__ void __launch_bounds__(256)
cvt1_k(const float* __restrict__ x, __half* __restrict__ h, int n)
{
    int i = (blockIdx.x * 256 + threadIdx.x) * 4;
    if (i >= n) return;
    float4 v = *(const float4*)(x + i);
    *(__half2*)(h + i)     = __floats2half2_rn(v.x, v.y);
    *(__half2*)(h + i + 2) = __floats2half2_rn(v.z, v.w);
}

// ---------------------------------------------------------------------------
// HMMA fp16 2-pass GEMM: C[M,N] = (Ah+Al)[M,K] @ Bh[N,K]^T (+bias), K=4096.
// Block 128x128x32, 8 warps (4Mx2N), warp tile 32x64. 3-stage cp.async,
// one __syncthreads per K-iter.
// MODE 0: fp32 row-major store (O projection -> d_out)
// MODE 1: bias? + RoPE + scale, store fp16 hi (+lo if Cl) [b][head][s][d]
// MODE 2: bias, store fp16 hi TRANSPOSED [b][head][d][s]
// ---------------------------------------------------------------------------
#define BK 32
#define ROWB 80
#define TILE_BYTES (128*ROWB)          // 10240
#define STAGEB (3*TILE_BYTES)          // Ah, Al, Bh = 30720
#define GEMM_SMEM (3*STAGEB)           // 92160

template<int MODE>
__global__ void __launch_bounds__(256, 2)
gemm_tc(const __half* __restrict__ Agh, const __half* __restrict__ Agl,
        const __half* __restrict__ Bgh,
        const float* __restrict__ bias, float* __restrict__ Cf,
        __half* __restrict__ Ch, __half* __restrict__ Cl,
        const float* __restrict__ cosp, const float* __restrict__ sinp,
        int n_heads, float scale)
{
    extern __shared__ char smem[];
    const uint32_t sbase = smem_to_u32(smem);
    const int tid = threadIdx.x;
    const int w   = tid >> 5;
    const int l   = tid & 31;
    const int wm  = w >> 1;
    const int wn  = w & 1;
    const int bm = blockIdx.y, bn = blockIdx.x;
    const int K = HDIM;
    const int NIT = K / BK;   // 128

    const int r0 = tid >> 2, c0 = tid & 3;
    const int r1 = (tid + 256) >> 2;
    const size_t aro = (size_t)(bm*128 + r0)*K + c0*8;
    const size_t ar1 = (size_t)(bm*128 + r1)*K + c0*8;
    const size_t bro = (size_t)(bn*128 + r0)*K + c0*8;
    const size_t br1 = (size_t)(bn*128 + r1)*K + c0*8;
    const uint32_t so0 = r0*ROWB + c0*16;
    const uint32_t so1 = r1*ROWB + c0*16;

    float acc[2][8][4];
#pragma unroll
    for (int mt = 0; mt < 2; mt++)
#pragma unroll
        for (int nt = 0; nt < 8; nt++)
#pragma unroll
            for (int e = 0; e < 4; e++) acc[mt][nt][e] = 0.f;

    // prologue: stages 0, 1
#pragma unroll
    for (int st = 0; st < 2; st++) {
        const int k0 = st * BK;
        uint32_t dst = sbase + st*STAGEB;
        CP_ASYNC16(dst + so0, Agh + aro + k0);
        CP_ASYNC16(dst + so1, Agh + ar1 + k0);
        CP_ASYNC16(dst + TILE_BYTES + so0, Agl + aro + k0);
        CP_ASYNC16(dst + TILE_BYTES + so1, Agl + ar1 + k0);
        CP_ASYNC16(dst + 2*TILE_BYTES + so0, Bgh + bro + k0);
        CP_ASYNC16(dst + 2*TILE_BYTES + so1, Bgh + br1 + k0);
        CP_COMMIT();
    }

    int stc = 0;                   // stage of tile `it`
    for (int it = 0; it < NIT; it++) {
        CP_WAIT(1);
        __syncthreads();
        if (it + 2 < NIT) {
            const int k0 = (it + 2) * BK;
            const int stn = (stc + 2 >= 3) ? stc - 1 : stc + 2;
            uint32_t dst = sbase + stn*STAGEB;
            CP_ASYNC16(dst + so0, Agh + aro + k0);
            CP_ASYNC16(dst + so1, Agh + ar1 + k0);
            CP_ASYNC16(dst + TILE_BYTES + so0, Agl + aro + k0);
            CP_ASYNC16(dst + TILE_BYTES + so1, Agl + ar1 + k0);
            CP_ASYNC16(dst + 2*TILE_BYTES + so0, Bgh + bro + k0);
            CP_ASYNC16(dst + 2*TILE_BYTES + so1, Bgh + br1 + k0);
        }
        CP_COMMIT();

        const uint32_t sAh = sbase + stc*STAGEB;
        const uint32_t sAl = sAh + TILE_BYTES;
        const uint32_t sBh = sAh + 2*TILE_BYTES;

#pragma unroll
        for (int ks = 0; ks < 2; ks++) {
            const uint32_t koff = ks*32 + ((l >> 4) * 16);
            const uint32_t aoff = (uint32_t)(wm*32 + (l & 15)) * ROWB + koff;
            const uint32_t boff = (uint32_t)(wn*64 + ((l >> 4) << 3) + (l & 7)) * ROWB
                                  + ks*32 + (((l >> 3) & 1) * 16);
            uint32_t ah[2][4], al[2][4], bh[4][4];
#pragma unroll
            for (int mt = 0; mt < 2; mt++) ldsm_x4(ah[mt], sAh + aoff + mt*16*ROWB);
#pragma unroll
            for (int bt = 0; bt < 4; bt++) ldsm_x4(bh[bt], sBh + boff + bt*16*ROWB);
#pragma unroll
            for (int mt = 0; mt < 2; mt++)
#pragma unroll
                for (int bt = 0; bt < 4; bt++) {
                    mma16816(acc[mt][2*bt],   ah[mt], &bh[bt][0]);
                    mma16816(acc[mt][2*bt+1], ah[mt], &bh[bt][2]);
                }
#pragma unroll
            for (int mt = 0; mt < 2; mt++) ldsm_x4(al[mt], sAl + aoff + mt*16*ROWB);
#pragma unroll
            for (int mt = 0; mt < 2; mt++)
#pragma unroll
                for (int bt = 0; bt < 4; bt++) {
                    mma16816(acc[mt][2*bt],   al[mt], &bh[bt][0]);
                    mma16816(acc[mt][2*bt+1], al[mt], &bh[bt][2]);
                }
        }
        stc = (stc + 1 == 3) ? 0 : stc + 1;
    }

    // ---------------- epilogue ----------------
#pragma unroll
    for (int mt = 0; mt < 2; mt++) {
        const int rbase = bm*128 + wm*32 + mt*16 + (l >> 2);
#pragma unroll
        for (int half = 0; half < 2; half++) {
            const int t  = rbase + half*8;
            const int bb = t >> 11;
            const int s  = t & (S_LEN - 1);
#pragma unroll
            for (int nt = 0; nt < 8; nt++) {
                const int n0 = bn*128 + wn*64 + nt*8 + (l & 3)*2;
                float x1 = acc[mt][nt][half*2 + 0];
                float x2 = acc[mt][nt][half*2 + 1];
                if (MODE == 0) {
                    float* cp = Cf + (size_t)t*HDIM + n0;
                    cp[0] = x1; cp[1] = x2;
                } else {
                    const int head = n0 >> 7;
                    const int cl   = n0 & 127;
                    if (MODE == 2) {
                        x1 += bias[n0]; x2 += bias[n0 + 1];
                        const size_t base = ((size_t)(bb*n_heads + head)*HD) * S_LEN;
                        Ch[base + (size_t)cl*S_LEN + s]     = __float2half(x1);
                        Ch[base + (size_t)(cl+1)*S_LEN + s] = __float2half(x2);
                    } else {
                        if (bias) { x1 += bias[n0]; x2 += bias[n0 + 1]; }
                        const int d = cl >> 1;
                        const float cs = cosp[s*64 + d];
                        const float sn = sinp[s*64 + d];
                        float y1 = (x1*cs - x2*sn) * scale;
                        float y2 = (x1*sn + x2*cs) * scale;
                        const size_t base = ((size_t)(bb*n_heads + head)*S_LEN + s) * HD;
                        __half h1 = __float2half(y1);
                        __half h2 = __float2half(y2);
                        Ch[base + d]      = h1;
                        Ch[base + 64 + d] = h2;
                        if (Cl) {
                            Cl[base + d]      = __float2half(y1 - __half2float(h1));
                            Cl[base + 64 + d] = __float2half(y2 - __half2float(h2));
                        }
                    }
                }
            }
        }
    }
}

// ---------------------------------------------------------------------------
// HMMA fp16 flash attention: BM=128 (8 warps x 16 rows), BN=64 keys, HD=128.
// Q (scaled, hi/lo) register-resident; K hi / V^T hi, cp.async 3-stage.
// Scores = 2 passes ((qh+ql)*kh); P split in regs; PV = 2 passes ((ph+pl)*vh).
// Online softmax exp2 domain. Output: AOh/AOl fp16 [t][h*HD+d].
// ---------------------------------------------------------------------------
#define KROW 272                   // K smem row stride (128 fp16 = 256B + 16)
#define VROW 144                   // V^T smem row stride (64 fp16 = 128B + 16)
#define OFF_V  17408               // K tile bytes (64*KROW)
#define ABUF   35840               // K + V per stage
#define ATTN_SMEM (3*ABUF)         // 107520

__global__ void __launch_bounds__(256, 1)
attn_tc(const __half* __restrict__ Qh, const __half* __restrict__ Ql,
        const __half* __restrict__ Kh, const __half* __restrict__ Vth,
        __half* __restrict__ AOh, __half* __restrict__ AOl)
{
    extern __shared__ char smem[];
    const uint32_t sbase = smem_to_u32(smem);
    const int tid = threadIdx.x;
    const int w   = tid >> 5;
    const int l   = tid & 31;
    const int qb  = blockIdx.x;
    const int bh  = blockIdx.y;
    const int b   = bh / NH;
    const int h   = bh % NH;
    const int kv  = h >> 2;

    const __half* Qhb = Qh + ((size_t)bh*S_LEN + qb*128)*HD;
    const __half* Qlb = Ql + ((size_t)bh*S_LEN + qb*128)*HD;
    const __half* Khb = Kh + ((size_t)(b*NKV + kv)*S_LEN)*HD;
    const __half* Vhb = Vth + ((size_t)(b*NKV + kv)*HD)*S_LEN;

    // ---- stage Q into smem (spans stage buffers 0-1), then load frags ----
#pragma unroll
    for (int i = 0; i < 8; i++) {
        int id = tid + i*256;
        int r = id >> 4, c = id & 15;
        *(uint4*)(smem + r*KROW + c*16) =
            *(const uint4*)(Qhb + (size_t)r*HD + c*8);
        *(uint4*)(smem + 34816 + r*KROW + c*16) =
            *(const uint4*)(Qlb + (size_t)r*HD + c*8);
    }
    __syncthreads();

    uint32_t qh[8][4], ql[8][4];
    {
        const uint32_t arow = (uint32_t)(w*16 + (l & 15)) * KROW;
#pragma unroll
        for (int kc = 0; kc < 8; kc++) {
            const uint32_t koff = kc*32 + ((l >> 4) * 16);
            ldsm_x4(qh[kc], sbase + arow + koff);
            ldsm_x4(ql[kc], sbase + 34816 + arow + koff);
        }
    }
    __syncthreads();

    float o[16][4];
#pragma unroll
    for (int nt = 0; nt < 16; nt++)
#pragma unroll
        for (int e = 0; e < 4; e++) o[nt][e] = 0.f;
    float m0 = -1e30f, m1 = -1e30f, l0 = 0.f, l1 = 0.f;

    // per-thread cp.async slots
    const int rk = tid >> 2, ck = tid & 3;      // K: 64 rows x (4 of 16 chunks)?
    // K tile: 64 rows x 16 chunks (1024 slots) -> use id loop
    // prologue: stages 0, 1
#pragma unroll
    for (int st = 0; st < 2; st++) {
        uint32_t dst = sbase + st*ABUF;
        const size_t ko = (size_t)st * 64 * HD;
        const size_t vo = (size_t)st * 64;
#pragma unroll
        for (int i = 0; i < 4; i++) {
            int id = tid + i*256;
            int r = id >> 4, c = id & 15;
            CP_ASYNC16(dst + r*KROW + c*16, Khb + ko + (size_t)r*HD + c*8);
            int rv = id >> 3, cv = id & 7;
            CP_ASYNC16(dst + OFF_V + rv*VROW + cv*16, Vhb + vo + (size_t)rv*S_LEN + cv*8);
        }
        CP_COMMIT();
    }

    const int NKT = S_LEN / 64;   // 32
    int stc = 0;
    for (int kt = 0; kt < NKT; kt++) {
        CP_WAIT(1);
        __syncthreads();
        if (kt + 2 < NKT) {
            const int stn = (stc + 2 >= 3) ? stc - 1 : stc + 2;
            uint32_t dst = sbase + stn*ABUF;
            const size_t ko = (size_t)(kt + 2) * 64 * HD;
            const size_t vo = (size_t)(kt + 2) * 64;
#pragma unroll
            for (int i = 0; i < 4; i++) {
                int id = tid + i*256;
                int r = id >> 4, c = id & 15;
                CP_ASYNC16(dst + r*KROW + c*16, Khb + ko + (size_t)r*HD + c*8);
                int rv = id >> 3, cv = id & 7;
                CP_ASYNC16(dst + OFF_V + rv*VROW + cv*16, Vhb + vo + (size_t)rv*S_LEN + cv*8);
            }
        }
        CP_COMMIT();

        const uint32_t sKh = sbase + stc*ABUF;
        const uint32_t sVh = sKh + OFF_V;

        // ---- QK^T: 16x64 scores, 2 passes ----
        float sc[8][4];
#pragma unroll
        for (int nt = 0; nt < 8; nt++)
#pragma unroll
            for (int e = 0; e < 4; e++) sc[nt][e] = 0.f;

        const uint32_t krow = (uint32_t)(((l >> 4) << 3) + (l & 7)) * KROW;
#pragma unroll
        for (int kc = 0; kc < 8; kc++) {
            const uint32_t kcol = kc*32 + (((l >> 3) & 1) * 16);
            uint32_t khf[4][4];
#pragma unroll
            for (int bt = 0; bt < 4; bt++) ldsm_x4(khf[bt], sKh + krow + bt*16*KROW + kcol);
#pragma unroll
            for (int bt = 0; bt < 4; bt++) {
                mma16816(sc[2*bt],   qh[kc], &khf[bt][0]);
                mma16816(sc[2*bt+1], qh[kc], &khf[bt][2]);
            }
#pragma unroll
            for (int bt = 0; bt < 4; bt++) {
                mma16816(sc[2*bt],   ql[kc], &khf[bt][0]);
                mma16816(sc[2*bt+1], ql[kc], &khf[bt][2]);
            }
        }

        // ---- online softmax (exp2 domain) ----
        float mt0 = -1e30f, mt1 = -1e30f;
#pragma unroll
        for (int nt = 0; nt < 8; nt++) {
            mt0 = fmaxf(mt0, fmaxf(sc[nt][0], sc[nt][1]));
            mt1 = fmaxf(mt1, fmaxf(sc[nt][2], sc[nt][3]));
        }
        mt0 = fmaxf(mt0, __shfl_xor_sync(0xffffffffu, mt0, 1));
        mt0 = fmaxf(mt0, __shfl_xor_sync(0xffffffffu, mt0, 2));
        mt1 = fmaxf(mt1, __shfl_xor_sync(0xffffffffu, mt1, 1));
        mt1 = fmaxf(mt1, __shfl_xor_sync(0xffffffffu, mt1, 2));
        const float mn0 = fmaxf(m0, mt0);
        const float mn1 = fmaxf(m1, mt1);
        const float al0 = ex2f(m0 - mn0);
        const float al1 = ex2f(m1 - mn1);
        m0 = mn0; m1 = mn1;

        float lp0 = 0.f, lp1 = 0.f;
#pragma unroll
        for (int nt = 0; nt < 8; nt++) {
            sc[nt][0] = ex2f(sc[nt][0] - mn0); lp0 += sc[nt][0];
            sc[nt][1] = ex2f(sc[nt][1] - mn0); lp0 += sc[nt][1];
            sc[nt][2] = ex2f(sc[nt][2] - mn1); lp1 += sc[nt][2];
            sc[nt][3] = ex2f(sc[nt][3] - mn1); lp1 += sc[nt][3];
        }
        l0 = l0*al0 + lp0;
        l1 = l1*al1 + lp1;
#pragma unroll
        for (int nt = 0; nt < 16; nt++) {
            o[nt][0] *= al0; o[nt][1] *= al0;
            o[nt][2] *= al1; o[nt][3] *= al1;
        }

        // ---- P split hi/lo fragments (registers, fp16) ----
        uint32_t ph[4][4], pl[4][4];
#pragma unroll
        for (int kk = 0; kk < 4; kk++) {
#pragma unroll
            for (int e = 0; e < 4; e++) {
                const int nt = 2*kk + (e >> 1);
                const int i0 = (e & 1) * 2;
                float p0 = sc[nt][i0], p1 = sc[nt][i0+1];
                __half2 hp = __floats2half2_rn(p0, p1);
                ph[kk][e] = h2_u32(hp);
                __half2 lp = __floats2half2_rn(p0 - __low2float(hp),
                                               p1 - __high2float(hp));
                pl[kk][e] = h2_u32(lp);
            }
        }

        // ---- O += P @ V  (2 passes) ----
        const uint32_t vrow = (uint32_t)(((l >> 4) << 3) + (l & 7)) * VROW;
#pragma unroll
        for (int kk = 0; kk < 4; kk++) {
            const uint32_t vcol = kk*32 + (((l >> 3) & 1) * 16);
            uint32_t vhf[8][4];
#pragma unroll
            for (int nt = 0; nt < 8; nt++) ldsm_x4(vhf[nt], sVh + vrow + nt*16*VROW + vcol);
#pragma unroll
            for (int nt = 0; nt < 8; nt++) {
                mma16816(o[2*nt],   ph[kk], &vhf[nt][0]);
                mma16816(o[2*nt+1], ph[kk], &vhf[nt][2]);
            }
#pragma unroll
            for (int nt = 0; nt < 8; nt++) {
                mma16816(o[2*nt],   pl[kk], &vhf[nt][0]);
                mma16816(o[2*nt+1], pl[kk], &vhf[nt][2]);
            }
        }
        stc = (stc + 1 == 3) ? 0 : stc + 1;
    }

    // ---- finalize ----
    l0 += __shfl_xor_sync(0xffffffffu, l0, 1);
    l0 += __shfl_xor_sync(0xffffffffu, l0, 2);
    l1 += __shfl_xor_sync(0xffffffffu, l1, 1);
    l1 += __shfl_xor_sync(0xffffffffu, l1, 2);
    const float inv0 = 1.f / l0;
    const float inv1 = 1.f / l1;

    const int gr = l >> 2;
    const int row0 = qb*128 + w*16 + gr;
    const int t0 = b*S_LEN + row0;
    const int t1 = t0 + 8;
    const int cbase = h*HD + (l & 3)*2;
#pragma unroll
    for (int nt = 0; nt < 16; nt++) {
        const int c = cbase + nt*8;
        {
            float v0 = o[nt][0]*inv0, v1 = o[nt][1]*inv0;
            __half2 hv = __floats2half2_rn(v0, v1);
            *(uint32_t*)(AOh + (size_t)t0*HDIM + c) = h2_u32(hv);
            __half2 lv = __floats2half2_rn(v0 - __low2float(hv),
                                           v1 - __high2float(hv));
            *(uint32_t*)(AOl + (size_t)t0*HDIM + c) = h2_u32(lv);
        }
        {
            float v0 = o[nt][2]*inv1, v1 = o[nt][3]*inv1;
            __half2 hv = __floats2half2_rn(v0, v1);
            *(uint32_t*)(AOh + (size_t)t1*HDIM + c) = h2_u32(hv);
            __half2 lv = __floats2half2_rn(v0 - __low2float(hv),
                                           v1 - __high2float(hv));
            *(uint32_t*)(AOl + (size_t)t1*HDIM + c) = h2_u32(lv);
        }
    }
}

// ---------------------------------------------------------------------------
extern "C" void kernel_launch(void* const* d_in, const int* in_sizes, int n_in,
                              void* d_out, int out_size)
{
    const float* hidden = (const float*)d_in[0];
    const float* cosp   = (const float*)d_in[1];
    const float* sinp   = (const float*)d_in[2];
    const float* Wq     = (const float*)d_in[3];
    const float* Wk     = (const float*)d_in[4];
    const float* bk     = (const float*)d_in[5];
    const float* Wv     = (const float*)d_in[6];
    const float* bv     = (const float*)d_in[7];
    const float* Wo     = (const float*)d_in[8];
    float* out = (float*)d_out;

    __half *Hh,*Hl,*Wqh,*Wkh,*Wvh,*Woh;
    __half *Qhp,*Qlp,*Khp,*Vthp,*AOh,*AOl;
    cudaGetSymbolAddress((void**)&Hh,  g_Hh);  cudaGetSymbolAddress((void**)&Hl,  g_Hl);
    cudaGetSymbolAddress((void**)&Wqh, g_Wqh);
    cudaGetSymbolAddress((void**)&Wkh, g_Wkh);
    cudaGetSymbolAddress((void**)&Wvh, g_Wvh);
    cudaGetSymbolAddress((void**)&Woh, g_Woh);
    cudaGetSymbolAddress((void**)&Qhp, g_Qh);  cudaGetSymbolAddress((void**)&Qlp, g_Ql);
    cudaGetSymbolAddress((void**)&Khp, g_Kh);
    cudaGetSymbolAddress((void**)&Vthp, g_Vth);
    cudaGetSymbolAddress((void**)&AOh, g_AOh); cudaGetSymbolAddress((void**)&AOl, g_AOl);

    static bool attr_set = false;
    if (!attr_set) {
        cudaFuncSetAttribute(gemm_tc<0>, cudaFuncAttributeMaxDynamicSharedMemorySize, GEMM_SMEM);
        cudaFuncSetAttribute(gemm_tc<1>, cudaFuncAttributeMaxDynamicSharedMemorySize, GEMM_SMEM);
        cudaFuncSetAttribute(gemm_tc<2>, cudaFuncAttributeMaxDynamicSharedMemorySize, GEMM_SMEM);
        cudaFuncSetAttribute(attn_tc, cudaFuncAttributeMaxDynamicSharedMemorySize, ATTN_SMEM);
        attr_set = true;
    }

    // convert fp32 inputs: hidden -> hi/lo; weights -> hi only
    {
        int nH = T_TOK*HDIM;
        int nW = HDIM*HDIM;
        int nK = KV_N*HDIM;
        cvt2_k<<<nH/1024, 256>>>(hidden, Hh, Hl, nH);
        cvt1_k<<<nW/1024, 256>>>(Wq, Wqh, nW);
        cvt1_k<<<nK/1024, 256>>>(Wk, Wkh, nK);
        cvt1_k<<<nK/1024, 256>>>(Wv, Wvh, nK);
        cvt1_k<<<nW/1024, 256>>>(Wo, Woh, nW);
    }

    // Q = rope(hidden @ Wq^T) * (SCALE*log2e)  -> fp16 hi/lo [b][h][s][d]
    gemm_tc<1><<<dim3(HDIM/128, T_TOK/128), 256, GEMM_SMEM>>>(
        Hh, Hl, Wqh, nullptr, nullptr, Qhp, Qlp, cosp, sinp, NH, Q_SCALE);
    // K = rope(hidden @ Wk^T + bk)             -> fp16 hi [b][kv][s][d]
    gemm_tc<1><<<dim3(KV_N/128, T_TOK/128), 256, GEMM_SMEM>>>(
        Hh, Hl, Wkh, bk, nullptr, Khp, nullptr, cosp, sinp, NKV, 1.0f);
    // V = hidden @ Wv^T + bv                   -> fp16 hi [b][kv][d][s]
    gemm_tc<2><<<dim3(KV_N/128, T_TOK/128), 256, GEMM_SMEM>>>(
        Hh, Hl, Wvh, bv, nullptr, Vthp, nullptr, nullptr, nullptr, NKV, 1.0f);

    // attention -> AOh/AOl fp16 [t][h*HD+d]
    attn_tc<<<dim3(S_LEN/128, BATCH*NH), 256, ATTN_SMEM>>>(
        Qhp, Qlp, Khp, Vthp, AOh, AOl);

    // out = AO @ Wo^T (fp32)
    gemm_tc<0><<<dim3(HDIM/128, T_TOK/128), 256, GEMM_SMEM>>>(
        AOh, AOl, Woh, nullptr, out, nullptr, nullptr, nullptr, nullptr, 0, 1.0f);
}

// round 13
// speedup vs baseline: 5.0000x; 1.0542x over previous
#include <cuda_runtime.h>
#include <cuda_fp16.h>
#include <cstdint>
#include <math.h>

#define S_LEN 2048
#define BATCH 2
#define HDIM  4096
#define HD    128
#define NH    32
#define NKV   8
#define T_TOK (BATCH*S_LEN)   // 4096 tokens
#define KV_N  (NKV*HD)        // 1024

// SCALE * log2(e) folded into Q so softmax works in exp2 domain
#define Q_SCALE (0.08838834764831845f * 1.4426950408889634f)

// ---------------- scratch (__device__ globals; no allocation allowed) -------
__device__ __half g_Hh[(size_t)T_TOK*HDIM];
__device__ __half g_Hl[(size_t)T_TOK*HDIM];
__device__ __half g_Wqh[(size_t)HDIM*HDIM];
__device__ __half g_Wkh[(size_t)KV_N*HDIM];
__device__ __half g_Wvh[(size_t)KV_N*HDIM];
__device__ __half g_Woh[(size_t)HDIM*HDIM];

__device__ __half g_Qh[(size_t)BATCH*NH*S_LEN*HD];   // [b][h][s][d] (scaled)
__device__ __half g_Ql[(size_t)BATCH*NH*S_LEN*HD];
__device__ __half g_Kh[(size_t)BATCH*NKV*S_LEN*HD];  // [b][kv][s][d] (hi only)
__device__ __half g_Vth[(size_t)BATCH*NKV*HD*S_LEN]; // [b][kv][d][s] (hi only)
__device__ __half g_AOh[(size_t)T_TOK*HDIM];         // [t][h*HD+d]
__device__ __half g_AOl[(size_t)T_TOK*HDIM];

// ---------------- PTX helpers ----------------
__device__ __forceinline__ uint32_t smem_to_u32(const void* p) {
    uint32_t a;
    asm("{ .reg .u64 t; cvta.to.shared.u64 t, %1; cvt.u32.u64 %0, t; }"
        : "=r"(a) : "l"(p));
    return a;
}
__device__ __forceinline__ void ldsm_x4(uint32_t* r, uint32_t addr) {
    asm volatile("ldmatrix.sync.aligned.m8n8.x4.shared.b16 {%0,%1,%2,%3}, [%4];"
                 : "=r"(r[0]), "=r"(r[1]), "=r"(r[2]), "=r"(r[3]) : "r"(addr));
}
__device__ __forceinline__ void mma16816(float* d, const uint32_t* a, const uint32_t* b) {
    asm volatile(
        "mma.sync.aligned.m16n8k16.row.col.f32.f16.f16.f32 "
        "{%0,%1,%2,%3}, {%4,%5,%6,%7}, {%8,%9}, {%0,%1,%2,%3};"
        : "+f"(d[0]), "+f"(d[1]), "+f"(d[2]), "+f"(d[3])
        : "r"(a[0]), "r"(a[1]), "r"(a[2]), "r"(a[3]), "r"(b[0]), "r"(b[1]));
}
#define CP_ASYNC16(dst, src) \
    asm volatile("cp.async.cg.shared.global [%0], [%1], 16;" \
                 :: "r"(dst), "l"(src))
#define CP_COMMIT() asm volatile("cp.async.commit_group;" ::: "memory")
#define CP_WAIT(n)  asm volatile("cp.async.wait_group %0;" :: "n"(n) : "memory")

__device__ __forceinline__ float ex2f(float x) {
    float y;
    asm("ex2.approx.ftz.f32 %0, %1;" : "=f"(y) : "f"(x));
    return y;
}
__device__ __forceinline__ uint32_t h2_u32(__half2 h) {
    return *reinterpret_cast<uint32_t*>(&h);
}

// ---------------- fp32 -> fp16 conversions -----------------------
__global__ void __launch_bounds__(256)
cvt2_k(const float* __restrict__ x, __half* __restrict__ h,
       __half* __restrict__ l, int n)
{
    int i = (blockIdx.x * 256 + threadIdx.x) * 4;
    if (i >= n) return;
    float4 v = *(const float4*)(x + i);
    __half h0 = __float2half(v.x);
    __half h1 = __float2half(v.y);
    __half h2 = __float2half(v.z);
    __half h3 = __float2half(v.w);
    *(__half2*)(h + i)     = __halves2half2(h0, h1);
    *(__half2*)(h + i + 2) = __halves2half2(h2, h3);
    *(__half2*)(l + i)     = __floats2half2_rn(v.x - __half2float(h0),
                                               v.y - __half2float(h1));
    *(__half2*)(l + i + 2) = __floats2half2_rn(v.z - __half2float(h2),
                                               v.w - __half2float(h3));
}
__global__ void __launch_bounds__(256)
cvt1_k(const float* __restrict__ x, __half* __restrict__ h, int n)
{
    int i = (blockIdx.x * 256 + threadIdx.x) * 4;
    if (i >= n) return;
    float4 v = *(const float4*)(x + i);
    *(__half2*)(h + i)     = __floats2half2_rn(v.x, v.y);
    *(__half2*)(h + i + 2) = __floats2half2_rn(v.z, v.w);
}

// ---------------------------------------------------------------------------
// HMMA fp16 2-pass GEMM: C[M,N] = (Ah+Al)[M,K] @ Bh[N,K]^T (+bias), K=4096.
// Block 128x128x32, 8 warps (4Mx2N), warp tile 32x64. 3-stage cp.async,
// one __syncthreads per K-iter.
// MODE 0: fp32 row-major store (O projection -> d_out)
// MODE 1: bias? + RoPE + scale, store fp16 hi (+lo if Cl) [b][head][s][d]
// MODE 2: bias, store fp16 hi TRANSPOSED [b][head][d][s]
// ---------------------------------------------------------------------------
#define BK 32
#define ROWB 80
#define TILE_BYTES (128*ROWB)          // 10240
#define STAGEB (3*TILE_BYTES)          // Ah, Al, Bh = 30720
#define GEMM_SMEM (3*STAGEB)           // 92160

template<int MODE>
__global__ void __launch_bounds__(256, 2)
gemm_tc(const __half* __restrict__ Agh, const __half* __restrict__ Agl,
        const __half* __restrict__ Bgh,
        const float* __restrict__ bias, float* __restrict__ Cf,
        __half* __restrict__ Ch, __half* __restrict__ Cl,
        const float* __restrict__ cosp, const float* __restrict__ sinp,
        int n_heads, float scale)
{
    extern __shared__ char smem[];
    const uint32_t sbase = smem_to_u32(smem);
    const int tid = threadIdx.x;
    const int w   = tid >> 5;
    const int l   = tid & 31;
    const int wm  = w >> 1;
    const int wn  = w & 1;
    const int bm = blockIdx.y, bn = blockIdx.x;
    const int K = HDIM;
    const int NIT = K / BK;   // 128

    const int r0 = tid >> 2, c0 = tid & 3;
    const int r1 = (tid + 256) >> 2;
    const size_t aro = (size_t)(bm*128 + r0)*K + c0*8;
    const size_t ar1 = (size_t)(bm*128 + r1)*K + c0*8;
    const size_t bro = (size_t)(bn*128 + r0)*K + c0*8;
    const size_t br1 = (size_t)(bn*128 + r1)*K + c0*8;
    const uint32_t so0 = r0*ROWB + c0*16;
    const uint32_t so1 = r1*ROWB + c0*16;

    float acc[2][8][4];
#pragma unroll
    for (int mt = 0; mt < 2; mt++)
#pragma unroll
        for (int nt = 0; nt < 8; nt++)
#pragma unroll
            for (int e = 0; e < 4; e++) acc[mt][nt][e] = 0.f;

    // prologue: stages 0, 1
#pragma unroll
    for (int st = 0; st < 2; st++) {
        const int k0 = st * BK;
        uint32_t dst = sbase + st*STAGEB;
        CP_ASYNC16(dst + so0, Agh + aro + k0);
        CP_ASYNC16(dst + so1, Agh + ar1 + k0);
        CP_ASYNC16(dst + TILE_BYTES + so0, Agl + aro + k0);
        CP_ASYNC16(dst + TILE_BYTES + so1, Agl + ar1 + k0);
        CP_ASYNC16(dst + 2*TILE_BYTES + so0, Bgh + bro + k0);
        CP_ASYNC16(dst + 2*TILE_BYTES + so1, Bgh + br1 + k0);
        CP_COMMIT();
    }

    int stc = 0;                   // stage of tile `it`
    for (int it = 0; it < NIT; it++) {
        CP_WAIT(1);
        __syncthreads();
        if (it + 2 < NIT) {
            const int k0 = (it + 2) * BK;
            const int stn = (stc + 2 >= 3) ? stc - 1 : stc + 2;
            uint32_t dst = sbase + stn*STAGEB;
            CP_ASYNC16(dst + so0, Agh + aro + k0);
            CP_ASYNC16(dst + so1, Agh + ar1 + k0);
            CP_ASYNC16(dst + TILE_BYTES + so0, Agl + aro + k0);
            CP_ASYNC16(dst + TILE_BYTES + so1, Agl + ar1 + k0);
            CP_ASYNC16(dst + 2*TILE_BYTES + so0, Bgh + bro + k0);
            CP_ASYNC16(dst + 2*TILE_BYTES + so1, Bgh + br1 + k0);
        }
        CP_COMMIT();

        const uint32_t sAh = sbase + stc*STAGEB;
        const uint32_t sAl = sAh + TILE_BYTES;
        const uint32_t sBh = sAh + 2*TILE_BYTES;

#pragma unroll
        for (int ks = 0; ks < 2; ks++) {
            const uint32_t koff = ks*32 + ((l >> 4) * 16);
            const uint32_t aoff = (uint32_t)(wm*32 + (l & 15)) * ROWB + koff;
            const uint32_t boff = (uint32_t)(wn*64 + ((l >> 4) << 3) + (l & 7)) * ROWB
                                  + ks*32 + (((l >> 3) & 1) * 16);
            uint32_t ah[2][4], al[2][4], bh[4][4];
#pragma unroll
            for (int mt = 0; mt < 2; mt++) ldsm_x4(ah[mt], sAh + aoff + mt*16*ROWB);
#pragma unroll
            for (int bt = 0; bt < 4; bt++) ldsm_x4(bh[bt], sBh + boff + bt*16*ROWB);
#pragma unroll
            for (int mt = 0; mt < 2; mt++)
#pragma unroll
                for (int bt = 0; bt < 4; bt++) {
                    mma16816(acc[mt][2*bt],   ah[mt], &bh[bt][0]);
                    mma16816(acc[mt][2*bt+1], ah[mt], &bh[bt][2]);
                }
#pragma unroll
            for (int mt = 0; mt < 2; mt++) ldsm_x4(al[mt], sAl + aoff + mt*16*ROWB);
#pragma unroll
            for (int mt = 0; mt < 2; mt++)
#pragma unroll
                for (int bt = 0; bt < 4; bt++) {
                    mma16816(acc[mt][2*bt],   al[mt], &bh[bt][0]);
                    mma16816(acc[mt][2*bt+1], al[mt], &bh[bt][2]);
                }
        }
        stc = (stc + 1 == 3) ? 0 : stc + 1;
    }

    // ---------------- epilogue ----------------
#pragma unroll
    for (int mt = 0; mt < 2; mt++) {
        const int rbase = bm*128 + wm*32 + mt*16 + (l >> 2);
#pragma unroll
        for (int half = 0; half < 2; half++) {
            const int t  = rbase + half*8;
            const int bb = t >> 11;
            const int s  = t & (S_LEN - 1);
#pragma unroll
            for (int nt = 0; nt < 8; nt++) {
                const int n0 = bn*128 + wn*64 + nt*8 + (l & 3)*2;
                float x1 = acc[mt][nt][half*2 + 0];
                float x2 = acc[mt][nt][half*2 + 1];
                if (MODE == 0) {
                    float* cp = Cf + (size_t)t*HDIM + n0;
                    cp[0] = x1; cp[1] = x2;
                } else {
                    const int head = n0 >> 7;
                    const int cl   = n0 & 127;
                    if (MODE == 2) {
                        x1 += bias[n0]; x2 += bias[n0 + 1];
                        const size_t base = ((size_t)(bb*n_heads + head)*HD) * S_LEN;
                        Ch[base + (size_t)cl*S_LEN + s]     = __float2half(x1);
                        Ch[base + (size_t)(cl+1)*S_LEN + s] = __float2half(x2);
                    } else {
                        if (bias) { x1 += bias[n0]; x2 += bias[n0 + 1]; }
                        const int d = cl >> 1;
                        const float cs = cosp[s*64 + d];
                        const float sn = sinp[s*64 + d];
                        float y1 = (x1*cs - x2*sn) * scale;
                        float y2 = (x1*sn + x2*cs) * scale;
                        const size_t base = ((size_t)(bb*n_heads + head)*S_LEN + s) * HD;
                        __half h1 = __float2half(y1);
                        __half h2 = __float2half(y2);
                        Ch[base + d]      = h1;
                        Ch[base + 64 + d] = h2;
                        if (Cl) {
                            Cl[base + d]      = __float2half(y1 - __half2float(h1));
                            Cl[base + 64 + d] = __float2half(y2 - __half2float(h2));
                        }
                    }
                }
            }
        }
    }
}

// ---------------------------------------------------------------------------
// HMMA fp16 flash attention: BM=128 (8 warps x 16 rows), BN=64 keys, HD=128.
// Q (scaled, hi/lo) register-resident; K hi / V^T hi, cp.async 3-stage.
// Scores = 2 passes ((qh+ql)*kh); PV = 1 pass (P hi only — rel err ~2^-12).
// Online softmax exp2 domain. Output: AOh/AOl fp16 [t][h*HD+d].
// ---------------------------------------------------------------------------
#define KROW 272                   // K smem row stride (128 fp16 = 256B + 16)
#define VROW 144                   // V^T smem row stride (64 fp16 = 128B + 16)
#define OFF_V  17408               // K tile bytes (64*KROW)
#define ABUF   35840               // K + V per stage
#define ATTN_SMEM (3*ABUF)         // 107520

__global__ void __launch_bounds__(256, 1)
attn_tc(const __half* __restrict__ Qh, const __half* __restrict__ Ql,
        const __half* __restrict__ Kh, const __half* __restrict__ Vth,
        __half* __restrict__ AOh, __half* __restrict__ AOl)
{
    extern __shared__ char smem[];
    const uint32_t sbase = smem_to_u32(smem);
    const int tid = threadIdx.x;
    const int w   = tid >> 5;
    const int l   = tid & 31;
    const int qb  = blockIdx.x;
    const int bh  = blockIdx.y;
    const int b   = bh / NH;
    const int h   = bh % NH;
    const int kv  = h >> 2;

    const __half* Qhb = Qh + ((size_t)bh*S_LEN + qb*128)*HD;
    const __half* Qlb = Ql + ((size_t)bh*S_LEN + qb*128)*HD;
    const __half* Khb = Kh + ((size_t)(b*NKV + kv)*S_LEN)*HD;
    const __half* Vhb = Vth + ((size_t)(b*NKV + kv)*HD)*S_LEN;

    // ---- stage Q into smem (spans stage buffers 0-1), then load frags ----
#pragma unroll
    for (int i = 0; i < 8; i++) {
        int id = tid + i*256;
        int r = id >> 4, c = id & 15;
        *(uint4*)(smem + r*KROW + c*16) =
            *(const uint4*)(Qhb + (size_t)r*HD + c*8);
        *(uint4*)(smem + 34816 + r*KROW + c*16) =
            *(const uint4*)(Qlb + (size_t)r*HD + c*8);
    }
    __syncthreads();

    uint32_t qh[8][4], ql[8][4];
    {
        const uint32_t arow = (uint32_t)(w*16 + (l & 15)) * KROW;
#pragma unroll
        for (int kc = 0; kc < 8; kc++) {
            const uint32_t koff = kc*32 + ((l >> 4) * 16);
            ldsm_x4(qh[kc], sbase + arow + koff);
            ldsm_x4(ql[kc], sbase + 34816 + arow + koff);
        }
    }
    __syncthreads();

    float o[16][4];
#pragma unroll
    for (int nt = 0; nt < 16; nt++)
#pragma unroll
        for (int e = 0; e < 4; e++) o[nt][e] = 0.f;
    float m0 = -1e30f, m1 = -1e30f, l0 = 0.f, l1 = 0.f;

    // prologue: stages 0, 1
#pragma unroll
    for (int st = 0; st < 2; st++) {
        uint32_t dst = sbase + st*ABUF;
        const size_t ko = (size_t)st * 64 * HD;
        const size_t vo = (size_t)st * 64;
#pragma unroll
        for (int i = 0; i < 4; i++) {
            int id = tid + i*256;
            int r = id >> 4, c = id & 15;
            CP_ASYNC16(dst + r*KROW + c*16, Khb + ko + (size_t)r*HD + c*8);
            int rv = id >> 3, cv = id & 7;
            CP_ASYNC16(dst + OFF_V + rv*VROW + cv*16, Vhb + vo + (size_t)rv*S_LEN + cv*8);
        }
        CP_COMMIT();
    }

    const int NKT = S_LEN / 64;   // 32
    int stc = 0;
    for (int kt = 0; kt < NKT; kt++) {
        CP_WAIT(1);
        __syncthreads();
        if (kt + 2 < NKT) {
            const int stn = (stc + 2 >= 3) ? stc - 1 : stc + 2;
            uint32_t dst = sbase + stn*ABUF;
            const size_t ko = (size_t)(kt + 2) * 64 * HD;
            const size_t vo = (size_t)(kt + 2) * 64;
#pragma unroll
            for (int i = 0; i < 4; i++) {
                int id = tid + i*256;
                int r = id >> 4, c = id & 15;
                CP_ASYNC16(dst + r*KROW + c*16, Khb + ko + (size_t)r*HD + c*8);
                int rv = id >> 3, cv = id & 7;
                CP_ASYNC16(dst + OFF_V + rv*VROW + cv*16, Vhb + vo + (size_t)rv*S_LEN + cv*8);
            }
        }
        CP_COMMIT();

        const uint32_t sKh = sbase + stc*ABUF;
        const uint32_t sVh = sKh + OFF_V;

        // ---- QK^T: 16x64 scores, 2 passes ----
        float sc[8][4];
#pragma unroll
        for (int nt = 0; nt < 8; nt++)
#pragma unroll
            for (int e = 0; e < 4; e++) sc[nt][e] = 0.f;

        const uint32_t krow = (uint32_t)(((l >> 4) << 3) + (l & 7)) * KROW;
#pragma unroll
        for (int kc = 0; kc < 8; kc++) {
            const uint32_t kcol = kc*32 + (((l >> 3) & 1) * 16);
            uint32_t khf[4][4];
#pragma unroll
            for (int bt = 0; bt < 4; bt++) ldsm_x4(khf[bt], sKh + krow + bt*16*KROW + kcol);
#pragma unroll
            for (int bt = 0; bt < 4; bt++) {
                mma16816(sc[2*bt],   qh[kc], &khf[bt][0]);
                mma16816(sc[2*bt+1], qh[kc], &khf[bt][2]);
            }
#pragma unroll
            for (int bt = 0; bt < 4; bt++) {
                mma16816(sc[2*bt],   ql[kc], &khf[bt][0]);
                mma16816(sc[2*bt+1], ql[kc], &khf[bt][2]);
            }
        }

        // ---- online softmax (exp2 domain) ----
        float mt0 = -1e30f, mt1 = -1e30f;
#pragma unroll
        for (int nt = 0; nt < 8; nt++) {
            mt0 = fmaxf(mt0, fmaxf(sc[nt][0], sc[nt][1]));
            mt1 = fmaxf(mt1, fmaxf(sc[nt][2], sc[nt][3]));
        }
        mt0 = fmaxf(mt0, __shfl_xor_sync(0xffffffffu, mt0, 1));
        mt0 = fmaxf(mt0, __shfl_xor_sync(0xffffffffu, mt0, 2));
        mt1 = fmaxf(mt1, __shfl_xor_sync(0xffffffffu, mt1, 1));
        mt1 = fmaxf(mt1, __shfl_xor_sync(0xffffffffu, mt1, 2));
        const float mn0 = fmaxf(m0, mt0);
        const float mn1 = fmaxf(m1, mt1);
        const float al0 = ex2f(m0 - mn0);
        const float al1 = ex2f(m1 - mn1);
        m0 = mn0; m1 = mn1;

        float lp0 = 0.f, lp1 = 0.f;
#pragma unroll
        for (int nt = 0; nt < 8; nt++) {
            sc[nt][0] = ex2f(sc[nt][0] - mn0); lp0 += sc[nt][0];
            sc[nt][1] = ex2f(sc[nt][1] - mn0); lp0 += sc[nt][1];
            sc[nt][2] = ex2f(sc[nt][2] - mn1); lp1 += sc[nt][2];
            sc[nt][3] = ex2f(sc[nt][3] - mn1); lp1 += sc[nt][3];
        }
        l0 = l0*al0 + lp0;
        l1 = l1*al1 + lp1;
#pragma unroll
        for (int nt = 0; nt < 16; nt++) {
            o[nt][0] *= al0; o[nt][1] *= al0;
            o[nt][2] *= al1; o[nt][3] *= al1;
        }

        // ---- P hi fragments (registers, fp16, single pass) ----
        uint32_t ph[4][4];
#pragma unroll
        for (int kk = 0; kk < 4; kk++) {
#pragma unroll
            for (int e = 0; e < 4; e++) {
                const int nt = 2*kk + (e >> 1);
                const int i0 = (e & 1) * 2;
                ph[kk][e] = h2_u32(__floats2half2_rn(sc[nt][i0], sc[nt][i0+1]));
            }
        }

        // ---- O += P @ V  (1 pass) ----
        const uint32_t vrow = (uint32_t)(((l >> 4) << 3) + (l & 7)) * VROW;
#pragma unroll
        for (int kk = 0; kk < 4; kk++) {
            const uint32_t vcol = kk*32 + (((l >> 3) & 1) * 16);
            uint32_t vhf[8][4];
#pragma unroll
            for (int nt = 0; nt < 8; nt++) ldsm_x4(vhf[nt], sVh + vrow + nt*16*VROW + vcol);
#pragma unroll
            for (int nt = 0; nt < 8; nt++) {
                mma16816(o[2*nt],   ph[kk], &vhf[nt][0]);
                mma16816(o[2*nt+1], ph[kk], &vhf[nt][2]);
            }
        }
        stc = (stc + 1 == 3) ? 0 : stc + 1;
    }

    // ---- finalize ----
    l0 += __shfl_xor_sync(0xffffffffu, l0, 1);
    l0 += __shfl_xor_sync(0xffffffffu, l0, 2);
    l1 += __shfl_xor_sync(0xffffffffu, l1, 1);
    l1 += __shfl_xor_sync(0xffffffffu, l1, 2);
    const float inv0 = 1.f / l0;
    const float inv1 = 1.f / l1;

    const int gr = l >> 2;
    const int row0 = qb*128 + w*16 + gr;
    const int t0 = b*S_LEN + row0;
    const int t1 = t0 + 8;
    const int cbase = h*HD + (l & 3)*2;
#pragma unroll
    for (int nt = 0; nt < 16; nt++) {
        const int c = cbase + nt*8;
        {
            float v0 = o[nt][0]*inv0, v1 = o[nt][1]*inv0;
            __half2 hv = __floats2half2_rn(v0, v1);
            *(uint32_t*)(AOh + (size_t)t0*HDIM + c) = h2_u32(hv);
            __half2 lv = __floats2half2_rn(v0 - __low2float(hv),
                                           v1 - __high2float(hv));
            *(uint32_t*)(AOl + (size_t)t0*HDIM + c) = h2_u32(lv);
        }
        {
            float v0 = o[nt][2]*inv1, v1 = o[nt][3]*inv1;
            __half2 hv = __floats2half2_rn(v0, v1);
            *(uint32_t*)(AOh + (size_t)t1*HDIM + c) = h2_u32(hv);
            __half2 lv = __floats2half2_rn(v0 - __low2float(hv),
                                           v1 - __high2float(hv));
            *(uint32_t*)(AOl + (size_t)t1*HDIM + c) = h2_u32(lv);
        }
    }
}

// ---------------------------------------------------------------------------
extern "C" void kernel_launch(void* const* d_in, const int* in_sizes, int n_in,
                              void* d_out, int out_size)
{
    const float* hidden = (const float*)d_in[0];
    const float* cosp   = (const float*)d_in[1];
    const float* sinp   = (const float*)d_in[2];
    const float* Wq     = (const float*)d_in[3];
    const float* Wk     = (const float*)d_in[4];
    const float* bk     = (const float*)d_in[5];
    const float* Wv     = (const float*)d_in[6];
    const float* bv     = (const float*)d_in[7];
    const float* Wo     = (const float*)d_in[8];
    float* out = (float*)d_out;

    __half *Hh,*Hl,*Wqh,*Wkh,*Wvh,*Woh;
    __half *Qhp,*Qlp,*Khp,*Vthp,*AOh,*AOl;
    cudaGetSymbolAddress((void**)&Hh,  g_Hh);  cudaGetSymbolAddress((void**)&Hl,  g_Hl);
    cudaGetSymbolAddress((void**)&Wqh, g_Wqh);
    cudaGetSymbolAddress((void**)&Wkh, g_Wkh);
    cudaGetSymbolAddress((void**)&Wvh, g_Wvh);
    cudaGetSymbolAddress((void**)&Woh, g_Woh);
    cudaGetSymbolAddress((void**)&Qhp, g_Qh);  cudaGetSymbolAddress((void**)&Qlp, g_Ql);
    cudaGetSymbolAddress((void**)&Khp, g_Kh);
    cudaGetSymbolAddress((void**)&Vthp, g_Vth);
    cudaGetSymbolAddress((void**)&AOh, g_AOh); cudaGetSymbolAddress((void**)&AOl, g_AOl);

    static bool attr_set = false;
    if (!attr_set) {
        cudaFuncSetAttribute(gemm_tc<0>, cudaFuncAttributeMaxDynamicSharedMemorySize, GEMM_SMEM);
        cudaFuncSetAttribute(gemm_tc<1>, cudaFuncAttributeMaxDynamicSharedMemorySize, GEMM_SMEM);
        cudaFuncSetAttribute(gemm_tc<2>, cudaFuncAttributeMaxDynamicSharedMemorySize, GEMM_SMEM);
        cudaFuncSetAttribute(attn_tc, cudaFuncAttributeMaxDynamicSharedMemorySize, ATTN_SMEM);
        attr_set = true;
    }

    // convert fp32 inputs: hidden -> hi/lo; weights -> hi only
    {
        int nH = T_TOK*HDIM;
        int nW = HDIM*HDIM;
        int nK = KV_N*HDIM;
        cvt2_k<<<nH/1024, 256>>>(hidden, Hh, Hl, nH);
        cvt1_k<<<nW/1024, 256>>>(Wq, Wqh, nW);
        cvt1_k<<<nK/1024, 256>>>(Wk, Wkh, nK);
        cvt1_k<<<nK/1024, 256>>>(Wv, Wvh, nK);
        cvt1_k<<<nW/1024, 256>>>(Wo, Woh, nW);
    }

    // Q = rope(hidden @ Wq^T) * (SCALE*log2e)  -> fp16 hi/lo [b][h][s][d]
    gemm_tc<1><<<dim3(HDIM/128, T_TOK/128), 256, GEMM_SMEM>>>(
        Hh, Hl, Wqh, nullptr, nullptr, Qhp, Qlp, cosp, sinp, NH, Q_SCALE);
    // K = rope(hidden @ Wk^T + bk)             -> fp16 hi [b][kv][s][d]
    gemm_tc<1><<<dim3(KV_N/128, T_TOK/128), 256, GEMM_SMEM>>>(
        Hh, Hl, Wkh, bk, nullptr, Khp, nullptr, cosp, sinp, NKV, 1.0f);
    // V = hidden @ Wv^T + bv                   -> fp16 hi [b][kv][d][s]
    gemm_tc<2><<<dim3(KV_N/128, T_TOK/128), 256, GEMM_SMEM>>>(
        Hh, Hl, Wvh, bv, nullptr, Vthp, nullptr, nullptr, nullptr, NKV, 1.0f);

    // attention -> AOh/AOl fp16 [t][h*HD+d]
    attn_tc<<<dim3(S_LEN/128, BATCH*NH), 256, ATTN_SMEM>>>(
        Qhp, Qlp, Khp, Vthp, AOh, AOl);

    // out = AO @ Wo^T (fp32)
    gemm_tc<0><<<dim3(HDIM/128, T_TOK/128), 256, GEMM_SMEM>>>(
        AOh, AOl, Woh, nullptr, out, nullptr, nullptr, nullptr, nullptr, 0, 1.0f);
}

// round 14
// speedup vs baseline: 6.1564x; 1.2313x over previous
#include <cuda_runtime.h>
#include <cuda_fp16.h>
#include <cstdint>
#include <math.h>

#define S_LEN 2048
#define BATCH 2
#define HDIM  4096
#define HD    128
#define NH    32
#define NKV   8
#define T_TOK (BATCH*S_LEN)   // 4096 tokens
#define KV_N  (NKV*HD)        // 1024

// SCALE * log2(e) folded into Q so softmax works in exp2 domain
#define Q_SCALE (0.08838834764831845f * 1.4426950408889634f)

// ---------------- scratch (__device__ globals; no allocation allowed) -------
__device__ __half g_Hh[(size_t)T_TOK*HDIM];
__device__ __half g_Hl[(size_t)T_TOK*HDIM];
__device__ __half g_Wqh[(size_t)HDIM*HDIM];
__device__ __half g_Wkh[(size_t)KV_N*HDIM];
__device__ __half g_Wvh[(size_t)KV_N*HDIM];
__device__ __half g_Woh[(size_t)HDIM*HDIM];

__device__ __half g_Qh[(size_t)BATCH*NH*S_LEN*HD];   // [b][h][s][d] (scaled)
__device__ __half g_Ql[(size_t)BATCH*NH*S_LEN*HD];
__device__ __half g_Kh[(size_t)BATCH*NKV*S_LEN*HD];  // [b][kv][s][d] (hi only)
__device__ __half g_Vth[(size_t)BATCH*NKV*HD*S_LEN]; // [b][kv][d][s] (hi only)
__device__ __half g_AOh[(size_t)T_TOK*HDIM];         // [t][h*HD+d] (hi only)

// ---------------- PTX helpers ----------------
__device__ __forceinline__ uint32_t smem_to_u32(const void* p) {
    uint32_t a;
    asm("{ .reg .u64 t; cvta.to.shared.u64 t, %1; cvt.u32.u64 %0, t; }"
        : "=r"(a) : "l"(p));
    return a;
}
__device__ __forceinline__ void ldsm_x4(uint32_t* r, uint32_t addr) {
    asm volatile("ldmatrix.sync.aligned.m8n8.x4.shared.b16 {%0,%1,%2,%3}, [%4];"
                 : "=r"(r[0]), "=r"(r[1]), "=r"(r[2]), "=r"(r[3]) : "r"(addr));
}
__device__ __forceinline__ void mma16816(float* d, const uint32_t* a, const uint32_t* b) {
    asm volatile(
        "mma.sync.aligned.m16n8k16.row.col.f32.f16.f16.f32 "
        "{%0,%1,%2,%3}, {%4,%5,%6,%7}, {%8,%9}, {%0,%1,%2,%3};"
        : "+f"(d[0]), "+f"(d[1]), "+f"(d[2]), "+f"(d[3])
        : "r"(a[0]), "r"(a[1]), "r"(a[2]), "r"(a[3]), "r"(b[0]), "r"(b[1]));
}
#define CP_ASYNC16(dst, src) \
    asm volatile("cp.async.cg.shared.global [%0], [%1], 16;" \
                 :: "r"(dst), "l"(src))
#define CP_COMMIT() asm volatile("cp.async.commit_group;" ::: "memory")
#define CP_WAIT(n)  asm volatile("cp.async.wait_group %0;" :: "n"(n) : "memory")

__device__ __forceinline__ float ex2f(float x) {
    float y;
    asm("ex2.approx.ftz.f32 %0, %1;" : "=f"(y) : "f"(x));
    return y;
}
__device__ __forceinline__ uint32_t h2_u32(__half2 h) {
    return *reinterpret_cast<uint32_t*>(&h);
}

// ---------------- fp32 -> fp16 conversions -----------------------
__global__ void __launch_bounds__(256)
cvt2_k(const float* __restrict__ x, __half* __restrict__ h,
       __half* __restrict__ l, int n)
{
    int i = (blockIdx.x * 256 + threadIdx.x) * 4;
    if (i >= n) return;
    float4 v = *(const float4*)(x + i);
    __half h0 = __float2half(v.x);
    __half h1 = __float2half(v.y);
    __half h2 = __float2half(v.z);
    __half h3 = __float2half(v.w);
    *(__half2*)(h + i)     = __halves2half2(h0, h1);
    *(__half2*)(h + i + 2) = __halves2half2(h2, h3);
    *(__half2*)(l + i)     = __floats2half2_rn(v.x - __half2float(h0),
                                               v.y - __half2float(h1));
    *(__half2*)(l + i + 2) = __floats2half2_rn(v.z - __half2float(h2),
                                               v.w - __half2float(h3));
}
__global__ void __launch_bounds__(256)
cvt1_k(const float* __restrict__ x, __half* __restrict__ h, int n)
{
    int i = (blockIdx.x * 256 + threadIdx.x) * 4;
    if (i >= n) return;
    float4 v = *(const float4*)(x + i);
    *(__half2*)(h + i)     = __floats2half2_rn(v.x, v.y);
    *(__half2*)(h + i + 2) = __floats2half2_rn(v.z, v.w);
}

// ---------------------------------------------------------------------------
// HMMA fp16 GEMM: C[M,N] = A[M,K] @ Bh[N,K]^T (+bias), K=4096.
// NPASS=2: A = Ah+Al (two MMA passes). NPASS=1: A = Ah only.
// Block 128x128x32, 8 warps (4Mx2N), warp tile 32x64. 3-stage cp.async,
// one __syncthreads per K-iter.
// MODE 0: fp32 row-major store (O projection -> d_out)
// MODE 1: bias? + RoPE + scale, store fp16 hi (+lo if Cl) [b][head][s][d]
// MODE 2: bias, store fp16 hi TRANSPOSED [b][head][d][s]
// ---------------------------------------------------------------------------
#define BK 32
#define ROWB 80
#define TILE_BYTES (128*ROWB)          // 10240
#define STAGEB (3*TILE_BYTES)          // Ah, Al, Bh = 30720
#define GEMM_SMEM (3*STAGEB)           // 92160

template<int MODE, int NPASS>
__global__ void __launch_bounds__(256, 2)
gemm_tc(const __half* __restrict__ Agh, const __half* __restrict__ Agl,
        const __half* __restrict__ Bgh,
        const float* __restrict__ bias, float* __restrict__ Cf,
        __half* __restrict__ Ch, __half* __restrict__ Cl,
        const float* __restrict__ cosp, const float* __restrict__ sinp,
        int n_heads, float scale)
{
    extern __shared__ char smem[];
    const uint32_t sbase = smem_to_u32(smem);
    const int tid = threadIdx.x;
    const int w   = tid >> 5;
    const int l   = tid & 31;
    const int wm  = w >> 1;
    const int wn  = w & 1;
    const int bm = blockIdx.y, bn = blockIdx.x;
    const int K = HDIM;
    const int NIT = K / BK;   // 128

    const int r0 = tid >> 2, c0 = tid & 3;
    const int r1 = (tid + 256) >> 2;
    const size_t aro = (size_t)(bm*128 + r0)*K + c0*8;
    const size_t ar1 = (size_t)(bm*128 + r1)*K + c0*8;
    const size_t bro = (size_t)(bn*128 + r0)*K + c0*8;
    const size_t br1 = (size_t)(bn*128 + r1)*K + c0*8;
    const uint32_t so0 = r0*ROWB + c0*16;
    const uint32_t so1 = r1*ROWB + c0*16;

    float acc[2][8][4];
#pragma unroll
    for (int mt = 0; mt < 2; mt++)
#pragma unroll
        for (int nt = 0; nt < 8; nt++)
#pragma unroll
            for (int e = 0; e < 4; e++) acc[mt][nt][e] = 0.f;

    // prologue: stages 0, 1
#pragma unroll
    for (int st = 0; st < 2; st++) {
        const int k0 = st * BK;
        uint32_t dst = sbase + st*STAGEB;
        CP_ASYNC16(dst + so0, Agh + aro + k0);
        CP_ASYNC16(dst + so1, Agh + ar1 + k0);
        if (NPASS == 2) {
            CP_ASYNC16(dst + TILE_BYTES + so0, Agl + aro + k0);
            CP_ASYNC16(dst + TILE_BYTES + so1, Agl + ar1 + k0);
        }
        CP_ASYNC16(dst + 2*TILE_BYTES + so0, Bgh + bro + k0);
        CP_ASYNC16(dst + 2*TILE_BYTES + so1, Bgh + br1 + k0);
        CP_COMMIT();
    }

    int stc = 0;                   // stage of tile `it`
    for (int it = 0; it < NIT; it++) {
        CP_WAIT(1);
        __syncthreads();
        if (it + 2 < NIT) {
            const int k0 = (it + 2) * BK;
            const int stn = (stc + 2 >= 3) ? stc - 1 : stc + 2;
            uint32_t dst = sbase + stn*STAGEB;
            CP_ASYNC16(dst + so0, Agh + aro + k0);
            CP_ASYNC16(dst + so1, Agh + ar1 + k0);
            if (NPASS == 2) {
                CP_ASYNC16(dst + TILE_BYTES + so0, Agl + aro + k0);
                CP_ASYNC16(dst + TILE_BYTES + so1, Agl + ar1 + k0);
            }
            CP_ASYNC16(dst + 2*TILE_BYTES + so0, Bgh + bro + k0);
            CP_ASYNC16(dst + 2*TILE_BYTES + so1, Bgh + br1 + k0);
        }
        CP_COMMIT();

        const uint32_t sAh = sbase + stc*STAGEB;
        const uint32_t sAl = sAh + TILE_BYTES;
        const uint32_t sBh = sAh + 2*TILE_BYTES;

#pragma unroll
        for (int ks = 0; ks < 2; ks++) {
            const uint32_t koff = ks*32 + ((l >> 4) * 16);
            const uint32_t aoff = (uint32_t)(wm*32 + (l & 15)) * ROWB + koff;
            const uint32_t boff = (uint32_t)(wn*64 + ((l >> 4) << 3) + (l & 7)) * ROWB
                                  + ks*32 + (((l >> 3) & 1) * 16);
            uint32_t ah[2][4], al[2][4], bh[4][4];
#pragma unroll
            for (int mt = 0; mt < 2; mt++) ldsm_x4(ah[mt], sAh + aoff + mt*16*ROWB);
#pragma unroll
            for (int bt = 0; bt < 4; bt++) ldsm_x4(bh[bt], sBh + boff + bt*16*ROWB);
#pragma unroll
            for (int mt = 0; mt < 2; mt++)
#pragma unroll
                for (int bt = 0; bt < 4; bt++) {
                    mma16816(acc[mt][2*bt],   ah[mt], &bh[bt][0]);
                    mma16816(acc[mt][2*bt+1], ah[mt], &bh[bt][2]);
                }
            if (NPASS == 2) {
#pragma unroll
                for (int mt = 0; mt < 2; mt++) ldsm_x4(al[mt], sAl + aoff + mt*16*ROWB);
#pragma unroll
                for (int mt = 0; mt < 2; mt++)
#pragma unroll
                    for (int bt = 0; bt < 4; bt++) {
                        mma16816(acc[mt][2*bt],   al[mt], &bh[bt][0]);
                        mma16816(acc[mt][2*bt+1], al[mt], &bh[bt][2]);
                    }
            }
        }
        stc = (stc + 1 == 3) ? 0 : stc + 1;
    }

    // ---------------- epilogue ----------------
#pragma unroll
    for (int mt = 0; mt < 2; mt++) {
        const int rbase = bm*128 + wm*32 + mt*16 + (l >> 2);
#pragma unroll
        for (int half = 0; half < 2; half++) {
            const int t  = rbase + half*8;
            const int bb = t >> 11;
            const int s  = t & (S_LEN - 1);
#pragma unroll
            for (int nt = 0; nt < 8; nt++) {
                const int n0 = bn*128 + wn*64 + nt*8 + (l & 3)*2;
                float x1 = acc[mt][nt][half*2 + 0];
                float x2 = acc[mt][nt][half*2 + 1];
                if (MODE == 0) {
                    float* cp = Cf + (size_t)t*HDIM + n0;
                    cp[0] = x1; cp[1] = x2;
                } else {
                    const int head = n0 >> 7;
                    const int cl   = n0 & 127;
                    if (MODE == 2) {
                        x1 += bias[n0]; x2 += bias[n0 + 1];
                        const size_t base = ((size_t)(bb*n_heads + head)*HD) * S_LEN;
                        Ch[base + (size_t)cl*S_LEN + s]     = __float2half(x1);
                        Ch[base + (size_t)(cl+1)*S_LEN + s] = __float2half(x2);
                    } else {
                        if (bias) { x1 += bias[n0]; x2 += bias[n0 + 1]; }
                        const int d = cl >> 1;
                        const float cs = cosp[s*64 + d];
                        const float sn = sinp[s*64 + d];
                        float y1 = (x1*cs - x2*sn) * scale;
                        float y2 = (x1*sn + x2*cs) * scale;
                        const size_t base = ((size_t)(bb*n_heads + head)*S_LEN + s) * HD;
                        __half h1 = __float2half(y1);
                        __half h2 = __float2half(y2);
                        Ch[base + d]      = h1;
                        Ch[base + 64 + d] = h2;
                        if (Cl) {
                            Cl[base + d]      = __float2half(y1 - __half2float(h1));
                            Cl[base + 64 + d] = __float2half(y2 - __half2float(h2));
                        }
                    }
                }
            }
        }
    }
}

// ---------------------------------------------------------------------------
// HMMA fp16 flash attention: BM=128 (8 warps x 16 rows), BN=64 keys, HD=128.
// Q (scaled, hi/lo) register-resident; K hi / V^T hi, cp.async 3-stage.
// Scores = 2 passes ((qh+ql)*kh); PV = 1 pass (P hi only).
// Online softmax exp2 domain. Output: AOh fp16 [t][h*HD+d] (hi only).
// ---------------------------------------------------------------------------
#define KROW 272                   // K smem row stride (128 fp16 = 256B + 16)
#define VROW 144                   // V^T smem row stride (64 fp16 = 128B + 16)
#define OFF_V  17408               // K tile bytes (64*KROW)
#define ABUF   35840               // K + V per stage
#define ATTN_SMEM (3*ABUF)         // 107520

__global__ void __launch_bounds__(256, 1)
attn_tc(const __half* __restrict__ Qh, const __half* __restrict__ Ql,
        const __half* __restrict__ Kh, const __half* __restrict__ Vth,
        __half* __restrict__ AOh)
{
    extern __shared__ char smem[];
    const uint32_t sbase = smem_to_u32(smem);
    const int tid = threadIdx.x;
    const int w   = tid >> 5;
    const int l   = tid & 31;
    const int qb  = blockIdx.x;
    const int bh  = blockIdx.y;
    const int b   = bh / NH;
    const int h   = bh % NH;
    const int kv  = h >> 2;

    const __half* Qhb = Qh + ((size_t)bh*S_LEN + qb*128)*HD;
    const __half* Qlb = Ql + ((size_t)bh*S_LEN + qb*128)*HD;
    const __half* Khb = Kh + ((size_t)(b*NKV + kv)*S_LEN)*HD;
    const __half* Vhb = Vth + ((size_t)(b*NKV + kv)*HD)*S_LEN;

    // ---- stage Q into smem (spans stage buffers 0-1), then load frags ----
#pragma unroll
    for (int i = 0; i < 8; i++) {
        int id = tid + i*256;
        int r = id >> 4, c = id & 15;
        *(uint4*)(smem + r*KROW + c*16) =
            *(const uint4*)(Qhb + (size_t)r*HD + c*8);
        *(uint4*)(smem + 34816 + r*KROW + c*16) =
            *(const uint4*)(Qlb + (size_t)r*HD + c*8);
    }
    __syncthreads();

    uint32_t qh[8][4], ql[8][4];
    {
        const uint32_t arow = (uint32_t)(w*16 + (l & 15)) * KROW;
#pragma unroll
        for (int kc = 0; kc < 8; kc++) {
            const uint32_t koff = kc*32 + ((l >> 4) * 16);
            ldsm_x4(qh[kc], sbase + arow + koff);
            ldsm_x4(ql[kc], sbase + 34816 + arow + koff);
        }
    }
    __syncthreads();

    float o[16][4];
#pragma unroll
    for (int nt = 0; nt < 16; nt++)
#pragma unroll
        for (int e = 0; e < 4; e++) o[nt][e] = 0.f;
    float m0 = -1e30f, m1 = -1e30f, l0 = 0.f, l1 = 0.f;

    // prologue: stages 0, 1
#pragma unroll
    for (int st = 0; st < 2; st++) {
        uint32_t dst = sbase + st*ABUF;
        const size_t ko = (size_t)st * 64 * HD;
        const size_t vo = (size_t)st * 64;
#pragma unroll
        for (int i = 0; i < 4; i++) {
            int id = tid + i*256;
            int r = id >> 4, c = id & 15;
            CP_ASYNC16(dst + r*KROW + c*16, Khb + ko + (size_t)r*HD + c*8);
            int rv = id >> 3, cv = id & 7;
            CP_ASYNC16(dst + OFF_V + rv*VROW + cv*16, Vhb + vo + (size_t)rv*S_LEN + cv*8);
        }
        CP_COMMIT();
    }

    const int NKT = S_LEN / 64;   // 32
    int stc = 0;
    for (int kt = 0; kt < NKT; kt++) {
        CP_WAIT(1);
        __syncthreads();
        if (kt + 2 < NKT) {
            const int stn = (stc + 2 >= 3) ? stc - 1 : stc + 2;
            uint32_t dst = sbase + stn*ABUF;
            const size_t ko = (size_t)(kt + 2) * 64 * HD;
            const size_t vo = (size_t)(kt + 2) * 64;
#pragma unroll
            for (int i = 0; i < 4; i++) {
                int id = tid + i*256;
                int r = id >> 4, c = id & 15;
                CP_ASYNC16(dst + r*KROW + c*16, Khb + ko + (size_t)r*HD + c*8);
                int rv = id >> 3, cv = id & 7;
                CP_ASYNC16(dst + OFF_V + rv*VROW + cv*16, Vhb + vo + (size_t)rv*S_LEN + cv*8);
            }
        }
        CP_COMMIT();

        const uint32_t sKh = sbase + stc*ABUF;
        const uint32_t sVh = sKh + OFF_V;

        // ---- QK^T: 16x64 scores, 2 passes ----
        float sc[8][4];
#pragma unroll
        for (int nt = 0; nt < 8; nt++)
#pragma unroll
            for (int e = 0; e < 4; e++) sc[nt][e] = 0.f;

        const uint32_t krow = (uint32_t)(((l >> 4) << 3) + (l & 7)) * KROW;
#pragma unroll
        for (int kc = 0; kc < 8; kc++) {
            const uint32_t kcol = kc*32 + (((l >> 3) & 1) * 16);
            uint32_t khf[4][4];
#pragma unroll
            for (int bt = 0; bt < 4; bt++) ldsm_x4(khf[bt], sKh + krow + bt*16*KROW + kcol);
#pragma unroll
            for (int bt = 0; bt < 4; bt++) {
                mma16816(sc[2*bt],   qh[kc], &khf[bt][0]);
                mma16816(sc[2*bt+1], qh[kc], &khf[bt][2]);
            }
#pragma unroll
            for (int bt = 0; bt < 4; bt++) {
                mma16816(sc[2*bt],   ql[kc], &khf[bt][0]);
                mma16816(sc[2*bt+1], ql[kc], &khf[bt][2]);
            }
        }

        // ---- online softmax (exp2 domain) ----
        float mt0 = -1e30f, mt1 = -1e30f;
#pragma unroll
        for (int nt = 0; nt < 8; nt++) {
            mt0 = fmaxf(mt0, fmaxf(sc[nt][0], sc[nt][1]));
            mt1 = fmaxf(mt1, fmaxf(sc[nt][2], sc[nt][3]));
        }
        mt0 = fmaxf(mt0, __shfl_xor_sync(0xffffffffu, mt0, 1));
        mt0 = fmaxf(mt0, __shfl_xor_sync(0xffffffffu, mt0, 2));
        mt1 = fmaxf(mt1, __shfl_xor_sync(0xffffffffu, mt1, 1));
        mt1 = fmaxf(mt1, __shfl_xor_sync(0xffffffffu, mt1, 2));
        const float mn0 = fmaxf(m0, mt0);
        const float mn1 = fmaxf(m1, mt1);
        const float al0 = ex2f(m0 - mn0);
        const float al1 = ex2f(m1 - mn1);
        m0 = mn0; m1 = mn1;

        float lp0 = 0.f, lp1 = 0.f;
#pragma unroll
        for (int nt = 0; nt < 8; nt++) {
            sc[nt][0] = ex2f(sc[nt][0] - mn0); lp0 += sc[nt][0];
            sc[nt][1] = ex2f(sc[nt][1] - mn0); lp0 += sc[nt][1];
            sc[nt][2] = ex2f(sc[nt][2] - mn1); lp1 += sc[nt][2];
            sc[nt][3] = ex2f(sc[nt][3] - mn1); lp1 += sc[nt][3];
        }
        l0 = l0*al0 + lp0;
        l1 = l1*al1 + lp1;
#pragma unroll
        for (int nt = 0; nt < 16; nt++) {
            o[nt][0] *= al0; o[nt][1] *= al0;
            o[nt][2] *= al1; o[nt][3] *= al1;
        }

        // ---- P hi fragments (registers, fp16, single pass) ----
        uint32_t ph[4][4];
#pragma unroll
        for (int kk = 0; kk < 4; kk++) {
#pragma unroll
            for (int e = 0; e < 4; e++) {
                const int nt = 2*kk + (e >> 1);
                const int i0 = (e & 1) * 2;
                ph[kk][e] = h2_u32(__floats2half2_rn(sc[nt][i0], sc[nt][i0+1]));
            }
        }

        // ---- O += P @ V  (1 pass) ----
        const uint32_t vrow = (uint32_t)(((l >> 4) << 3) + (l & 7)) * VROW;
#pragma unroll
        for (int kk = 0; kk < 4; kk++) {
            const uint32_t vcol = kk*32 + (((l >> 3) & 1) * 16);
            uint32_t vhf[8][4];
#pragma unroll
            for (int nt = 0; nt < 8; nt++) ldsm_x4(vhf[nt], sVh + vrow + nt*16*VROW + vcol);
#pragma unroll
            for (int nt = 0; nt < 8; nt++) {
                mma16816(o[2*nt],   ph[kk], &vhf[nt][0]);
                mma16816(o[2*nt+1], ph[kk], &vhf[nt][2]);
            }
        }
        stc = (stc + 1 == 3) ? 0 : stc + 1;
    }

    // ---- finalize ----
    l0 += __shfl_xor_sync(0xffffffffu, l0, 1);
    l0 += __shfl_xor_sync(0xffffffffu, l0, 2);
    l1 += __shfl_xor_sync(0xffffffffu, l1, 1);
    l1 += __shfl_xor_sync(0xffffffffu, l1, 2);
    const float inv0 = 1.f / l0;
    const float inv1 = 1.f / l1;

    const int gr = l >> 2;
    const int row0 = qb*128 + w*16 + gr;
    const int t0 = b*S_LEN + row0;
    const int t1 = t0 + 8;
    const int cbase = h*HD + (l & 3)*2;
#pragma unroll
    for (int nt = 0; nt < 16; nt++) {
        const int c = cbase + nt*8;
        {
            float v0 = o[nt][0]*inv0, v1 = o[nt][1]*inv0;
            *(uint32_t*)(AOh + (size_t)t0*HDIM + c) = h2_u32(__floats2half2_rn(v0, v1));
        }
        {
            float v0 = o[nt][2]*inv1, v1 = o[nt][3]*inv1;
            *(uint32_t*)(AOh + (size_t)t1*HDIM + c) = h2_u32(__floats2half2_rn(v0, v1));
        }
    }
}

// ---------------------------------------------------------------------------
extern "C" void kernel_launch(void* const* d_in, const int* in_sizes, int n_in,
                              void* d_out, int out_size)
{
    const float* hidden = (const float*)d_in[0];
    const float* cosp   = (const float*)d_in[1];
    const float* sinp   = (const float*)d_in[2];
    const float* Wq     = (const float*)d_in[3];
    const float* Wk     = (const float*)d_in[4];
    const float* bk     = (const float*)d_in[5];
    const float* Wv     = (const float*)d_in[6];
    const float* bv     = (const float*)d_in[7];
    const float* Wo     = (const float*)d_in[8];
    float* out = (float*)d_out;

    __half *Hh,*Hl,*Wqh,*Wkh,*Wvh,*Woh;
    __half *Qhp,*Qlp,*Khp,*Vthp,*AOh;
    cudaGetSymbolAddress((void**)&Hh,  g_Hh);  cudaGetSymbolAddress((void**)&Hl,  g_Hl);
    cudaGetSymbolAddress((void**)&Wqh, g_Wqh);
    cudaGetSymbolAddress((void**)&Wkh, g_Wkh);
    cudaGetSymbolAddress((void**)&Wvh, g_Wvh);
    cudaGetSymbolAddress((void**)&Woh, g_Woh);
    cudaGetSymbolAddress((void**)&Qhp, g_Qh);  cudaGetSymbolAddress((void**)&Qlp, g_Ql);
    cudaGetSymbolAddress((void**)&Khp, g_Kh);
    cudaGetSymbolAddress((void**)&Vthp, g_Vth);
    cudaGetSymbolAddress((void**)&AOh, g_AOh);

    static bool attr_set = false;
    if (!attr_set) {
        cudaFuncSetAttribute((const void*)gemm_tc<0,1>, cudaFuncAttributeMaxDynamicSharedMemorySize, GEMM_SMEM);
        cudaFuncSetAttribute((const void*)gemm_tc<1,2>, cudaFuncAttributeMaxDynamicSharedMemorySize, GEMM_SMEM);
        cudaFuncSetAttribute((const void*)gemm_tc<1,1>, cudaFuncAttributeMaxDynamicSharedMemorySize, GEMM_SMEM);
        cudaFuncSetAttribute((const void*)gemm_tc<2,1>, cudaFuncAttributeMaxDynamicSharedMemorySize, GEMM_SMEM);
        cudaFuncSetAttribute((const void*)attn_tc, cudaFuncAttributeMaxDynamicSharedMemorySize, ATTN_SMEM);
        attr_set = true;
    }

    // convert fp32 inputs: hidden -> hi/lo; weights -> hi only
    {
        int nH = T_TOK*HDIM;
        int nW = HDIM*HDIM;
        int nK = KV_N*HDIM;
        cvt2_k<<<nH/1024, 256>>>(hidden, Hh, Hl, nH);
        cvt1_k<<<nW/1024, 256>>>(Wq, Wqh, nW);
        cvt1_k<<<nK/1024, 256>>>(Wk, Wkh, nK);
        cvt1_k<<<nK/1024, 256>>>(Wv, Wvh, nK);
        cvt1_k<<<nW/1024, 256>>>(Wo, Woh, nW);
    }

    // Q = rope(hidden @ Wq^T) * (SCALE*log2e)  -> fp16 hi/lo [b][h][s][d], 2-pass A
    gemm_tc<1,2><<<dim3(HDIM/128, T_TOK/128), 256, GEMM_SMEM>>>(
        Hh, Hl, Wqh, nullptr, nullptr, Qhp, Qlp, cosp, sinp, NH, Q_SCALE);
    // K = rope(hidden @ Wk^T + bk)             -> fp16 hi [b][kv][s][d], 1-pass A
    gemm_tc<1,1><<<dim3(KV_N/128, T_TOK/128), 256, GEMM_SMEM>>>(
        Hh, nullptr, Wkh, bk, nullptr, Khp, nullptr, cosp, sinp, NKV, 1.0f);
    // V = hidden @ Wv^T + bv                   -> fp16 hi [b][kv][d][s], 1-pass A
    gemm_tc<2,1><<<dim3(KV_N/128, T_TOK/128), 256, GEMM_SMEM>>>(
        Hh, nullptr, Wvh, bv, nullptr, Vthp, nullptr, nullptr, nullptr, NKV, 1.0f);

    // attention -> AOh fp16 [t][h*HD+d]
    attn_tc<<<dim3(S_LEN/128, BATCH*NH), 256, ATTN_SMEM>>>(
        Qhp, Qlp, Khp, Vthp, AOh);

    // out = AO @ Wo^T (fp32), 1-pass A
    gemm_tc<0,1><<<dim3(HDIM/128, T_TOK/128), 256, GEMM_SMEM>>>(
        AOh, nullptr, Woh, nullptr, out, nullptr, nullptr, nullptr, nullptr, 0, 1.0f);
}

// round 15
// speedup vs baseline: 7.8770x; 1.2795x over previous
#include <cuda_runtime.h>
#include <cuda_fp16.h>
#include <cstdint>
#include <math.h>

#define S_LEN 2048
#define BATCH 2
#define HDIM  4096
#define HD    128
#define NH    32
#define NKV   8
#define T_TOK (BATCH*S_LEN)   // 4096 tokens
#define KV_N  (NKV*HD)        // 1024

// SCALE * log2(e) folded into Q so softmax works in exp2 domain
#define Q_SCALE (0.08838834764831845f * 1.4426950408889634f)

// ---------------- scratch (__device__ globals; no allocation allowed) -------
__device__ __half g_Hh[(size_t)T_TOK*HDIM];
__device__ __half g_Wqh[(size_t)HDIM*HDIM];
__device__ __half g_Wkh[(size_t)KV_N*HDIM];
__device__ __half g_Wvh[(size_t)KV_N*HDIM];
__device__ __half g_Woh[(size_t)HDIM*HDIM];

__device__ __half g_Qh[(size_t)BATCH*NH*S_LEN*HD];   // [b][h][s][d] (scaled)
__device__ __half g_Kh[(size_t)BATCH*NKV*S_LEN*HD];  // [b][kv][s][d]
__device__ __half g_Vth[(size_t)BATCH*NKV*HD*S_LEN]; // [b][kv][d][s] (transposed)
__device__ __half g_AOh[(size_t)T_TOK*HDIM];         // [t][h*HD+d]

// ---------------- PTX helpers ----------------
__device__ __forceinline__ uint32_t smem_to_u32(const void* p) {
    uint32_t a;
    asm("{ .reg .u64 t; cvta.to.shared.u64 t, %1; cvt.u32.u64 %0, t; }"
        : "=r"(a) : "l"(p));
    return a;
}
__device__ __forceinline__ void ldsm_x4(uint32_t* r, uint32_t addr) {
    asm volatile("ldmatrix.sync.aligned.m8n8.x4.shared.b16 {%0,%1,%2,%3}, [%4];"
                 : "=r"(r[0]), "=r"(r[1]), "=r"(r[2]), "=r"(r[3]) : "r"(addr));
}
__device__ __forceinline__ void mma16816(float* d, const uint32_t* a, const uint32_t* b) {
    asm volatile(
        "mma.sync.aligned.m16n8k16.row.col.f32.f16.f16.f32 "
        "{%0,%1,%2,%3}, {%4,%5,%6,%7}, {%8,%9}, {%0,%1,%2,%3};"
        : "+f"(d[0]), "+f"(d[1]), "+f"(d[2]), "+f"(d[3])
        : "r"(a[0]), "r"(a[1]), "r"(a[2]), "r"(a[3]), "r"(b[0]), "r"(b[1]));
}
#define CP_ASYNC16(dst, src) \
    asm volatile("cp.async.cg.shared.global [%0], [%1], 16;" \
                 :: "r"(dst), "l"(src))
#define CP_COMMIT() asm volatile("cp.async.commit_group;" ::: "memory")
#define CP_WAIT(n)  asm volatile("cp.async.wait_group %0;" :: "n"(n) : "memory")

__device__ __forceinline__ float ex2f(float x) {
    float y;
    asm("ex2.approx.ftz.f32 %0, %1;" : "=f"(y) : "f"(x));
    return y;
}
__device__ __forceinline__ uint32_t h2_u32(__half2 h) {
    return *reinterpret_cast<uint32_t*>(&h);
}

// ---------------- fp32 -> fp16 conversion (8 elem/thread for ILP) -----------
__global__ void __launch_bounds__(256)
cvt1_k(const float* __restrict__ x, __half* __restrict__ h, int n)
{
    int i = (blockIdx.x * 256 + threadIdx.x) * 8;
    if (i >= n) return;
    float4 a = *(const float4*)(x + i);
    float4 b = *(const float4*)(x + i + 4);
    uint4 o;
    o.x = h2_u32(__floats2half2_rn(a.x, a.y));
    o.y = h2_u32(__floats2half2_rn(a.z, a.w));
    o.z = h2_u32(__floats2half2_rn(b.x, b.y));
    o.w = h2_u32(__floats2half2_rn(b.z, b.w));
    *(uint4*)(h + i) = o;
}

// ---------------------------------------------------------------------------
// HMMA fp16 1-pass GEMM: C[M,N] = Ah[M,K] @ Bh[N,K]^T (+bias), K=4096.
// Block 128x128x32, 8 warps (4Mx2N), warp tile 32x64. 3-stage cp.async,
// one __syncthreads per K-iter.
// MODE 0: fp32 row-major store (O projection -> d_out)
// MODE 1: bias? + RoPE + scale, store fp16 hi [b][head][s][d]  (Q, K)
// MODE 2: bias, store fp16 hi TRANSPOSED [b][head][d][s]       (V)
// ---------------------------------------------------------------------------
#define BK 32
#define ROWB 80
#define TILE_BYTES (128*ROWB)          // 10240
#define STAGEB (2*TILE_BYTES)          // Ah, Bh = 20480
#define GEMM_SMEM (3*STAGEB)           // 61440

template<int MODE>
__global__ void __launch_bounds__(256, 2)
gemm_tc(const __half* __restrict__ Agh,
        const __half* __restrict__ Bgh,
        const float* __restrict__ bias, float* __restrict__ Cf,
        __half* __restrict__ Ch,
        const float* __restrict__ cosp, const float* __restrict__ sinp,
        int n_heads, float scale)
{
    extern __shared__ char smem[];
    const uint32_t sbase = smem_to_u32(smem);
    const int tid = threadIdx.x;
    const int w   = tid >> 5;
    const int l   = tid & 31;
    const int wm  = w >> 1;
    const int wn  = w & 1;
    const int bm = blockIdx.y, bn = blockIdx.x;
    const int K = HDIM;
    const int NIT = K / BK;   // 128

    const int r0 = tid >> 2, c0 = tid & 3;
    const int r1 = (tid + 256) >> 2;
    const size_t aro = (size_t)(bm*128 + r0)*K + c0*8;
    const size_t ar1 = (size_t)(bm*128 + r1)*K + c0*8;
    const size_t bro = (size_t)(bn*128 + r0)*K + c0*8;
    const size_t br1 = (size_t)(bn*128 + r1)*K + c0*8;
    const uint32_t so0 = r0*ROWB + c0*16;
    const uint32_t so1 = r1*ROWB + c0*16;

    float acc[2][8][4];
#pragma unroll
    for (int mt = 0; mt < 2; mt++)
#pragma unroll
        for (int nt = 0; nt < 8; nt++)
#pragma unroll
            for (int e = 0; e < 4; e++) acc[mt][nt][e] = 0.f;

    // prologue: stages 0, 1
#pragma unroll
    for (int st = 0; st < 2; st++) {
        const int k0 = st * BK;
        uint32_t dst = sbase + st*STAGEB;
        CP_ASYNC16(dst + so0, Agh + aro + k0);
        CP_ASYNC16(dst + so1, Agh + ar1 + k0);
        CP_ASYNC16(dst + TILE_BYTES + so0, Bgh + bro + k0);
        CP_ASYNC16(dst + TILE_BYTES + so1, Bgh + br1 + k0);
        CP_COMMIT();
    }

    int stc = 0;                   // stage of tile `it`
    for (int it = 0; it < NIT; it++) {
        CP_WAIT(1);
        __syncthreads();
        if (it + 2 < NIT) {
            const int k0 = (it + 2) * BK;
            const int stn = (stc + 2 >= 3) ? stc - 1 : stc + 2;
            uint32_t dst = sbase + stn*STAGEB;
            CP_ASYNC16(dst + so0, Agh + aro + k0);
            CP_ASYNC16(dst + so1, Agh + ar1 + k0);
            CP_ASYNC16(dst + TILE_BYTES + so0, Bgh + bro + k0);
            CP_ASYNC16(dst + TILE_BYTES + so1, Bgh + br1 + k0);
        }
        CP_COMMIT();

        const uint32_t sAh = sbase + stc*STAGEB;
        const uint32_t sBh = sAh + TILE_BYTES;

#pragma unroll
        for (int ks = 0; ks < 2; ks++) {
            const uint32_t koff = ks*32 + ((l >> 4) * 16);
            const uint32_t aoff = (uint32_t)(wm*32 + (l & 15)) * ROWB + koff;
            const uint32_t boff = (uint32_t)(wn*64 + ((l >> 4) << 3) + (l & 7)) * ROWB
                                  + ks*32 + (((l >> 3) & 1) * 16);
            uint32_t ah[2][4], bh[4][4];
#pragma unroll
            for (int mt = 0; mt < 2; mt++) ldsm_x4(ah[mt], sAh + aoff + mt*16*ROWB);
#pragma unroll
            for (int bt = 0; bt < 4; bt++) ldsm_x4(bh[bt], sBh + boff + bt*16*ROWB);
#pragma unroll
            for (int mt = 0; mt < 2; mt++)
#pragma unroll
                for (int bt = 0; bt < 4; bt++) {
                    mma16816(acc[mt][2*bt],   ah[mt], &bh[bt][0]);
                    mma16816(acc[mt][2*bt+1], ah[mt], &bh[bt][2]);
                }
        }
        stc = (stc + 1 == 3) ? 0 : stc + 1;
    }

    // ---------------- epilogue ----------------
#pragma unroll
    for (int mt = 0; mt < 2; mt++) {
        const int rbase = bm*128 + wm*32 + mt*16 + (l >> 2);
#pragma unroll
        for (int half = 0; half < 2; half++) {
            const int t  = rbase + half*8;
            const int bb = t >> 11;
            const int s  = t & (S_LEN - 1);
#pragma unroll
            for (int nt = 0; nt < 8; nt++) {
                const int n0 = bn*128 + wn*64 + nt*8 + (l & 3)*2;
                float x1 = acc[mt][nt][half*2 + 0];
                float x2 = acc[mt][nt][half*2 + 1];
                if (MODE == 0) {
                    float* cp = Cf + (size_t)t*HDIM + n0;
                    cp[0] = x1; cp[1] = x2;
                } else {
                    const int head = n0 >> 7;
                    const int cl   = n0 & 127;
                    if (MODE == 2) {
                        x1 += bias[n0]; x2 += bias[n0 + 1];
                        const size_t base = ((size_t)(bb*n_heads + head)*HD) * S_LEN;
                        Ch[base + (size_t)cl*S_LEN + s]     = __float2half(x1);
                        Ch[base + (size_t)(cl+1)*S_LEN + s] = __float2half(x2);
                    } else {
                        if (bias) { x1 += bias[n0]; x2 += bias[n0 + 1]; }
                        const int d = cl >> 1;
                        const float cs = cosp[s*64 + d];
                        const float sn = sinp[s*64 + d];
                        float y1 = (x1*cs - x2*sn) * scale;
                        float y2 = (x1*sn + x2*cs) * scale;
                        const size_t base = ((size_t)(bb*n_heads + head)*S_LEN + s) * HD;
                        Ch[base + d]      = __float2half(y1);
                        Ch[base + 64 + d] = __float2half(y2);
                    }
                }
            }
        }
    }
}

// ---------------------------------------------------------------------------
// HMMA fp16 flash attention: BM=128 (8 warps x 16 rows), BN=64 keys, HD=128.
// Q (scaled) register-resident; K / V^T, cp.async 3-stage.
// Scores = 1 pass (qh*kh); PV = 1 pass (P hi only).
// Online softmax exp2 domain. Output: AOh fp16 [t][h*HD+d].
// ---------------------------------------------------------------------------
#define KROW 272                   // K smem row stride (128 fp16 = 256B + 16)
#define VROW 144                   // V^T smem row stride (64 fp16 = 128B + 16)
#define OFF_V  17408               // K tile bytes (64*KROW)
#define ABUF   35840               // K + V per stage
#define ATTN_SMEM (3*ABUF)         // 107520

__global__ void __launch_bounds__(256, 1)
attn_tc(const __half* __restrict__ Qh,
        const __half* __restrict__ Kh, const __half* __restrict__ Vth,
        __half* __restrict__ AOh)
{
    extern __shared__ char smem[];
    const uint32_t sbase = smem_to_u32(smem);
    const int tid = threadIdx.x;
    const int w   = tid >> 5;
    const int l   = tid & 31;
    const int qb  = blockIdx.x;
    const int bh  = blockIdx.y;
    const int b   = bh / NH;
    const int h   = bh % NH;
    const int kv  = h >> 2;

    const __half* Qhb = Qh + ((size_t)bh*S_LEN + qb*128)*HD;
    const __half* Khb = Kh + ((size_t)(b*NKV + kv)*S_LEN)*HD;
    const __half* Vhb = Vth + ((size_t)(b*NKV + kv)*HD)*S_LEN;

    // ---- stage Q into smem (buf area), then load frags ----
#pragma unroll
    for (int i = 0; i < 8; i++) {
        int id = tid + i*256;
        int r = id >> 4, c = id & 15;
        *(uint4*)(smem + r*KROW + c*16) =
            *(const uint4*)(Qhb + (size_t)r*HD + c*8);
    }
    __syncthreads();

    uint32_t qh[8][4];
    {
        const uint32_t arow = (uint32_t)(w*16 + (l & 15)) * KROW;
#pragma unroll
        for (int kc = 0; kc < 8; kc++) {
            const uint32_t koff = kc*32 + ((l >> 4) * 16);
            ldsm_x4(qh[kc], sbase + arow + koff);
        }
    }
    __syncthreads();

    float o[16][4];
#pragma unroll
    for (int nt = 0; nt < 16; nt++)
#pragma unroll
        for (int e = 0; e < 4; e++) o[nt][e] = 0.f;
    float m0 = -1e30f, m1 = -1e30f, l0 = 0.f, l1 = 0.f;

    // prologue: stages 0, 1
#pragma unroll
    for (int st = 0; st < 2; st++) {
        uint32_t dst = sbase + st*ABUF;
        const size_t ko = (size_t)st * 64 * HD;
        const size_t vo = (size_t)st * 64;
#pragma unroll
        for (int i = 0; i < 4; i++) {
            int id = tid + i*256;
            int r = id >> 4, c = id & 15;
            CP_ASYNC16(dst + r*KROW + c*16, Khb + ko + (size_t)r*HD + c*8);
            int rv = id >> 3, cv = id & 7;
            CP_ASYNC16(dst + OFF_V + rv*VROW + cv*16, Vhb + vo + (size_t)rv*S_LEN + cv*8);
        }
        CP_COMMIT();
    }

    const int NKT = S_LEN / 64;   // 32
    int stc = 0;
    for (int kt = 0; kt < NKT; kt++) {
        CP_WAIT(1);
        __syncthreads();
        if (kt + 2 < NKT) {
            const int stn = (stc + 2 >= 3) ? stc - 1 : stc + 2;
            uint32_t dst = sbase + stn*ABUF;
            const size_t ko = (size_t)(kt + 2) * 64 * HD;
            const size_t vo = (size_t)(kt + 2) * 64;
#pragma unroll
            for (int i = 0; i < 4; i++) {
                int id = tid + i*256;
                int r = id >> 4, c = id & 15;
                CP_ASYNC16(dst + r*KROW + c*16, Khb + ko + (size_t)r*HD + c*8);
                int rv = id >> 3, cv = id & 7;
                CP_ASYNC16(dst + OFF_V + rv*VROW + cv*16, Vhb + vo + (size_t)rv*S_LEN + cv*8);
            }
        }
        CP_COMMIT();

        const uint32_t sKh = sbase + stc*ABUF;
        const uint32_t sVh = sKh + OFF_V;

        // ---- QK^T: 16x64 scores, 1 pass ----
        float sc[8][4];
#pragma unroll
        for (int nt = 0; nt < 8; nt++)
#pragma unroll
            for (int e = 0; e < 4; e++) sc[nt][e] = 0.f;

        const uint32_t krow = (uint32_t)(((l >> 4) << 3) + (l & 7)) * KROW;
#pragma unroll
        for (int kc = 0; kc < 8; kc++) {
            const uint32_t kcol = kc*32 + (((l >> 3) & 1) * 16);
            uint32_t khf[4][4];
#pragma unroll
            for (int bt = 0; bt < 4; bt++) ldsm_x4(khf[bt], sKh + krow + bt*16*KROW + kcol);
#pragma unroll
            for (int bt = 0; bt < 4; bt++) {
                mma16816(sc[2*bt],   qh[kc], &khf[bt][0]);
                mma16816(sc[2*bt+1], qh[kc], &khf[bt][2]);
            }
        }

        // ---- online softmax (exp2 domain) ----
        float mt0 = -1e30f, mt1 = -1e30f;
#pragma unroll
        for (int nt = 0; nt < 8; nt++) {
            mt0 = fmaxf(mt0, fmaxf(sc[nt][0], sc[nt][1]));
            mt1 = fmaxf(mt1, fmaxf(sc[nt][2], sc[nt][3]));
        }
        mt0 = fmaxf(mt0, __shfl_xor_sync(0xffffffffu, mt0, 1));
        mt0 = fmaxf(mt0, __shfl_xor_sync(0xffffffffu, mt0, 2));
        mt1 = fmaxf(mt1, __shfl_xor_sync(0xffffffffu, mt1, 1));
        mt1 = fmaxf(mt1, __shfl_xor_sync(0xffffffffu, mt1, 2));
        const float mn0 = fmaxf(m0, mt0);
        const float mn1 = fmaxf(m1, mt1);
        const float al0 = ex2f(m0 - mn0);
        const float al1 = ex2f(m1 - mn1);
        m0 = mn0; m1 = mn1;

        float lp0 = 0.f, lp1 = 0.f;
#pragma unroll
        for (int nt = 0; nt < 8; nt++) {
            sc[nt][0] = ex2f(sc[nt][0] - mn0); lp0 += sc[nt][0];
            sc[nt][1] = ex2f(sc[nt][1] - mn0); lp0 += sc[nt][1];
            sc[nt][2] = ex2f(sc[nt][2] - mn1); lp1 += sc[nt][2];
            sc[nt][3] = ex2f(sc[nt][3] - mn1); lp1 += sc[nt][3];
        }
        l0 = l0*al0 + lp0;
        l1 = l1*al1 + lp1;
#pragma unroll
        for (int nt = 0; nt < 16; nt++) {
            o[nt][0] *= al0; o[nt][1] *= al0;
            o[nt][2] *= al1; o[nt][3] *= al1;
        }

        // ---- P hi fragments (registers, fp16, single pass) ----
        uint32_t ph[4][4];
#pragma unroll
        for (int kk = 0; kk < 4; kk++) {
#pragma unroll
            for (int e = 0; e < 4; e++) {
                const int nt = 2*kk + (e >> 1);
                const int i0 = (e & 1) * 2;
                ph[kk][e] = h2_u32(__floats2half2_rn(sc[nt][i0], sc[nt][i0+1]));
            }
        }

        // ---- O += P @ V  (1 pass) ----
        const uint32_t vrow = (uint32_t)(((l >> 4) << 3) + (l & 7)) * VROW;
#pragma unroll
        for (int kk = 0; kk < 4; kk++) {
            const uint32_t vcol = kk*32 + (((l >> 3) & 1) * 16);
            uint32_t vhf[8][4];
#pragma unroll
            for (int nt = 0; nt < 8; nt++) ldsm_x4(vhf[nt], sVh + vrow + nt*16*VROW + vcol);
#pragma unroll
            for (int nt = 0; nt < 8; nt++) {
                mma16816(o[2*nt],   ph[kk], &vhf[nt][0]);
                mma16816(o[2*nt+1], ph[kk], &vhf[nt][2]);
            }
        }
        stc = (stc + 1 == 3) ? 0 : stc + 1;
    }

    // ---- finalize ----
    l0 += __shfl_xor_sync(0xffffffffu, l0, 1);
    l0 += __shfl_xor_sync(0xffffffffu, l0, 2);
    l1 += __shfl_xor_sync(0xffffffffu, l1, 1);
    l1 += __shfl_xor_sync(0xffffffffu, l1, 2);
    const float inv0 = 1.f / l0;
    const float inv1 = 1.f / l1;

    const int gr = l >> 2;
    const int row0 = qb*128 + w*16 + gr;
    const int t0 = b*S_LEN + row0;
    const int t1 = t0 + 8;
    const int cbase = h*HD + (l & 3)*2;
#pragma unroll
    for (int nt = 0; nt < 16; nt++) {
        const int c = cbase + nt*8;
        {
            float v0 = o[nt][0]*inv0, v1 = o[nt][1]*inv0;
            *(uint32_t*)(AOh + (size_t)t0*HDIM + c) = h2_u32(__floats2half2_rn(v0, v1));
        }
        {
            float v0 = o[nt][2]*inv1, v1 = o[nt][3]*inv1;
            *(uint32_t*)(AOh + (size_t)t1*HDIM + c) = h2_u32(__floats2half2_rn(v0, v1));
        }
    }
}

// ---------------------------------------------------------------------------
extern "C" void kernel_launch(void* const* d_in, const int* in_sizes, int n_in,
                              void* d_out, int out_size)
{
    const float* hidden = (const float*)d_in[0];
    const float* cosp   = (const float*)d_in[1];
    const float* sinp   = (const float*)d_in[2];
    const float* Wq     = (const float*)d_in[3];
    const float* Wk     = (const float*)d_in[4];
    const float* bk     = (const float*)d_in[5];
    const float* Wv     = (const float*)d_in[6];
    const float* bv     = (const float*)d_in[7];
    const float* Wo     = (const float*)d_in[8];
    float* out = (float*)d_out;

    __half *Hh,*Wqh,*Wkh,*Wvh,*Woh;
    __half *Qhp,*Khp,*Vthp,*AOh;
    cudaGetSymbolAddress((void**)&Hh,  g_Hh);
    cudaGetSymbolAddress((void**)&Wqh, g_Wqh);
    cudaGetSymbolAddress((void**)&Wkh, g_Wkh);
    cudaGetSymbolAddress((void**)&Wvh, g_Wvh);
    cudaGetSymbolAddress((void**)&Woh, g_Woh);
    cudaGetSymbolAddress((void**)&Qhp, g_Qh);
    cudaGetSymbolAddress((void**)&Khp, g_Kh);
    cudaGetSymbolAddress((void**)&Vthp, g_Vth);
    cudaGetSymbolAddress((void**)&AOh, g_AOh);

    static bool attr_set = false;
    if (!attr_set) {
        cudaFuncSetAttribute((const void*)gemm_tc<0>, cudaFuncAttributeMaxDynamicSharedMemorySize, GEMM_SMEM);
        cudaFuncSetAttribute((const void*)gemm_tc<1>, cudaFuncAttributeMaxDynamicSharedMemorySize, GEMM_SMEM);
        cudaFuncSetAttribute((const void*)gemm_tc<2>, cudaFuncAttributeMaxDynamicSharedMemorySize, GEMM_SMEM);
        cudaFuncSetAttribute((const void*)attn_tc, cudaFuncAttributeMaxDynamicSharedMemorySize, ATTN_SMEM);
        attr_set = true;
    }

    // convert fp32 inputs to fp16
    {
        int nH = T_TOK*HDIM;   // 16M
        int nW = HDIM*HDIM;    // 16M
        int nK = KV_N*HDIM;    // 4M
        cvt1_k<<<nH/2048, 256>>>(hidden, Hh, nH);
        cvt1_k<<<nW/2048, 256>>>(Wq, Wqh, nW);
        cvt1_k<<<nK/2048, 256>>>(Wk, Wkh, nK);
        cvt1_k<<<nK/2048, 256>>>(Wv, Wvh, nK);
        cvt1_k<<<nW/2048, 256>>>(Wo, Woh, nW);
    }

    // Q = rope(hidden @ Wq^T) * (SCALE*log2e)  -> fp16 [b][h][s][d]
    gemm_tc<1><<<dim3(HDIM/128, T_TOK/128), 256, GEMM_SMEM>>>(
        Hh, Wqh, nullptr, nullptr, Qhp, cosp, sinp, NH, Q_SCALE);
    // K = rope(hidden @ Wk^T + bk)             -> fp16 [b][kv][s][d]
    gemm_tc<1><<<dim3(KV_N/128, T_TOK/128), 256, GEMM_SMEM>>>(
        Hh, Wkh, bk, nullptr, Khp, cosp, sinp, NKV, 1.0f);
    // V = hidden @ Wv^T + bv                   -> fp16 [b][kv][d][s]
    gemm_tc<2><<<dim3(KV_N/128, T_TOK/128), 256, GEMM_SMEM>>>(
        Hh, Wvh, bv, nullptr, Vthp, nullptr, nullptr, NKV, 1.0f);

    // attention -> AOh fp16 [t][h*HD+d]
    attn_tc<<<dim3(S_LEN/128, BATCH*NH), 256, ATTN_SMEM>>>(
        Qhp, Khp, Vthp, AOh);

    // out = AO @ Wo^T (fp32)
    gemm_tc<0><<<dim3(HDIM/128, T_TOK/128), 256, GEMM_SMEM>>>(
        AOh, Woh, nullptr, out, nullptr, nullptr, nullptr, 0, 1.0f);
}

// round 16
// speedup vs baseline: 8.0024x; 1.0159x over previous
#include <cuda_runtime.h>
#include <cuda_fp16.h>
#include <cstdint>
#include <math.h>

#define S_LEN 2048
#define BATCH 2
#define HDIM  4096
#define HD    128
#define NH    32
#define NKV   8
#define T_TOK (BATCH*S_LEN)   // 4096 tokens
#define KV_N  (NKV*HD)        // 1024

// SCALE * log2(e) folded into Q so softmax works in exp2 domain
#define Q_SCALE (0.08838834764831845f * 1.4426950408889634f)

// ---------------- scratch (__device__ globals; no allocation allowed) -------
__device__ __half g_Hh[(size_t)T_TOK*HDIM];
__device__ __half g_Wqh[(size_t)HDIM*HDIM];
__device__ __half g_Wkh[(size_t)KV_N*HDIM];
__device__ __half g_Wvh[(size_t)KV_N*HDIM];
__device__ __half g_Woh[(size_t)HDIM*HDIM];

__device__ __half g_Qh[(size_t)BATCH*NH*S_LEN*HD];   // [b][h][s][d] (scaled)
__device__ __half g_Kh[(size_t)BATCH*NKV*S_LEN*HD];  // [b][kv][s][d]
__device__ __half g_Vth[(size_t)BATCH*NKV*HD*S_LEN]; // [b][kv][d][s] (transposed)
__device__ __half g_AOh[(size_t)T_TOK*HDIM];         // [t][h*HD+d]

// ---------------- PTX helpers ----------------
__device__ __forceinline__ uint32_t smem_to_u32(const void* p) {
    uint32_t a;
    asm("{ .reg .u64 t; cvta.to.shared.u64 t, %1; cvt.u32.u64 %0, t; }"
        : "=r"(a) : "l"(p));
    return a;
}
__device__ __forceinline__ void ldsm_x4(uint32_t* r, uint32_t addr) {
    asm volatile("ldmatrix.sync.aligned.m8n8.x4.shared.b16 {%0,%1,%2,%3}, [%4];"
                 : "=r"(r[0]), "=r"(r[1]), "=r"(r[2]), "=r"(r[3]) : "r"(addr));
}
__device__ __forceinline__ void mma16816(float* d, const uint32_t* a, const uint32_t* b) {
    asm volatile(
        "mma.sync.aligned.m16n8k16.row.col.f32.f16.f16.f32 "
        "{%0,%1,%2,%3}, {%4,%5,%6,%7}, {%8,%9}, {%0,%1,%2,%3};"
        : "+f"(d[0]), "+f"(d[1]), "+f"(d[2]), "+f"(d[3])
        : "r"(a[0]), "r"(a[1]), "r"(a[2]), "r"(a[3]), "r"(b[0]), "r"(b[1]));
}
#define CP_ASYNC16(dst, src) \
    asm volatile("cp.async.cg.shared.global [%0], [%1], 16;" \
                 :: "r"(dst), "l"(src))
#define CP_COMMIT() asm volatile("cp.async.commit_group;" ::: "memory")
#define CP_WAIT(n)  asm volatile("cp.async.wait_group %0;" :: "n"(n) : "memory")

__device__ __forceinline__ float ex2f(float x) {
    float y;
    asm("ex2.approx.ftz.f32 %0, %1;" : "=f"(y) : "f"(x));
    return y;
}
__device__ __forceinline__ uint32_t h2_u32(__half2 h) {
    return *reinterpret_cast<uint32_t*>(&h);
}

// ---------------- fp32 -> fp16 conversion (8 elem/thread for ILP) -----------
__global__ void __launch_bounds__(256)
cvt1_k(const float* __restrict__ x, __half* __restrict__ h, int n)
{
    int i = (blockIdx.x * 256 + threadIdx.x) * 8;
    if (i >= n) return;
    float4 a = *(const float4*)(x + i);
    float4 b = *(const float4*)(x + i + 4);
    uint4 o;
    o.x = h2_u32(__floats2half2_rn(a.x, a.y));
    o.y = h2_u32(__floats2half2_rn(a.z, a.w));
    o.z = h2_u32(__floats2half2_rn(b.x, b.y));
    o.w = h2_u32(__floats2half2_rn(b.z, b.w));
    *(uint4*)(h + i) = o;
}

// ---------------------------------------------------------------------------
// GEMM constants (BK=32, 3-stage, proven mainloop)
// ---------------------------------------------------------------------------
#define BK 32
#define ROWB 80
#define TILE_BYTES (128*ROWB)          // 10240
#define STAGEB (2*TILE_BYTES)          // Ah, Bh = 20480
#define GEMM_SMEM (3*STAGEB)           // 61440

// ---------------------------------------------------------------------------
// Merged QKV projection: one launch, grid x = 48 (32 Q | 8 K | 8 V), y = 32.
// Per-block uniform dispatch: Q -> rope*scale -> g_Qh; K -> bias+rope -> g_Kh;
// V -> bias, transposed -> g_Vth. Same 3-stage fp16 1-pass mainloop.
// ---------------------------------------------------------------------------
__global__ void __launch_bounds__(256, 2)
gemm_qkv(const __half* __restrict__ Hh,
         const __half* __restrict__ Wqh, const __half* __restrict__ Wkh,
         const __half* __restrict__ Wvh,
         const float* __restrict__ bk, const float* __restrict__ bv,
         __half* __restrict__ Qh, __half* __restrict__ Kh,
         __half* __restrict__ Vth,
         const float* __restrict__ cosp, const float* __restrict__ sinp)
{
    extern __shared__ char smem[];
    const uint32_t sbase = smem_to_u32(smem);
    const int tid = threadIdx.x;
    const int w   = tid >> 5;
    const int l   = tid & 31;
    const int wm  = w >> 1;
    const int wn  = w & 1;
    const int bm = blockIdx.y, bn = blockIdx.x;
    const int K = HDIM;
    const int NIT = K / BK;   // 128

    // dispatch (uniform per block)
    const __half* Bg;
    const float*  bias;
    __half* Ch;
    int bnl, n_heads, mode;           // mode 1 = rope path, 2 = V transposed
    float scale;
    if (bn < 32)      { Bg = Wqh; bnl = bn;      bias = nullptr; Ch = Qh;  n_heads = NH;  mode = 1; scale = Q_SCALE; }
    else if (bn < 40) { Bg = Wkh; bnl = bn - 32; bias = bk;      Ch = Kh;  n_heads = NKV; mode = 1; scale = 1.0f; }
    else              { Bg = Wvh; bnl = bn - 40; bias = bv;      Ch = Vth; n_heads = NKV; mode = 2; scale = 1.0f; }

    const int r0 = tid >> 2, c0 = tid & 3;
    const int r1 = (tid + 256) >> 2;
    const size_t aro = (size_t)(bm*128 + r0)*K + c0*8;
    const size_t ar1 = (size_t)(bm*128 + r1)*K + c0*8;
    const size_t bro = (size_t)(bnl*128 + r0)*K + c0*8;
    const size_t br1 = (size_t)(bnl*128 + r1)*K + c0*8;
    const uint32_t so0 = r0*ROWB + c0*16;
    const uint32_t so1 = r1*ROWB + c0*16;

    float acc[2][8][4];
#pragma unroll
    for (int mt = 0; mt < 2; mt++)
#pragma unroll
        for (int nt = 0; nt < 8; nt++)
#pragma unroll
            for (int e = 0; e < 4; e++) acc[mt][nt][e] = 0.f;

#pragma unroll
    for (int st = 0; st < 2; st++) {
        const int k0 = st * BK;
        uint32_t dst = sbase + st*STAGEB;
        CP_ASYNC16(dst + so0, Hh + aro + k0);
        CP_ASYNC16(dst + so1, Hh + ar1 + k0);
        CP_ASYNC16(dst + TILE_BYTES + so0, Bg + bro + k0);
        CP_ASYNC16(dst + TILE_BYTES + so1, Bg + br1 + k0);
        CP_COMMIT();
    }

    int stc = 0;
    for (int it = 0; it < NIT; it++) {
        CP_WAIT(1);
        __syncthreads();
        if (it + 2 < NIT) {
            const int k0 = (it + 2) * BK;
            const int stn = (stc + 2 >= 3) ? stc - 1 : stc + 2;
            uint32_t dst = sbase + stn*STAGEB;
            CP_ASYNC16(dst + so0, Hh + aro + k0);
            CP_ASYNC16(dst + so1, Hh + ar1 + k0);
            CP_ASYNC16(dst + TILE_BYTES + so0, Bg + bro + k0);
            CP_ASYNC16(dst + TILE_BYTES + so1, Bg + br1 + k0);
        }
        CP_COMMIT();

        const uint32_t sAh = sbase + stc*STAGEB;
        const uint32_t sBh = sAh + TILE_BYTES;

#pragma unroll
        for (int ks = 0; ks < 2; ks++) {
            const uint32_t koff = ks*32 + ((l >> 4) * 16);
            const uint32_t aoff = (uint32_t)(wm*32 + (l & 15)) * ROWB + koff;
            const uint32_t boff = (uint32_t)(wn*64 + ((l >> 4) << 3) + (l & 7)) * ROWB
                                  + ks*32 + (((l >> 3) & 1) * 16);
            uint32_t ah[2][4], bh[4][4];
#pragma unroll
            for (int mt = 0; mt < 2; mt++) ldsm_x4(ah[mt], sAh + aoff + mt*16*ROWB);
#pragma unroll
            for (int bt = 0; bt < 4; bt++) ldsm_x4(bh[bt], sBh + boff + bt*16*ROWB);
#pragma unroll
            for (int mt = 0; mt < 2; mt++)
#pragma unroll
                for (int bt = 0; bt < 4; bt++) {
                    mma16816(acc[mt][2*bt],   ah[mt], &bh[bt][0]);
                    mma16816(acc[mt][2*bt+1], ah[mt], &bh[bt][2]);
                }
        }
        stc = (stc + 1 == 3) ? 0 : stc + 1;
    }

    // ---------------- epilogue ----------------
#pragma unroll
    for (int mt = 0; mt < 2; mt++) {
        const int rbase = bm*128 + wm*32 + mt*16 + (l >> 2);
#pragma unroll
        for (int half = 0; half < 2; half++) {
            const int t  = rbase + half*8;
            const int bb = t >> 11;
            const int s  = t & (S_LEN - 1);
#pragma unroll
            for (int nt = 0; nt < 8; nt++) {
                const int n0 = bnl*128 + wn*64 + nt*8 + (l & 3)*2;
                float x1 = acc[mt][nt][half*2 + 0];
                float x2 = acc[mt][nt][half*2 + 1];
                const int head = n0 >> 7;
                const int cl   = n0 & 127;
                if (mode == 2) {
                    x1 += bias[n0]; x2 += bias[n0 + 1];
                    const size_t base = ((size_t)(bb*n_heads + head)*HD) * S_LEN;
                    Ch[base + (size_t)cl*S_LEN + s]     = __float2half(x1);
                    Ch[base + (size_t)(cl+1)*S_LEN + s] = __float2half(x2);
                } else {
                    if (bias) { x1 += bias[n0]; x2 += bias[n0 + 1]; }
                    const int d = cl >> 1;
                    const float cs = cosp[s*64 + d];
                    const float sn = sinp[s*64 + d];
                    float y1 = (x1*cs - x2*sn) * scale;
                    float y2 = (x1*sn + x2*cs) * scale;
                    const size_t base = ((size_t)(bb*n_heads + head)*S_LEN + s) * HD;
                    Ch[base + d]      = __float2half(y1);
                    Ch[base + 64 + d] = __float2half(y2);
                }
            }
        }
    }
}

// ---------------------------------------------------------------------------
// O projection: out = AO @ Wo^T (fp32 out), same mainloop.
// ---------------------------------------------------------------------------
__global__ void __launch_bounds__(256, 2)
gemm_o(const __half* __restrict__ Agh, const __half* __restrict__ Bgh,
       float* __restrict__ Cf)
{
    extern __shared__ char smem[];
    const uint32_t sbase = smem_to_u32(smem);
    const int tid = threadIdx.x;
    const int w   = tid >> 5;
    const int l   = tid & 31;
    const int wm  = w >> 1;
    const int wn  = w & 1;
    const int bm = blockIdx.y, bn = blockIdx.x;
    const int K = HDIM;
    const int NIT = K / BK;

    const int r0 = tid >> 2, c0 = tid & 3;
    const int r1 = (tid + 256) >> 2;
    const size_t aro = (size_t)(bm*128 + r0)*K + c0*8;
    const size_t ar1 = (size_t)(bm*128 + r1)*K + c0*8;
    const size_t bro = (size_t)(bn*128 + r0)*K + c0*8;
    const size_t br1 = (size_t)(bn*128 + r1)*K + c0*8;
    const uint32_t so0 = r0*ROWB + c0*16;
    const uint32_t so1 = r1*ROWB + c0*16;

    float acc[2][8][4];
#pragma unroll
    for (int mt = 0; mt < 2; mt++)
#pragma unroll
        for (int nt = 0; nt < 8; nt++)
#pragma unroll
            for (int e = 0; e < 4; e++) acc[mt][nt][e] = 0.f;

#pragma unroll
    for (int st = 0; st < 2; st++) {
        const int k0 = st * BK;
        uint32_t dst = sbase + st*STAGEB;
        CP_ASYNC16(dst + so0, Agh + aro + k0);
        CP_ASYNC16(dst + so1, Agh + ar1 + k0);
        CP_ASYNC16(dst + TILE_BYTES + so0, Bgh + bro + k0);
        CP_ASYNC16(dst + TILE_BYTES + so1, Bgh + br1 + k0);
        CP_COMMIT();
    }

    int stc = 0;
    for (int it = 0; it < NIT; it++) {
        CP_WAIT(1);
        __syncthreads();
        if (it + 2 < NIT) {
            const int k0 = (it + 2) * BK;
            const int stn = (stc + 2 >= 3) ? stc - 1 : stc + 2;
            uint32_t dst = sbase + stn*STAGEB;
            CP_ASYNC16(dst + so0, Agh + aro + k0);
            CP_ASYNC16(dst + so1, Agh + ar1 + k0);
            CP_ASYNC16(dst + TILE_BYTES + so0, Bgh + bro + k0);
            CP_ASYNC16(dst + TILE_BYTES + so1, Bgh + br1 + k0);
        }
        CP_COMMIT();

        const uint32_t sAh = sbase + stc*STAGEB;
        const uint32_t sBh = sAh + TILE_BYTES;

#pragma unroll
        for (int ks = 0; ks < 2; ks++) {
            const uint32_t koff = ks*32 + ((l >> 4) * 16);
            const uint32_t aoff = (uint32_t)(wm*32 + (l & 15)) * ROWB + koff;
            const uint32_t boff = (uint32_t)(wn*64 + ((l >> 4) << 3) + (l & 7)) * ROWB
                                  + ks*32 + (((l >> 3) & 1) * 16);
            uint32_t ah[2][4], bh[4][4];
#pragma unroll
            for (int mt = 0; mt < 2; mt++) ldsm_x4(ah[mt], sAh + aoff + mt*16*ROWB);
#pragma unroll
            for (int bt = 0; bt < 4; bt++) ldsm_x4(bh[bt], sBh + boff + bt*16*ROWB);
#pragma unroll
            for (int mt = 0; mt < 2; mt++)
#pragma unroll
                for (int bt = 0; bt < 4; bt++) {
                    mma16816(acc[mt][2*bt],   ah[mt], &bh[bt][0]);
                    mma16816(acc[mt][2*bt+1], ah[mt], &bh[bt][2]);
                }
        }
        stc = (stc + 1 == 3) ? 0 : stc + 1;
    }

#pragma unroll
    for (int mt = 0; mt < 2; mt++) {
        const int rbase = bm*128 + wm*32 + mt*16 + (l >> 2);
#pragma unroll
        for (int half = 0; half < 2; half++) {
            const int t = rbase + half*8;
#pragma unroll
            for (int nt = 0; nt < 8; nt++) {
                const int n0 = bn*128 + wn*64 + nt*8 + (l & 3)*2;
                float* cp = Cf + (size_t)t*HDIM + n0;
                cp[0] = acc[mt][nt][half*2 + 0];
                cp[1] = acc[mt][nt][half*2 + 1];
            }
        }
    }
}

// ---------------------------------------------------------------------------
// HMMA fp16 flash attention: BM=128 (8 warps x 16 rows), BN=128 keys, HD=128.
// Q (scaled) register-resident; K / V^T, cp.async 3-stage.
// Scores = 1 pass; PV = 1 pass. Online softmax exp2 domain (16 key-tiles).
// ---------------------------------------------------------------------------
#define KROW 272                   // K smem row stride (128 fp16 = 256B + 16)
#define VROW 272                   // V^T smem row stride (128 fp16 = 256B + 16)
#define OFF_V  34816               // K tile bytes (128*KROW)
#define ABUF   69632               // K + V per stage
#define ATTN_SMEM (3*ABUF)         // 208896

__global__ void __launch_bounds__(256, 1)
attn_tc(const __half* __restrict__ Qh,
        const __half* __restrict__ Kh, const __half* __restrict__ Vth,
        __half* __restrict__ AOh)
{
    extern __shared__ char smem[];
    const uint32_t sbase = smem_to_u32(smem);
    const int tid = threadIdx.x;
    const int w   = tid >> 5;
    const int l   = tid & 31;
    const int qb  = blockIdx.x;
    const int bh  = blockIdx.y;
    const int b   = bh / NH;
    const int h   = bh % NH;
    const int kv  = h >> 2;

    const __half* Qhb = Qh + ((size_t)bh*S_LEN + qb*128)*HD;
    const __half* Khb = Kh + ((size_t)(b*NKV + kv)*S_LEN)*HD;
    const __half* Vhb = Vth + ((size_t)(b*NKV + kv)*HD)*S_LEN;

    // ---- stage Q into smem (stage-0 area), then load frags ----
#pragma unroll
    for (int i = 0; i < 8; i++) {
        int id = tid + i*256;
        int r = id >> 4, c = id & 15;
        *(uint4*)(smem + r*KROW + c*16) =
            *(const uint4*)(Qhb + (size_t)r*HD + c*8);
    }
    __syncthreads();

    uint32_t qh[8][4];
    {
        const uint32_t arow = (uint32_t)(w*16 + (l & 15)) * KROW;
#pragma unroll
        for (int kc = 0; kc < 8; kc++) {
            const uint32_t koff = kc*32 + ((l >> 4) * 16);
            ldsm_x4(qh[kc], sbase + arow + koff);
        }
    }
    __syncthreads();

    float o[16][4];
#pragma unroll
    for (int nt = 0; nt < 16; nt++)
#pragma unroll
        for (int e = 0; e < 4; e++) o[nt][e] = 0.f;
    float m0 = -1e30f, m1 = -1e30f, l0 = 0.f, l1 = 0.f;

    // prologue: stages 0, 1 (key tiles 0, 1) — 16 cp.async per thread each
#pragma unroll
    for (int st = 0; st < 2; st++) {
        uint32_t dst = sbase + st*ABUF;
        const size_t ko = (size_t)st * 128 * HD;
        const size_t vo = (size_t)st * 128;
#pragma unroll
        for (int i = 0; i < 8; i++) {
            int id = tid + i*256;
            int r = id >> 4, c = id & 15;
            CP_ASYNC16(dst + r*KROW + c*16, Khb + ko + (size_t)r*HD + c*8);
            CP_ASYNC16(dst + OFF_V + r*VROW + c*16, Vhb + vo + (size_t)r*S_LEN + c*8);
        }
        CP_COMMIT();
    }

    const int NKT = S_LEN / 128;   // 16
    int stc = 0;
    for (int kt = 0; kt < NKT; kt++) {
        CP_WAIT(1);
        __syncthreads();
        if (kt + 2 < NKT) {
            const int stn = (stc + 2 >= 3) ? stc - 1 : stc + 2;
            uint32_t dst = sbase + stn*ABUF;
            const size_t ko = (size_t)(kt + 2) * 128 * HD;
            const size_t vo = (size_t)(kt + 2) * 128;
#pragma unroll
            for (int i = 0; i < 8; i++) {
                int id = tid + i*256;
                int r = id >> 4, c = id & 15;
                CP_ASYNC16(dst + r*KROW + c*16, Khb + ko + (size_t)r*HD + c*8);
                CP_ASYNC16(dst + OFF_V + r*VROW + c*16, Vhb + vo + (size_t)r*S_LEN + c*8);
            }
        }
        CP_COMMIT();

        const uint32_t sKh = sbase + stc*ABUF;
        const uint32_t sVh = sKh + OFF_V;

        // ---- QK^T: 16x128 scores, 1 pass ----
        float sc[16][4];
#pragma unroll
        for (int nt = 0; nt < 16; nt++)
#pragma unroll
            for (int e = 0; e < 4; e++) sc[nt][e] = 0.f;

        const uint32_t krow = (uint32_t)(((l >> 4) << 3) + (l & 7)) * KROW;
#pragma unroll
        for (int kc = 0; kc < 8; kc++) {
            const uint32_t kcol = kc*32 + (((l >> 3) & 1) * 16);
#pragma unroll
            for (int bt = 0; bt < 8; bt++) {
                uint32_t khf[4];
                ldsm_x4(khf, sKh + krow + bt*16*KROW + kcol);
                mma16816(sc[2*bt],   qh[kc], &khf[0]);
                mma16816(sc[2*bt+1], qh[kc], &khf[2]);
            }
        }

        // ---- online softmax (exp2 domain) ----
        float mt0 = -1e30f, mt1 = -1e30f;
#pragma unroll
        for (int nt = 0; nt < 16; nt++) {
            mt0 = fmaxf(mt0, fmaxf(sc[nt][0], sc[nt][1]));
            mt1 = fmaxf(mt1, fmaxf(sc[nt][2], sc[nt][3]));
        }
        mt0 = fmaxf(mt0, __shfl_xor_sync(0xffffffffu, mt0, 1));
        mt0 = fmaxf(mt0, __shfl_xor_sync(0xffffffffu, mt0, 2));
        mt1 = fmaxf(mt1, __shfl_xor_sync(0xffffffffu, mt1, 1));
        mt1 = fmaxf(mt1, __shfl_xor_sync(0xffffffffu, mt1, 2));
        const float mn0 = fmaxf(m0, mt0);
        const float mn1 = fmaxf(m1, mt1);
        const float al0 = ex2f(m0 - mn0);
        const float al1 = ex2f(m1 - mn1);
        m0 = mn0; m1 = mn1;

        float lp0 = 0.f, lp1 = 0.f;
        uint32_t ph[8][4];
#pragma unroll
        for (int nt = 0; nt < 16; nt += 2) {
            float p00 = ex2f(sc[nt][0]   - mn0); lp0 += p00;
            float p01 = ex2f(sc[nt][1]   - mn0); lp0 += p01;
            float p02 = ex2f(sc[nt][2]   - mn1); lp1 += p02;
            float p03 = ex2f(sc[nt][3]   - mn1); lp1 += p03;
            float p10 = ex2f(sc[nt+1][0] - mn0); lp0 += p10;
            float p11 = ex2f(sc[nt+1][1] - mn0); lp0 += p11;
            float p12 = ex2f(sc[nt+1][2] - mn1); lp1 += p12;
            float p13 = ex2f(sc[nt+1][3] - mn1); lp1 += p13;
            const int kk = nt >> 1;
            ph[kk][0] = h2_u32(__floats2half2_rn(p00, p01));
            ph[kk][1] = h2_u32(__floats2half2_rn(p02, p03));
            ph[kk][2] = h2_u32(__floats2half2_rn(p10, p11));
            ph[kk][3] = h2_u32(__floats2half2_rn(p12, p13));
        }
        l0 = l0*al0 + lp0;
        l1 = l1*al1 + lp1;
#pragma unroll
        for (int nt = 0; nt < 16; nt++) {
            o[nt][0] *= al0; o[nt][1] *= al0;
            o[nt][2] *= al1; o[nt][3] *= al1;
        }

        // ---- O += P @ V  (1 pass over 128 keys = 8 k16 chunks) ----
        const uint32_t vrow = (uint32_t)(((l >> 4) << 3) + (l & 7)) * VROW;
#pragma unroll
        for (int kk = 0; kk < 8; kk++) {
            const uint32_t vcol = kk*32 + (((l >> 3) & 1) * 16);
#pragma unroll
            for (int nt = 0; nt < 8; nt++) {
                uint32_t vhf[4];
                ldsm_x4(vhf, sVh + vrow + nt*16*VROW + vcol);
                mma16816(o[2*nt],   ph[kk], &vhf[0]);
                mma16816(o[2*nt+1], ph[kk], &vhf[2]);
            }
        }
        stc = (stc + 1 == 3) ? 0 : stc + 1;
    }

    // ---- finalize ----
    l0 += __shfl_xor_sync(0xffffffffu, l0, 1);
    l0 += __shfl_xor_sync(0xffffffffu, l0, 2);
    l1 += __shfl_xor_sync(0xffffffffu, l1, 1);
    l1 += __shfl_xor_sync(0xffffffffu, l1, 2);
    const float inv0 = 1.f / l0;
    const float inv1 = 1.f / l1;

    const int gr = l >> 2;
    const int row0 = qb*128 + w*16 + gr;
    const int t0 = b*S_LEN + row0;
    const int t1 = t0 + 8;
    const int cbase = h*HD + (l & 3)*2;
#pragma unroll
    for (int nt = 0; nt < 16; nt++) {
        const int c = cbase + nt*8;
        {
            float v0 = o[nt][0]*inv0, v1 = o[nt][1]*inv0;
            *(uint32_t*)(AOh + (size_t)t0*HDIM + c) = h2_u32(__floats2half2_rn(v0, v1));
        }
        {
            float v0 = o[nt][2]*inv1, v1 = o[nt][3]*inv1;
            *(uint32_t*)(AOh + (size_t)t1*HDIM + c) = h2_u32(__floats2half2_rn(v0, v1));
        }
    }
}

// ---------------------------------------------------------------------------
extern "C" void kernel_launch(void* const* d_in, const int* in_sizes, int n_in,
                              void* d_out, int out_size)
{
    const float* hidden = (const float*)d_in[0];
    const float* cosp   = (const float*)d_in[1];
    const float* sinp   = (const float*)d_in[2];
    const float* Wq     = (const float*)d_in[3];
    const float* Wk     = (const float*)d_in[4];
    const float* bk     = (const float*)d_in[5];
    const float* Wv     = (const float*)d_in[6];
    const float* bv     = (const float*)d_in[7];
    const float* Wo     = (const float*)d_in[8];
    float* out = (float*)d_out;

    __half *Hh,*Wqh,*Wkh,*Wvh,*Woh;
    __half *Qhp,*Khp,*Vthp,*AOh;
    cudaGetSymbolAddress((void**)&Hh,  g_Hh);
    cudaGetSymbolAddress((void**)&Wqh, g_Wqh);
    cudaGetSymbolAddress((void**)&Wkh, g_Wkh);
    cudaGetSymbolAddress((void**)&Wvh, g_Wvh);
    cudaGetSymbolAddress((void**)&Woh, g_Woh);
    cudaGetSymbolAddress((void**)&Qhp, g_Qh);
    cudaGetSymbolAddress((void**)&Khp, g_Kh);
    cudaGetSymbolAddress((void**)&Vthp, g_Vth);
    cudaGetSymbolAddress((void**)&AOh, g_AOh);

    static bool attr_set = false;
    if (!attr_set) {
        cudaFuncSetAttribute((const void*)gemm_qkv, cudaFuncAttributeMaxDynamicSharedMemorySize, GEMM_SMEM);
        cudaFuncSetAttribute((const void*)gemm_o,   cudaFuncAttributeMaxDynamicSharedMemorySize, GEMM_SMEM);
        cudaFuncSetAttribute((const void*)attn_tc,  cudaFuncAttributeMaxDynamicSharedMemorySize, ATTN_SMEM);
        attr_set = true;
    }

    // convert fp32 inputs to fp16
    {
        int nH = T_TOK*HDIM;   // 16M
        int nW = HDIM*HDIM;    // 16M
        int nK = KV_N*HDIM;    // 4M
        cvt1_k<<<nH/2048, 256>>>(hidden, Hh, nH);
        cvt1_k<<<nW/2048, 256>>>(Wq, Wqh, nW);
        cvt1_k<<<nK/2048, 256>>>(Wk, Wkh, nK);
        cvt1_k<<<nK/2048, 256>>>(Wv, Wvh, nK);
        cvt1_k<<<nW/2048, 256>>>(Wo, Woh, nW);
    }

    // merged QKV projections (Q rope+scale / K rope+bias / V bias+transpose)
    gemm_qkv<<<dim3(48, T_TOK/128), 256, GEMM_SMEM>>>(
        Hh, Wqh, Wkh, Wvh, bk, bv, Qhp, Khp, Vthp, cosp, sinp);

    // attention -> AOh fp16 [t][h*HD+d]
    attn_tc<<<dim3(S_LEN/128, BATCH*NH), 256, ATTN_SMEM>>>(
        Qhp, Khp, Vthp, AOh);

    // out = AO @ Wo^T (fp32)
    gemm_o<<<dim3(HDIM/128, T_TOK/128), 256, GEMM_SMEM>>>(AOh, Woh, out);
}